// round 2
// baseline (speedup 1.0000x reference)
#include <cuda_runtime.h>
#include <cuda_bf16.h>
#include <math.h>

// Problem dims
#define BB 4
#define SS 1024
#define DD 1024
#define FF 2048
#define HH 16
#define EE 8
#define DK 64
#define TT (BB*SS)          // 4096 tokens
#define NTHREADS 256

// ---------------- static device scratch ----------------
__device__ float g_x2a[TT*DD];
__device__ float g_tmp1[TT*FF];
__device__ float g_tmp2[TT*FF];
__device__ float g_q[TT*DD];
__device__ float g_kk[TT*DD];
__device__ float g_v[TT*DD];
__device__ float g_attn[(size_t)BB*HH*SS*SS];   // 268MB
__device__ float g_vp[BB*HH*SS*DK];
__device__ float g_cp[BB*HH*SS*DK];
__device__ float g_ctx[TT*DD];
__device__ float g_xres[TT*DD];
__device__ float g_x2b[TT*DD];
__device__ float g_mh[TT*FF];
__device__ float g_moe[(size_t)EE*TT*DD];       // 134MB
__device__ int   g_counts[EE];
__device__ int   g_etok[EE*TT];
__device__ int   g_texp[TT*2];
__device__ int   g_tslot[TT*2];
__device__ float g_tw[TT*2];

// ---------------- helpers ----------------
__device__ __forceinline__ float blockReduceSum(float v, float* sh) {
    int tid = threadIdx.x;
    sh[tid] = v; __syncthreads();
    for (int s = 128; s > 0; s >>= 1) {
        if (tid < s) sh[tid] += sh[tid + s];
        __syncthreads();
    }
    float r = sh[0]; __syncthreads();
    return r;
}
__device__ __forceinline__ float blockReduceMax(float v, float* sh) {
    int tid = threadIdx.x;
    sh[tid] = v; __syncthreads();
    for (int s = 128; s > 0; s >>= 1) {
        if (tid < s) sh[tid] = fmaxf(sh[tid], sh[tid + s]);
        __syncthreads();
    }
    float r = sh[0]; __syncthreads();
    return r;
}

// ---------------- LayerNorm ----------------
__global__ void ln_k(const float* __restrict__ x, const float* __restrict__ g,
                     const float* __restrict__ b, float* __restrict__ out) {
    __shared__ float sh[NTHREADS];
    int r = blockIdx.x;
    const float* row = x + (size_t)r * DD;
    float s = 0.f;
    for (int i = threadIdx.x; i < DD; i += NTHREADS) s += row[i];
    float mean = blockReduceSum(s, sh) * (1.0f / DD);
    float v = 0.f;
    for (int i = threadIdx.x; i < DD; i += NTHREADS) {
        float d = row[i] - mean; v += d * d;
    }
    float var = blockReduceSum(v, sh) * (1.0f / DD);
    float inv = rsqrtf(var + 1e-5f);
    float* o = out + (size_t)r * DD;
    for (int i = threadIdx.x; i < DD; i += NTHREADS)
        o[i] = (row[i] - mean) * inv * g[i] + b[i];
}

// ---------------- generic tiled GEMM ----------------
// C[M,N] = A[M,K]@B[K,N] + bias (+ R if EPI==1).  Batched via blockIdx.z strides.
template<int BM, int BN, int BK, int TM, int TN, int EPI>
__global__ void gemm_k(const float* __restrict__ A, int lda, long long sAz,
                       const float* __restrict__ Bw, int ldb, long long sBz,
                       const float* __restrict__ bias,
                       const float* __restrict__ R,
                       float* __restrict__ C, int ldc, long long sCz,
                       int M, const int* __restrict__ Mptr, int N, int Kd) {
    if (Mptr) M = *Mptr;
    int br = blockIdx.x, bc = blockIdx.y, z = blockIdx.z;
    if (br * BM >= M) return;
    A  += (long long)z * sAz;
    Bw += (long long)z * sBz;
    C  += (long long)z * sCz;

    __shared__ float As[BK][BM];
    __shared__ float Bs[BK][BN];
    int tid = threadIdx.x;
    const int TXN = BN / TN;
    int tx = tid % TXN, ty = tid / TXN;

    float acc[TM][TN];
#pragma unroll
    for (int i = 0; i < TM; i++)
#pragma unroll
        for (int j = 0; j < TN; j++) acc[i][j] = 0.f;

    float ra[TM], rb[TN];
    for (int k0 = 0; k0 < Kd; k0 += BK) {
        for (int i = tid; i < BM * BK; i += NTHREADS) {
            int r = i / BK, c = i % BK;
            int gr = br * BM + r;
            As[c][r] = (gr < M) ? A[(long long)gr * lda + k0 + c] : 0.f;
        }
        for (int i = tid; i < BK * BN; i += NTHREADS) {
            int r = i / BN, c = i % BN;
            int gc = bc * BN + c;
            Bs[r][c] = (gc < N) ? Bw[(long long)(k0 + r) * ldb + gc] : 0.f;
        }
        __syncthreads();
#pragma unroll
        for (int k = 0; k < BK; k++) {
#pragma unroll
            for (int i = 0; i < TM; i++) ra[i] = As[k][ty * TM + i];
#pragma unroll
            for (int j = 0; j < TN; j++) rb[j] = Bs[k][tx * TN + j];
#pragma unroll
            for (int i = 0; i < TM; i++)
#pragma unroll
                for (int j = 0; j < TN; j++) acc[i][j] += ra[i] * rb[j];
        }
        __syncthreads();
    }
#pragma unroll
    for (int i = 0; i < TM; i++) {
        int gr = br * BM + ty * TM + i;
        if (gr >= M) continue;
#pragma unroll
        for (int j = 0; j < TN; j++) {
            int gc = bc * BN + tx * TN + j;
            if (gc >= N) continue;
            float vv = acc[i][j];
            if (bias) vv += bias[gc];
            if (EPI == 1) vv += R[(long long)gr * ldc + gc];
            C[(long long)gr * ldc + gc] = vv;
        }
    }
}

// ---------------- gather GEMM (MoE expert input) ----------------
// C[slot,N] = X[tok[slot],K] @ B[K,N] + bias, for slot < *cnt
template<int BM, int BN, int BK, int TM, int TN>
__global__ void ggemm_k(const float* __restrict__ X, int ldx,
                        const int* __restrict__ tok, const int* __restrict__ cnt,
                        const float* __restrict__ Bw, int ldb,
                        const float* __restrict__ bias,
                        float* __restrict__ C, int ldc, int N, int Kd) {
    int M = *cnt;
    int br = blockIdx.x, bc = blockIdx.y;
    if (br * BM >= M) return;

    __shared__ float As[BK][BM];
    __shared__ float Bs[BK][BN];
    __shared__ int toks[BM];
    int tid = threadIdx.x;
    for (int i = tid; i < BM; i += NTHREADS) {
        int gr = br * BM + i;
        toks[i] = (gr < M) ? tok[gr] : -1;
    }
    __syncthreads();

    const int TXN = BN / TN;
    int tx = tid % TXN, ty = tid / TXN;
    float acc[TM][TN];
#pragma unroll
    for (int i = 0; i < TM; i++)
#pragma unroll
        for (int j = 0; j < TN; j++) acc[i][j] = 0.f;
    float ra[TM], rb[TN];

    for (int k0 = 0; k0 < Kd; k0 += BK) {
        for (int i = tid; i < BM * BK; i += NTHREADS) {
            int r = i / BK, c = i % BK;
            int tk = toks[r];
            As[c][r] = (tk >= 0) ? X[(long long)tk * ldx + k0 + c] : 0.f;
        }
        for (int i = tid; i < BK * BN; i += NTHREADS) {
            int r = i / BN, c = i % BN;
            Bs[r][c] = Bw[(long long)(k0 + r) * ldb + bc * BN + c];
        }
        __syncthreads();
#pragma unroll
        for (int k = 0; k < BK; k++) {
#pragma unroll
            for (int i = 0; i < TM; i++) ra[i] = As[k][ty * TM + i];
#pragma unroll
            for (int j = 0; j < TN; j++) rb[j] = Bs[k][tx * TN + j];
#pragma unroll
            for (int i = 0; i < TM; i++)
#pragma unroll
                for (int j = 0; j < TN; j++) acc[i][j] += ra[i] * rb[j];
        }
        __syncthreads();
    }
#pragma unroll
    for (int i = 0; i < TM; i++) {
        int gr = br * BM + ty * TM + i;
        if (gr >= M) continue;
#pragma unroll
        for (int j = 0; j < TN; j++) {
            int gc = bc * BN + tx * TN + j;
            C[(long long)gr * ldc + gc] = acc[i][j] + bias[gc];
        }
    }
}

// ---------------- SwiGLU elementwise ----------------
__global__ void swiglu_k(const float* __restrict__ a, const float* __restrict__ b,
                         float* __restrict__ o, long long n,
                         const int* __restrict__ cntPtr, int cols) {
    long long i = (long long)blockIdx.x * NTHREADS + threadIdx.x;
    long long nn = cntPtr ? (long long)(*cntPtr) * cols : n;
    if (i < nn) {
        float x = a[i];
        o[i] = (x / (1.f + __expf(-x))) * b[i];
    }
}

// ---------------- attention scores ----------------
// scores[b,h,q,k] = dot(q[b,q,h*64+:], k[b,k,h*64+:]) / 8  (masked)
__global__ void scores_k(const float* __restrict__ q, const float* __restrict__ kb,
                         const int* __restrict__ mask, float* __restrict__ attn) {
    int z = blockIdx.z;            // b*H + h
    int b = z / HH, h = z % HH;
    int q0 = blockIdx.x * 64, k0 = blockIdx.y * 64;
    __shared__ float qt[64][65];   // [d][row]
    __shared__ float kt[64][65];
    int tid = threadIdx.x;
    for (int i = tid; i < 64 * 64; i += NTHREADS) {
        int r = i / 64, c = i % 64;
        qt[c][r] = q[((long long)(b * SS + q0 + r)) * DD + h * DK + c];
        kt[c][r] = kb[((long long)(b * SS + k0 + r)) * DD + h * DK + c];
    }
    __syncthreads();
    int tx = tid % 16, ty = tid / 16;
    float acc[4][4];
#pragma unroll
    for (int i = 0; i < 4; i++)
#pragma unroll
        for (int j = 0; j < 4; j++) acc[i][j] = 0.f;
#pragma unroll
    for (int d = 0; d < 64; d++) {
        float ra[4], rb[4];
#pragma unroll
        for (int i = 0; i < 4; i++) ra[i] = qt[d][ty * 4 + i];
#pragma unroll
        for (int j = 0; j < 4; j++) rb[j] = kt[d][tx * 4 + j];
#pragma unroll
        for (int i = 0; i < 4; i++)
#pragma unroll
            for (int j = 0; j < 4; j++) acc[i][j] += ra[i] * rb[j];
    }
#pragma unroll
    for (int i = 0; i < 4; i++) {
        int gq = q0 + ty * 4 + i;
#pragma unroll
        for (int j = 0; j < 4; j++) {
            int gk = k0 + tx * 4 + j;
            float s = acc[i][j] * 0.125f;
            int m = mask[(long long)b * SS * SS + (long long)gq * SS + gk];
            if (m == 0) s = -1e9f;
            attn[((size_t)z * SS + gq) * SS + gk] = s;
        }
    }
}

// ---------------- row softmax (in place) ----------------
__global__ void softmax_k(float* __restrict__ a) {
    __shared__ float sh[NTHREADS];
    size_t row = blockIdx.x;
    float* p = a + row * SS;
    float v[4];
    int tid = threadIdx.x;
    float m = -1e30f;
#pragma unroll
    for (int i = 0; i < 4; i++) { v[i] = p[tid + i * NTHREADS]; m = fmaxf(m, v[i]); }
    m = blockReduceMax(m, sh);
    float s = 0.f;
#pragma unroll
    for (int i = 0; i < 4; i++) { v[i] = __expf(v[i] - m); s += v[i]; }
    s = blockReduceSum(s, sh);
    float inv = 1.f / s;
#pragma unroll
    for (int i = 0; i < 4; i++) p[tid + i * NTHREADS] = v[i] * inv;
}

// ---------------- head permutes ----------------
__global__ void permv_k(const float* __restrict__ v, float* __restrict__ vp) {
    int i = blockIdx.x * NTHREADS + threadIdx.x;   // over B*H*S*DK
    int d = i % DK, s = (i / DK) % SS, h = (i / (DK * SS)) % HH, b = i / (DK * SS * HH);
    vp[i] = v[((long long)(b * SS + s)) * DD + h * DK + d];
}
__global__ void unpermc_k(const float* __restrict__ cp, float* __restrict__ ctx) {
    int i = blockIdx.x * NTHREADS + threadIdx.x;   // over ctx layout [b,s,h,d]
    int d = i % DK, h = (i / DK) % HH, s = (i / DD) % SS, b = i / (DD * SS);
    ctx[i] = cp[(((long long)(b * HH + h) * SS + s)) * DK + d];
}

// ---------------- gate + routing ----------------
__global__ void zero_counts_k(int* counts) {
    if (threadIdx.x < EE) counts[threadIdx.x] = 0;
}
__global__ void gate_route_k(const float* __restrict__ x2, const float* __restrict__ gw,
                             const float* __restrict__ gb, int* counts, int* etok,
                             int* texp, int* tslot, float* tw) {
    int t = blockIdx.x;
    __shared__ float xs[DD];
    __shared__ float logits[EE];
    const float* row = x2 + (long long)t * DD;
    for (int i = threadIdx.x; i < DD; i += NTHREADS) xs[i] = row[i];
    __syncthreads();
    int w = threadIdx.x / 32, lane = threadIdx.x % 32;
    float s = 0.f;
    for (int d = lane; d < DD; d += 32) s += xs[d] * gw[d * EE + w];
    for (int o = 16; o; o >>= 1) s += __shfl_xor_sync(0xffffffff, s, o);
    if (lane == 0) logits[w] = s + gb[w];
    __syncthreads();
    if (threadIdx.x == 0) {
        float p[EE];
        float m = -1e30f;
        for (int e = 0; e < EE; e++) m = fmaxf(m, logits[e]);
        float sum = 0.f;
        for (int e = 0; e < EE; e++) { p[e] = __expf(logits[e] - m); sum += p[e]; }
        for (int e = 0; e < EE; e++) p[e] /= sum;
        int i0 = 0;
        for (int e = 1; e < EE; e++) if (p[e] > p[i0]) i0 = e;
        int i1 = -1;
        for (int e = 0; e < EE; e++) {
            if (e == i0) continue;
            if (i1 < 0 || p[e] > p[i1]) i1 = e;
        }
        float denom = p[i0] + p[i1] + 1e-6f;
        int s0 = atomicAdd(&counts[i0], 1);
        int s1 = atomicAdd(&counts[i1], 1);
        etok[i0 * TT + s0] = t;
        etok[i1 * TT + s1] = t;
        texp[t * 2] = i0; texp[t * 2 + 1] = i1;
        tslot[t * 2] = s0; tslot[t * 2 + 1] = s1;
        tw[t * 2] = p[i0] / denom; tw[t * 2 + 1] = p[i1] / denom;
    }
}

// ---------------- final combine ----------------
__global__ void combine_k(const float* __restrict__ xres, const int* __restrict__ texp,
                          const int* __restrict__ tslot, const float* __restrict__ tw,
                          const float* __restrict__ moe, float* __restrict__ out) {
    int t = blockIdx.x;
    int e0 = texp[t * 2], e1 = texp[t * 2 + 1];
    int s0 = tslot[t * 2], s1 = tslot[t * 2 + 1];
    float w0 = tw[t * 2], w1 = tw[t * 2 + 1];
    const float* m0 = moe + ((size_t)e0 * TT + s0) * DD;
    const float* m1 = moe + ((size_t)e1 * TT + s1) * DD;
    const float* xr = xres + (long long)t * DD;
    float* o = out + (long long)t * DD;
    for (int i = threadIdx.x; i < DD; i += NTHREADS)
        o[i] = xr[i] + w0 * m0[i] + w1 * m1[i];
}

// ---------------- host side ----------------
static float* devPtrF(const void* sym) {
    void* p = nullptr;
    cudaGetSymbolAddress(&p, sym);
    return (float*)p;
}
static int* devPtrI(const void* sym) {
    void* p = nullptr;
    cudaGetSymbolAddress(&p, sym);
    return (int*)p;
}

extern "C" void kernel_launch(void* const* d_in, const int* in_sizes, int n_in,
                              void* d_out, int out_size) {
    const float* x    = (const float*)d_in[0];
    const int*   mask = (const int*)  d_in[1];
    const float* wq1 = (const float*)d_in[2];  const float* bq1 = (const float*)d_in[3];
    const float* wq2 = (const float*)d_in[4];  const float* bq2 = (const float*)d_in[5];
    const float* wk1 = (const float*)d_in[6];  const float* bk1 = (const float*)d_in[7];
    const float* wk2 = (const float*)d_in[8];  const float* bk2 = (const float*)d_in[9];
    const float* wv1 = (const float*)d_in[10]; const float* bv1 = (const float*)d_in[11];
    const float* wv2 = (const float*)d_in[12]; const float* bv2 = (const float*)d_in[13];
    const float* wo  = (const float*)d_in[14]; const float* bo  = (const float*)d_in[15];
    const float* ln1g = (const float*)d_in[16]; const float* ln1b = (const float*)d_in[17];
    const float* ln2g = (const float*)d_in[18]; const float* ln2b = (const float*)d_in[19];
    const float* gw  = (const float*)d_in[20]; const float* gb  = (const float*)d_in[21];
    const float* ew1 = (const float*)d_in[22]; const float* eb1 = (const float*)d_in[23];
    const float* ew2 = (const float*)d_in[24]; const float* eb2 = (const float*)d_in[25];
    const float* ew3 = (const float*)d_in[26]; const float* eb3 = (const float*)d_in[27];
    float* out = (float*)d_out;

    float* x2a  = devPtrF(g_x2a);
    float* tmp1 = devPtrF(g_tmp1);
    float* tmp2 = devPtrF(g_tmp2);
    float* qb   = devPtrF(g_q);
    float* kb   = devPtrF(g_kk);
    float* vb   = devPtrF(g_v);
    float* attn = devPtrF(g_attn);
    float* vp   = devPtrF(g_vp);
    float* cp   = devPtrF(g_cp);
    float* ctx  = devPtrF(g_ctx);
    float* xres = devPtrF(g_xres);
    float* x2b  = devPtrF(g_x2b);
    float* mh   = devPtrF(g_mh);
    float* moe  = devPtrF(g_moe);
    int* counts = devPtrI(g_counts);
    int* etok   = devPtrI(g_etok);
    int* texp   = devPtrI(g_texp);
    int* tslot  = devPtrI(g_tslot);
    float* tw   = devPtrF(g_tw);

    // 1) LN1
    ln_k<<<TT, NTHREADS>>>(x, ln1g, ln1b, x2a);

    // 2) SwiGLU projections q,k,v
    dim3 gProj((TT + 127) / 128, DD / 128, 1);
    long long nTD = (long long)TT * DD;
    int gridElem = (int)((nTD + NTHREADS - 1) / NTHREADS);

    gemm_k<128,128,8,8,8,0><<<gProj, NTHREADS>>>(x2a, DD, 0, wq1, DD, 0, bq1, nullptr, tmp1, DD, 0, TT, nullptr, DD, DD);
    gemm_k<128,128,8,8,8,0><<<gProj, NTHREADS>>>(x2a, DD, 0, wq2, DD, 0, bq2, nullptr, tmp2, DD, 0, TT, nullptr, DD, DD);
    swiglu_k<<<gridElem, NTHREADS>>>(tmp1, tmp2, qb, nTD, nullptr, 0);

    gemm_k<128,128,8,8,8,0><<<gProj, NTHREADS>>>(x2a, DD, 0, wk1, DD, 0, bk1, nullptr, tmp1, DD, 0, TT, nullptr, DD, DD);
    gemm_k<128,128,8,8,8,0><<<gProj, NTHREADS>>>(x2a, DD, 0, wk2, DD, 0, bk2, nullptr, tmp2, DD, 0, TT, nullptr, DD, DD);
    swiglu_k<<<gridElem, NTHREADS>>>(tmp1, tmp2, kb, nTD, nullptr, 0);

    gemm_k<128,128,8,8,8,0><<<gProj, NTHREADS>>>(x2a, DD, 0, wv1, DD, 0, bv1, nullptr, tmp1, DD, 0, TT, nullptr, DD, DD);
    gemm_k<128,128,8,8,8,0><<<gProj, NTHREADS>>>(x2a, DD, 0, wv2, DD, 0, bv2, nullptr, tmp2, DD, 0, TT, nullptr, DD, DD);
    swiglu_k<<<gridElem, NTHREADS>>>(tmp1, tmp2, vb, nTD, nullptr, 0);

    // 3) attention scores + softmax
    scores_k<<<dim3(SS / 64, SS / 64, BB * HH), NTHREADS>>>(qb, kb, mask, attn);
    softmax_k<<<BB * HH * SS, NTHREADS>>>(attn);

    // 4) ctx = attn @ v  (batched over b,h)
    permv_k<<<gridElem, NTHREADS>>>(vb, vp);
    gemm_k<128,64,8,8,4,0><<<dim3(SS / 128, 1, BB * HH), NTHREADS>>>(
        attn, SS, (long long)SS * SS,
        vp, DK, (long long)SS * DK,
        nullptr, nullptr,
        cp, DK, (long long)SS * DK,
        SS, nullptr, DK, SS);
    unpermc_k<<<gridElem, NTHREADS>>>(cp, ctx);

    // 5) out proj + residual
    gemm_k<128,128,8,8,8,1><<<gProj, NTHREADS>>>(ctx, DD, 0, wo, DD, 0, bo, x, xres, DD, 0, TT, nullptr, DD, DD);

    // 6) LN2
    ln_k<<<TT, NTHREADS>>>(xres, ln2g, ln2b, x2b);

    // 7) gate + routing
    zero_counts_k<<<1, 32>>>(counts);
    gate_route_k<<<TT, NTHREADS>>>(x2b, gw, gb, counts, etok, texp, tslot, tw);

    // 8) MoE experts (gathered; worst-case grids with early exit)
    dim3 gE1((TT + 127) / 128, FF / 128, 1);
    dim3 gE2((TT + 127) / 128, DD / 128, 1);
    long long nTF = (long long)TT * FF;
    int gridElemF = (int)((nTF + NTHREADS - 1) / NTHREADS);
    for (int e = 0; e < EE; e++) {
        const int* cnt = counts + e;
        const int* tok = etok + e * TT;
        ggemm_k<128,128,8,8,8><<<gE1, NTHREADS>>>(x2b, DD, tok, cnt,
            ew1 + (long long)e * DD * FF, FF, eb1 + e * FF, tmp1, FF, FF, DD);
        ggemm_k<128,128,8,8,8><<<gE1, NTHREADS>>>(x2b, DD, tok, cnt,
            ew3 + (long long)e * DD * FF, FF, eb3 + e * FF, tmp2, FF, FF, DD);
        swiglu_k<<<gridElemF, NTHREADS>>>(tmp1, tmp2, mh, nTF, cnt, FF);
        gemm_k<128,128,8,8,8,0><<<gE2, NTHREADS>>>(mh, FF, 0,
            ew2 + (long long)e * FF * DD, DD, 0, eb2 + e * DD, nullptr,
            moe + (size_t)e * TT * DD, DD, 0, TT, cnt, DD, FF);
    }

    // 9) combine
    combine_k<<<TT, NTHREADS>>>(xres, texp, tslot, tw, moe, out);
}

// round 3
// speedup vs baseline: 2.1665x; 2.1665x over previous
#include <cuda_runtime.h>
#include <cuda_bf16.h>
#include <math.h>
#include <stdint.h>

// Problem dims
#define BB 4
#define SS 1024
#define DD 1024
#define FF 2048
#define HH 16
#define EE 8
#define DK 64
#define TT (BB*SS)          // 4096 tokens
#define NTHREADS 256
typedef long long ll;

// ---------------- static device scratch ----------------
__device__ float g_x2a[TT*DD];
__device__ float g_tmp1[TT*FF];
__device__ float g_tmp2[TT*FF];
__device__ float g_q[TT*DD];
__device__ float g_kk[TT*DD];
__device__ float g_v[TT*DD];
__device__ float g_attn[(size_t)BB*HH*SS*SS];   // 268MB
__device__ float g_ctx[TT*DD];
__device__ float g_xres[TT*DD];
__device__ float g_x2b[TT*DD];
__device__ float g_mh[TT*FF];
__device__ float g_moe[(size_t)EE*TT*DD];       // 134MB
__device__ int   g_counts[EE];
__device__ int   g_etok[EE*TT];
__device__ int   g_texp[TT*2];
__device__ int   g_tslot[TT*2];
__device__ float g_tw[TT*2];

// ---------------- helpers ----------------
__device__ __forceinline__ float blockReduceSum(float v, float* sh) {
    int tid = threadIdx.x;
    sh[tid] = v; __syncthreads();
    for (int s = 128; s > 0; s >>= 1) {
        if (tid < s) sh[tid] += sh[tid + s];
        __syncthreads();
    }
    float r = sh[0]; __syncthreads();
    return r;
}
__device__ __forceinline__ float blockReduceMax(float v, float* sh) {
    int tid = threadIdx.x;
    sh[tid] = v; __syncthreads();
    for (int s = 128; s > 0; s >>= 1) {
        if (tid < s) sh[tid] = fmaxf(sh[tid], sh[tid + s]);
        __syncthreads();
    }
    float r = sh[0]; __syncthreads();
    return r;
}

__device__ __forceinline__ uint32_t f2tf(float f) {
    uint32_t u;
    asm("cvt.rna.tf32.f32 %0, %1;" : "=r"(u) : "f"(f));
    return u;
}
__device__ __forceinline__ void mma_tf32(float4& d, const uint32_t* a, const uint32_t* b) {
    asm volatile(
        "mma.sync.aligned.m16n8k8.row.col.f32.tf32.tf32.f32 "
        "{%0,%1,%2,%3}, {%4,%5,%6,%7}, {%8,%9}, {%0,%1,%2,%3};"
        : "+f"(d.x), "+f"(d.y), "+f"(d.z), "+f"(d.w)
        : "r"(a[0]), "r"(a[1]), "r"(a[2]), "r"(a[3]), "r"(b[0]), "r"(b[1]));
}

// ---------------- LayerNorm ----------------
__global__ void ln_k(const float* __restrict__ x, const float* __restrict__ g,
                     const float* __restrict__ b, float* __restrict__ out) {
    __shared__ float sh[NTHREADS];
    int r = blockIdx.x;
    const float* row = x + (size_t)r * DD;
    float s = 0.f;
    for (int i = threadIdx.x; i < DD; i += NTHREADS) s += row[i];
    float mean = blockReduceSum(s, sh) * (1.0f / DD);
    float v = 0.f;
    for (int i = threadIdx.x; i < DD; i += NTHREADS) {
        float d = row[i] - mean; v += d * d;
    }
    float var = blockReduceSum(v, sh) * (1.0f / DD);
    float inv = rsqrtf(var + 1e-5f);
    float* o = out + (size_t)r * DD;
    for (int i = threadIdx.x; i < DD; i += NTHREADS)
        o[i] = (row[i] - mean) * inv * g[i] + b[i];
}

// ================= tensor-core tf32 GEMM =================
// C[M,N] = A @ B, batched via blockIdx.z with (zb,zh) = (z/ZH, z%ZH) offsets.
// EPI: 0 = +bias, 1 = +bias+R residual, 2 = *0.125 + mask(-1e9)
// GATHER: A rows gathered via tok[] (slots), M from *Mptr.
// TRANSB: B stored [N,K] row-major (B^T access).
// Fixed: BK=32, 8 warps (256 threads).
template<int BM, int BN, int WGM, int WGN, int EPI, int GATHER, int TRANSB>
__global__ void tcgemm(const float* __restrict__ A, int lda, ll sAb, ll sAh,
                       const float* __restrict__ Bm, int ldb, ll sBb, ll sBh,
                       const float* __restrict__ bias,
                       const float* __restrict__ R,
                       const int* __restrict__ maskp,
                       float* __restrict__ C, int ldc, ll sCb, ll sCh,
                       int ZH, int M, const int* __restrict__ Mptr, int Kd,
                       const int* __restrict__ tok) {
    constexpr int BK = 32;
    constexpr int KT = 4;               // 8-wide k-tiles per BK
    constexpr int WM = BM / WGM;
    constexpr int WN = BN / WGN;
    constexpr int MT = WM / 16;
    constexpr int NT = WN / 8;
    static_assert(WGM * WGN == 8, "8 warps");

    if (Mptr) M = *Mptr;
    int bm0 = blockIdx.x * BM;
    if (bm0 >= M) return;
    int bn0 = blockIdx.y * BN;
    int z = blockIdx.z;
    int zb = z / ZH, zh = z - zb * ZH;
    A  += (ll)zb * sAb + (ll)zh * sAh;
    Bm += (ll)zb * sBb + (ll)zh * sBh;
    C  += (ll)zb * sCb + (ll)zh * sCh;

    __shared__ uint32_t As[BM * BK];
    __shared__ uint32_t Bs[BK * BN];
    __shared__ int toks[GATHER ? BM : 1];

    int tid = threadIdx.x;
    if (GATHER) {
        for (int i = tid; i < BM; i += NTHREADS) {
            int gr = bm0 + i;
            toks[i] = (gr < M) ? tok[gr] : -1;
        }
        __syncthreads();
    }

    int wid = tid >> 5, lane = tid & 31;
    int wm = wid / WGN, wn = wid - wm * WGN;
    int mbase = wm * (WM / 16);
    int nbase = wn * (WN / 8);

    float4 acc[MT][NT];
#pragma unroll
    for (int i = 0; i < MT; i++)
#pragma unroll
        for (int j = 0; j < NT; j++) acc[i][j] = make_float4(0.f, 0.f, 0.f, 0.f);

    for (int k0 = 0; k0 < Kd; k0 += BK) {
        // ---- load A tile into fragment-permuted smem ----
        constexpr int AF4 = BM / 32;  // BM rows * 8 f4 / 256 threads
#pragma unroll
        for (int it = 0; it < AF4; it++) {
            int flat = it * NTHREADS + tid;
            int row = flat >> 3, c4 = flat & 7;
            float4 v;
            if (GATHER) {
                int tk = toks[row];
                v = (tk >= 0) ? *(const float4*)(A + (ll)tk * lda + k0 + c4 * 4)
                              : make_float4(0.f, 0.f, 0.f, 0.f);
            } else {
                v = *(const float4*)(A + (ll)(bm0 + row) * lda + k0 + c4 * 4);
            }
            float vv[4] = {v.x, v.y, v.z, v.w};
            int mt = row >> 4, r = row & 15;
#pragma unroll
            for (int e = 0; e < 4; e++) {
                int c = c4 * 4 + e;
                int kt = c >> 3, cc = c & 7;
                int ln = (r & 7) * 4 + (cc & 3);
                int rg = (r >> 3) + 2 * (cc >> 2);
                As[(mt * KT + kt) * 128 + ln * 4 + rg] = f2tf(vv[e]);
            }
        }
        // ---- load B tile ----
        if (TRANSB) {
            constexpr int BF4 = BN / 32;
#pragma unroll
            for (int it = 0; it < BF4; it++) {
                int flat = it * NTHREADS + tid;
                int nrow = flat >> 3, c4 = flat & 7;
                float4 v = *(const float4*)(Bm + (ll)(bn0 + nrow) * ldb + k0 + c4 * 4);
                float vv[4] = {v.x, v.y, v.z, v.w};
                int nt = nrow >> 3, nn = nrow & 7;
#pragma unroll
                for (int e = 0; e < 4; e++) {
                    int k = c4 * 4 + e;
                    int kt = k >> 3, k7 = k & 7;
                    int ln = nn * 4 + (k7 & 3);
                    int rg = k7 >> 2;
                    Bs[(nt * KT + kt) * 64 + ln * 2 + rg] = f2tf(vv[e]);
                }
            }
        } else {
            constexpr int RF4 = BN / 4;               // float4 per k-row
            constexpr int BF4 = (BK * BN) / 4 / NTHREADS;
#pragma unroll
            for (int it = 0; it < BF4; it++) {
                int flat = it * NTHREADS + tid;
                int kk = flat / RF4, c4 = flat - kk * RF4;
                float4 v = *(const float4*)(Bm + (ll)(k0 + kk) * ldb + bn0 + c4 * 4);
                float vv[4] = {v.x, v.y, v.z, v.w};
                int kt = kk >> 3, k7 = kk & 7;
#pragma unroll
                for (int e = 0; e < 4; e++) {
                    int n = c4 * 4 + e;
                    int nt = n >> 3, nn = n & 7;
                    int ln = nn * 4 + (k7 & 3);
                    int rg = k7 >> 2;
                    Bs[(nt * KT + kt) * 64 + ln * 2 + rg] = f2tf(vv[e]);
                }
            }
        }
        __syncthreads();
        // ---- compute ----
#pragma unroll
        for (int kt = 0; kt < KT; kt++) {
            uint4 afr[MT];
            uint2 bfr[NT];
#pragma unroll
            for (int mt = 0; mt < MT; mt++)
                afr[mt] = *(const uint4*)&As[((mbase + mt) * KT + kt) * 128 + lane * 4];
#pragma unroll
            for (int nt = 0; nt < NT; nt++)
                bfr[nt] = *(const uint2*)&Bs[((nbase + nt) * KT + kt) * 64 + lane * 2];
#pragma unroll
            for (int mt = 0; mt < MT; mt++)
#pragma unroll
                for (int nt = 0; nt < NT; nt++)
                    mma_tf32(acc[mt][nt], (const uint32_t*)&afr[mt], (const uint32_t*)&bfr[nt]);
        }
        __syncthreads();
    }

    // ---- epilogue ----
#pragma unroll
    for (int mt = 0; mt < MT; mt++) {
        int r0 = bm0 + wm * WM + mt * 16 + (lane >> 2);
        int r1 = r0 + 8;
#pragma unroll
        for (int nt = 0; nt < NT; nt++) {
            int col = bn0 + wn * WN + nt * 8 + (lane & 3) * 2;
            float v0 = acc[mt][nt].x, v1 = acc[mt][nt].y;
            float v2 = acc[mt][nt].z, v3 = acc[mt][nt].w;
            if (EPI == 2) {
                v0 *= 0.125f; v1 *= 0.125f; v2 *= 0.125f; v3 *= 0.125f;
                const int* mrow0 = maskp + (ll)zb * SS * SS + (ll)r0 * SS + col;
                const int* mrow1 = maskp + (ll)zb * SS * SS + (ll)r1 * SS + col;
                if (mrow0[0] == 0) v0 = -1e9f;
                if (mrow0[1] == 0) v1 = -1e9f;
                if (mrow1[0] == 0) v2 = -1e9f;
                if (mrow1[1] == 0) v3 = -1e9f;
            } else {
                if (bias) {
                    float b0 = bias[col], b1 = bias[col + 1];
                    v0 += b0; v1 += b1; v2 += b0; v3 += b1;
                }
                if (EPI == 1) {
                    v0 += R[(ll)r0 * ldc + col];
                    v1 += R[(ll)r0 * ldc + col + 1];
                    v2 += R[(ll)r1 * ldc + col];
                    v3 += R[(ll)r1 * ldc + col + 1];
                }
            }
            if (r0 < M) {
                C[(ll)r0 * ldc + col] = v0;
                C[(ll)r0 * ldc + col + 1] = v1;
            }
            if (r1 < M) {
                C[(ll)r1 * ldc + col] = v2;
                C[(ll)r1 * ldc + col + 1] = v3;
            }
        }
    }
}

// ---------------- SwiGLU elementwise ----------------
__global__ void swiglu_k(const float* __restrict__ a, const float* __restrict__ b,
                         float* __restrict__ o, ll n,
                         const int* __restrict__ cntPtr, int cols) {
    ll i = (ll)blockIdx.x * NTHREADS + threadIdx.x;
    ll nn = cntPtr ? (ll)(*cntPtr) * cols : n;
    if (i < nn) {
        float x = a[i];
        o[i] = (x / (1.f + __expf(-x))) * b[i];
    }
}

// ---------------- row softmax (in place) ----------------
__global__ void softmax_k(float* __restrict__ a) {
    __shared__ float sh[NTHREADS];
    size_t row = blockIdx.x;
    float* p = a + row * SS;
    float v[4];
    int tid = threadIdx.x;
    float m = -1e30f;
#pragma unroll
    for (int i = 0; i < 4; i++) { v[i] = p[tid + i * NTHREADS]; m = fmaxf(m, v[i]); }
    m = blockReduceMax(m, sh);
    float s = 0.f;
#pragma unroll
    for (int i = 0; i < 4; i++) { v[i] = __expf(v[i] - m); s += v[i]; }
    s = blockReduceSum(s, sh);
    float inv = 1.f / s;
#pragma unroll
    for (int i = 0; i < 4; i++) p[tid + i * NTHREADS] = v[i] * inv;
}

// ---------------- gate + routing ----------------
__global__ void zero_counts_k(int* counts) {
    if (threadIdx.x < EE) counts[threadIdx.x] = 0;
}
__global__ void gate_route_k(const float* __restrict__ x2, const float* __restrict__ gw,
                             const float* __restrict__ gb, int* counts, int* etok,
                             int* texp, int* tslot, float* tw) {
    int t = blockIdx.x;
    __shared__ float xs[DD];
    __shared__ float logits[EE];
    const float* row = x2 + (ll)t * DD;
    for (int i = threadIdx.x; i < DD; i += NTHREADS) xs[i] = row[i];
    __syncthreads();
    int w = threadIdx.x / 32, lane = threadIdx.x % 32;
    float s = 0.f;
    for (int d = lane; d < DD; d += 32) s += xs[d] * gw[d * EE + w];
    for (int o = 16; o; o >>= 1) s += __shfl_xor_sync(0xffffffff, s, o);
    if (lane == 0) logits[w] = s + gb[w];
    __syncthreads();
    if (threadIdx.x == 0) {
        float p[EE];
        float m = -1e30f;
        for (int e = 0; e < EE; e++) m = fmaxf(m, logits[e]);
        float sum = 0.f;
        for (int e = 0; e < EE; e++) { p[e] = __expf(logits[e] - m); sum += p[e]; }
        for (int e = 0; e < EE; e++) p[e] /= sum;
        int i0 = 0;
        for (int e = 1; e < EE; e++) if (p[e] > p[i0]) i0 = e;
        int i1 = -1;
        for (int e = 0; e < EE; e++) {
            if (e == i0) continue;
            if (i1 < 0 || p[e] > p[i1]) i1 = e;
        }
        float denom = p[i0] + p[i1] + 1e-6f;
        int s0 = atomicAdd(&counts[i0], 1);
        int s1 = atomicAdd(&counts[i1], 1);
        etok[i0 * TT + s0] = t;
        etok[i1 * TT + s1] = t;
        texp[t * 2] = i0; texp[t * 2 + 1] = i1;
        tslot[t * 2] = s0; tslot[t * 2 + 1] = s1;
        tw[t * 2] = p[i0] / denom; tw[t * 2 + 1] = p[i1] / denom;
    }
}

// ---------------- final combine ----------------
__global__ void combine_k(const float* __restrict__ xres, const int* __restrict__ texp,
                          const int* __restrict__ tslot, const float* __restrict__ tw,
                          const float* __restrict__ moe, float* __restrict__ out) {
    int t = blockIdx.x;
    int e0 = texp[t * 2], e1 = texp[t * 2 + 1];
    int s0 = tslot[t * 2], s1 = tslot[t * 2 + 1];
    float w0 = tw[t * 2], w1 = tw[t * 2 + 1];
    const float* m0 = moe + ((size_t)e0 * TT + s0) * DD;
    const float* m1 = moe + ((size_t)e1 * TT + s1) * DD;
    const float* xr = xres + (ll)t * DD;
    float* o = out + (ll)t * DD;
    for (int i = threadIdx.x; i < DD; i += NTHREADS)
        o[i] = xr[i] + w0 * m0[i] + w1 * m1[i];
}

// ---------------- host side ----------------
static float* devPtrF(const void* sym) {
    void* p = nullptr;
    cudaGetSymbolAddress(&p, sym);
    return (float*)p;
}
static int* devPtrI(const void* sym) {
    void* p = nullptr;
    cudaGetSymbolAddress(&p, sym);
    return (int*)p;
}

extern "C" void kernel_launch(void* const* d_in, const int* in_sizes, int n_in,
                              void* d_out, int out_size) {
    const float* x    = (const float*)d_in[0];
    const int*   mask = (const int*)  d_in[1];
    const float* wq1 = (const float*)d_in[2];  const float* bq1 = (const float*)d_in[3];
    const float* wq2 = (const float*)d_in[4];  const float* bq2 = (const float*)d_in[5];
    const float* wk1 = (const float*)d_in[6];  const float* bk1 = (const float*)d_in[7];
    const float* wk2 = (const float*)d_in[8];  const float* bk2 = (const float*)d_in[9];
    const float* wv1 = (const float*)d_in[10]; const float* bv1 = (const float*)d_in[11];
    const float* wv2 = (const float*)d_in[12]; const float* bv2 = (const float*)d_in[13];
    const float* wo  = (const float*)d_in[14]; const float* bo  = (const float*)d_in[15];
    const float* ln1g = (const float*)d_in[16]; const float* ln1b = (const float*)d_in[17];
    const float* ln2g = (const float*)d_in[18]; const float* ln2b = (const float*)d_in[19];
    const float* gw  = (const float*)d_in[20]; const float* gb  = (const float*)d_in[21];
    const float* ew1 = (const float*)d_in[22]; const float* eb1 = (const float*)d_in[23];
    const float* ew2 = (const float*)d_in[24]; const float* eb2 = (const float*)d_in[25];
    const float* ew3 = (const float*)d_in[26]; const float* eb3 = (const float*)d_in[27];
    float* out = (float*)d_out;

    float* x2a  = devPtrF(g_x2a);
    float* tmp1 = devPtrF(g_tmp1);
    float* tmp2 = devPtrF(g_tmp2);
    float* qb   = devPtrF(g_q);
    float* kb   = devPtrF(g_kk);
    float* vb   = devPtrF(g_v);
    float* attn = devPtrF(g_attn);
    float* ctx  = devPtrF(g_ctx);
    float* xres = devPtrF(g_xres);
    float* x2b  = devPtrF(g_x2b);
    float* mh   = devPtrF(g_mh);
    float* moe  = devPtrF(g_moe);
    int* counts = devPtrI(g_counts);
    int* etok   = devPtrI(g_etok);
    int* texp   = devPtrI(g_texp);
    int* tslot  = devPtrI(g_tslot);
    float* tw   = devPtrF(g_tw);

    // 1) LN1
    ln_k<<<TT, NTHREADS>>>(x, ln1g, ln1b, x2a);

    // 2) SwiGLU projections q,k,v
    dim3 gProj(TT / 128, DD / 128, 1);
    ll nTD = (ll)TT * DD;
    int gridElem = (int)((nTD + NTHREADS - 1) / NTHREADS);

    tcgemm<128,128,2,4,0,0,0><<<gProj, NTHREADS>>>(x2a, DD,0,0, wq1, DD,0,0, bq1, nullptr, nullptr, tmp1, DD,0,0, 1, TT, nullptr, DD, nullptr);
    tcgemm<128,128,2,4,0,0,0><<<gProj, NTHREADS>>>(x2a, DD,0,0, wq2, DD,0,0, bq2, nullptr, nullptr, tmp2, DD,0,0, 1, TT, nullptr, DD, nullptr);
    swiglu_k<<<gridElem, NTHREADS>>>(tmp1, tmp2, qb, nTD, nullptr, 0);

    tcgemm<128,128,2,4,0,0,0><<<gProj, NTHREADS>>>(x2a, DD,0,0, wk1, DD,0,0, bk1, nullptr, nullptr, tmp1, DD,0,0, 1, TT, nullptr, DD, nullptr);
    tcgemm<128,128,2,4,0,0,0><<<gProj, NTHREADS>>>(x2a, DD,0,0, wk2, DD,0,0, bk2, nullptr, nullptr, tmp2, DD,0,0, 1, TT, nullptr, DD, nullptr);
    swiglu_k<<<gridElem, NTHREADS>>>(tmp1, tmp2, kb, nTD, nullptr, 0);

    tcgemm<128,128,2,4,0,0,0><<<gProj, NTHREADS>>>(x2a, DD,0,0, wv1, DD,0,0, bv1, nullptr, nullptr, tmp1, DD,0,0, 1, TT, nullptr, DD, nullptr);
    tcgemm<128,128,2,4,0,0,0><<<gProj, NTHREADS>>>(x2a, DD,0,0, wv2, DD,0,0, bv2, nullptr, nullptr, tmp2, DD,0,0, 1, TT, nullptr, DD, nullptr);
    swiglu_k<<<gridElem, NTHREADS>>>(tmp1, tmp2, vb, nTD, nullptr, 0);

    // 3) attention scores (batched over b,h; B = K buffer transposed) + softmax
    tcgemm<128,128,2,4,2,0,1><<<dim3(SS/128, SS/128, BB*HH), NTHREADS>>>(
        qb, DD, (ll)SS*DD, 64,
        kb, DD, (ll)SS*DD, 64,
        nullptr, nullptr, mask,
        attn, SS, (ll)HH*SS*SS, (ll)SS*SS,
        HH, SS, nullptr, DK, nullptr);
    softmax_k<<<BB * HH * SS, NTHREADS>>>(attn);

    // 4) ctx = attn @ v  (batched, writes [b,s,h,d] directly)
    tcgemm<128,64,4,2,0,0,0><<<dim3(SS/128, 1, BB*HH), NTHREADS>>>(
        attn, SS, (ll)HH*SS*SS, (ll)SS*SS,
        vb, DD, (ll)SS*DD, 64,
        nullptr, nullptr, nullptr,
        ctx, DD, (ll)SS*DD, 64,
        HH, SS, nullptr, SS, nullptr);

    // 5) out proj + residual
    tcgemm<128,128,2,4,1,0,0><<<gProj, NTHREADS>>>(ctx, DD,0,0, wo, DD,0,0, bo, x, nullptr, xres, DD,0,0, 1, TT, nullptr, DD, nullptr);

    // 6) LN2
    ln_k<<<TT, NTHREADS>>>(xres, ln2g, ln2b, x2b);

    // 7) gate + routing
    zero_counts_k<<<1, 32>>>(counts);
    gate_route_k<<<TT, NTHREADS>>>(x2b, gw, gb, counts, etok, texp, tslot, tw);

    // 8) MoE experts (gathered; worst-case grids with early exit)
    dim3 gE1(TT / 128, FF / 128, 1);
    dim3 gE2(TT / 128, DD / 128, 1);
    ll nTF = (ll)TT * FF;
    int gridElemF = (int)((nTF + NTHREADS - 1) / NTHREADS);
    for (int e = 0; e < EE; e++) {
        const int* cnt = counts + e;
        const int* tok = etok + e * TT;
        tcgemm<128,128,2,4,0,1,0><<<gE1, NTHREADS>>>(x2b, DD,0,0,
            ew1 + (ll)e * DD * FF, FF,0,0, eb1 + e * FF, nullptr, nullptr,
            tmp1, FF,0,0, 1, 0, cnt, DD, tok);
        tcgemm<128,128,2,4,0,1,0><<<gE1, NTHREADS>>>(x2b, DD,0,0,
            ew3 + (ll)e * DD * FF, FF,0,0, eb3 + e * FF, nullptr, nullptr,
            tmp2, FF,0,0, 1, 0, cnt, DD, tok);
        swiglu_k<<<gridElemF, NTHREADS>>>(tmp1, tmp2, mh, nTF, cnt, FF);
        tcgemm<128,128,2,4,0,0,0><<<gE2, NTHREADS>>>(mh, FF,0,0,
            ew2 + (ll)e * FF * DD, DD,0,0, eb2 + e * DD, nullptr, nullptr,
            moe + (size_t)e * TT * DD, DD,0,0, 1, 0, cnt, FF, nullptr);
    }

    // 9) combine
    combine_k<<<TT, NTHREADS>>>(xres, texp, tslot, tw, moe, out);
}

// round 4
// speedup vs baseline: 7.7426x; 3.5737x over previous
#include <cuda_runtime.h>
#include <cuda_bf16.h>
#include <math.h>
#include <stdint.h>

// Problem dims
#define BB 4
#define SS 1024
#define DD 1024
#define FF 2048
#define HH 16
#define EE 8
#define DK 64
#define TT (BB*SS)          // 4096 tokens
#define NTHREADS 256
typedef long long ll;

// ---------------- static device scratch ----------------
__device__ float g_x2a[TT*DD];
__device__ float g_tmp1[TT*FF];
__device__ float g_q[TT*DD];
__device__ float g_kk[TT*DD];
__device__ float g_v[TT*DD];
__device__ float g_attn[(size_t)BB*HH*SS*SS];   // 268MB
__device__ float g_ctx[TT*DD];
__device__ float g_xres[TT*DD];
__device__ float g_x2b[TT*DD];
__device__ float g_mh[TT*FF];
__device__ float g_moe[(size_t)EE*TT*DD];       // 134MB
__device__ int   g_counts[EE];
__device__ int   g_etok[EE*TT];
__device__ int   g_texp[TT*2];
__device__ int   g_tslot[TT*2];
__device__ float g_tw[TT*2];

// ---------------- helpers ----------------
__device__ __forceinline__ float blockReduceSum(float v, float* sh) {
    int tid = threadIdx.x;
    sh[tid] = v; __syncthreads();
    for (int s = 128; s > 0; s >>= 1) {
        if (tid < s) sh[tid] += sh[tid + s];
        __syncthreads();
    }
    float r = sh[0]; __syncthreads();
    return r;
}
__device__ __forceinline__ float blockReduceMax(float v, float* sh) {
    int tid = threadIdx.x;
    sh[tid] = v; __syncthreads();
    for (int s = 128; s > 0; s >>= 1) {
        if (tid < s) sh[tid] = fmaxf(sh[tid], sh[tid + s]);
        __syncthreads();
    }
    float r = sh[0]; __syncthreads();
    return r;
}
__device__ __forceinline__ void mma_tf32(float4& d, const uint32_t* a, const uint32_t* b) {
    asm volatile(
        "mma.sync.aligned.m16n8k8.row.col.f32.tf32.tf32.f32 "
        "{%0,%1,%2,%3}, {%4,%5,%6,%7}, {%8,%9}, {%0,%1,%2,%3};"
        : "+f"(d.x), "+f"(d.y), "+f"(d.z), "+f"(d.w)
        : "r"(a[0]), "r"(a[1]), "r"(a[2]), "r"(a[3]), "r"(b[0]), "r"(b[1]));
}
__device__ __forceinline__ void cpa16(float* dst, const float* src, int sz) {
    uint32_t d = (uint32_t)__cvta_generic_to_shared(dst);
    asm volatile("cp.async.cg.shared.global [%0], [%1], 16, %2;\n"
                 :: "r"(d), "l"(src), "r"(sz));
}
__device__ __forceinline__ float siluf(float x) {
    return x / (1.f + __expf(-x));
}

// ---------------- LayerNorm ----------------
__global__ void ln_k(const float* __restrict__ x, const float* __restrict__ g,
                     const float* __restrict__ b, float* __restrict__ out) {
    __shared__ float sh[NTHREADS];
    int r = blockIdx.x;
    const float* row = x + (size_t)r * DD;
    float s = 0.f;
    for (int i = threadIdx.x; i < DD; i += NTHREADS) s += row[i];
    float mean = blockReduceSum(s, sh) * (1.0f / DD);
    float v = 0.f;
    for (int i = threadIdx.x; i < DD; i += NTHREADS) {
        float d = row[i] - mean; v += d * d;
    }
    float var = blockReduceSum(v, sh) * (1.0f / DD);
    float inv = rsqrtf(var + 1e-5f);
    float* o = out + (size_t)r * DD;
    for (int i = threadIdx.x; i < DD; i += NTHREADS)
        o[i] = (row[i] - mean) * inv * g[i] + b[i];
}

// ================= pipelined tensor-core tf32 GEMM =================
// C[M,N] = A @ B, batched via blockIdx.z with (zb,zh) = (z/ZH, z%ZH) offsets.
// EPI: 0 = +bias; 1 = +bias + S residual; 2 = *0.125 + mask(-1e9);
//      3 = silu(S) * (acc + bias)  [fused SwiGLU second half]
// GATHER: A rows gathered via tok[] (slots), M from *Mptr.
// TRANSB: B stored [N,K] row-major (B^T access).
// Fixed: BK=32, 8 warps (256 threads), cp.async 2-stage pipeline,
// raw fp32 bits fed to tf32 MMA (HW truncation).
template<int BM, int BN, int WGM, int WGN, int EPI, int GATHER, int TRANSB>
__global__ void __launch_bounds__(NTHREADS)
tcg(const float* __restrict__ A, int lda, ll sAb, ll sAh,
    const float* __restrict__ Bm, int ldb, ll sBb, ll sBh,
    const float* __restrict__ bias,
    const float* __restrict__ S,
    const int* __restrict__ maskp,
    float* __restrict__ C, int ldc, ll sCb, ll sCh,
    int ZH, int M, const int* __restrict__ Mptr, int Kd,
    const int* __restrict__ tok) {
    constexpr int BK = 32;
    constexpr int KT = 4;
    constexpr int ASTR = 36;                       // BK+4  (stride ≡ 4 mod 32)
    constexpr int BSTR = BN + 8;                   // stride ≡ 8 mod 32
    constexpr int ASZ = BM * ASTR;
    constexpr int BSZ = TRANSB ? BN * ASTR : BK * BSTR;
    constexpr int STG = ASZ + BSZ;
    constexpr int WM = BM / WGM;
    constexpr int WN = BN / WGN;
    constexpr int MT = WM / 16;
    constexpr int NT = WN / 8;
    static_assert(WGM * WGN == 8, "8 warps");

    if (Mptr) M = *Mptr;
    int bm0 = blockIdx.x * BM;
    if (bm0 >= M) return;
    int bn0 = blockIdx.y * BN;
    int z = blockIdx.z;
    int zb = z / ZH, zh = z - zb * ZH;
    A  += (ll)zb * sAb + (ll)zh * sAh;
    Bm += (ll)zb * sBb + (ll)zh * sBh;
    C  += (ll)zb * sCb + (ll)zh * sCh;

    extern __shared__ float smf[];
    int* toks = (int*)(smf + 2 * STG);
    int tid = threadIdx.x;

    if (GATHER) {
        for (int i = tid; i < BM; i += NTHREADS) {
            int gr = bm0 + i;
            toks[i] = (gr < M) ? tok[gr] : -1;
        }
        __syncthreads();
    }

    int wid = tid >> 5, lane = tid & 31;
    int wm = wid / WGN, wn = wid - wm * WGN;
    int lr = lane >> 2, lc = lane & 3;

    auto fill = [&](int st, int k0) {
        float* As = smf + st * STG;
        float* Bs = As + ASZ;
        // A tile: BM rows x 32 floats = BM*8 float4 chunks
#pragma unroll
        for (int it = 0; it < BM * 8 / NTHREADS; it++) {
            int i = it * NTHREADS + tid;
            int row = i >> 3, c4 = i & 7;
            float* dst = As + row * ASTR + c4 * 4;
            const float* src;
            int sz = 16;
            if (GATHER) {
                int tk = toks[row];
                src = A + (ll)(tk < 0 ? 0 : tk) * lda + k0 + c4 * 4;
                if (tk < 0) sz = 0;
            } else {
                src = A + (ll)(bm0 + row) * lda + k0 + c4 * 4;
            }
            cpa16(dst, src, sz);
        }
        if (TRANSB) {
#pragma unroll
            for (int it = 0; it < BN * 8 / NTHREADS; it++) {
                int i = it * NTHREADS + tid;
                int row = i >> 3, c4 = i & 7;
                cpa16(Bs + row * ASTR + c4 * 4,
                      Bm + (ll)(bn0 + row) * ldb + k0 + c4 * 4, 16);
            }
        } else {
            constexpr int RF4 = BN / 4;
#pragma unroll
            for (int it = 0; it < BK * RF4 / NTHREADS; it++) {
                int i = it * NTHREADS + tid;
                int kk = i / RF4, c4 = i - kk * RF4;
                cpa16(Bs + kk * BSTR + c4 * 4,
                      Bm + (ll)(k0 + kk) * ldb + bn0 + c4 * 4, 16);
            }
        }
    };

    float4 acc[MT][NT];
#pragma unroll
    for (int i = 0; i < MT; i++)
#pragma unroll
        for (int j = 0; j < NT; j++) acc[i][j] = make_float4(0.f, 0.f, 0.f, 0.f);

    int nIt = Kd / BK;
    fill(0, 0);
    asm volatile("cp.async.commit_group;\n");

    for (int itK = 0; itK < nIt; itK++) {
        if (itK + 1 < nIt) {
            fill((itK + 1) & 1, (itK + 1) * BK);
            asm volatile("cp.async.commit_group;\n");
            asm volatile("cp.async.wait_group 1;\n");
        } else {
            asm volatile("cp.async.wait_group 0;\n");
        }
        __syncthreads();
        const float* As = smf + (itK & 1) * STG;
        const float* Bs = As + ASZ;
#pragma unroll
        for (int kt = 0; kt < KT; kt++) {
            uint32_t af[MT][4];
            uint32_t bf[NT][2];
#pragma unroll
            for (int mt = 0; mt < MT; mt++) {
                const float* ap = As + (wm * WM + mt * 16 + lr) * ASTR + kt * 8 + lc;
                af[mt][0] = __float_as_uint(ap[0]);
                af[mt][1] = __float_as_uint(ap[8 * ASTR]);
                af[mt][2] = __float_as_uint(ap[4]);
                af[mt][3] = __float_as_uint(ap[8 * ASTR + 4]);
            }
#pragma unroll
            for (int nt = 0; nt < NT; nt++) {
                int nb = wn * WN + nt * 8;
                if (TRANSB) {
                    const float* bp = Bs + (nb + lr) * ASTR + kt * 8 + lc;
                    bf[nt][0] = __float_as_uint(bp[0]);
                    bf[nt][1] = __float_as_uint(bp[4]);
                } else {
                    const float* bp = Bs + (kt * 8 + lc) * BSTR + nb + lr;
                    bf[nt][0] = __float_as_uint(bp[0]);
                    bf[nt][1] = __float_as_uint(bp[4 * BSTR]);
                }
            }
#pragma unroll
            for (int mt = 0; mt < MT; mt++)
#pragma unroll
                for (int nt = 0; nt < NT; nt++)
                    mma_tf32(acc[mt][nt], af[mt], bf[nt]);
        }
        __syncthreads();
    }

    // ---- epilogue ----
#pragma unroll
    for (int mt = 0; mt < MT; mt++) {
        int r0 = bm0 + wm * WM + mt * 16 + lr;
        int r1 = r0 + 8;
#pragma unroll
        for (int nt = 0; nt < NT; nt++) {
            int col = bn0 + wn * WN + nt * 8 + lc * 2;
            float v0 = acc[mt][nt].x, v1 = acc[mt][nt].y;
            float v2 = acc[mt][nt].z, v3 = acc[mt][nt].w;
            if (EPI == 2) {
                v0 *= 0.125f; v1 *= 0.125f; v2 *= 0.125f; v3 *= 0.125f;
                const int* mrow0 = maskp + (ll)zb * SS * SS + (ll)r0 * SS + col;
                const int* mrow1 = maskp + (ll)zb * SS * SS + (ll)r1 * SS + col;
                if (mrow0[0] == 0) v0 = -1e9f;
                if (mrow0[1] == 0) v1 = -1e9f;
                if (mrow1[0] == 0) v2 = -1e9f;
                if (mrow1[1] == 0) v3 = -1e9f;
            } else {
                if (bias) {
                    float b0 = bias[col], b1 = bias[col + 1];
                    v0 += b0; v1 += b1; v2 += b0; v3 += b1;
                }
                if (EPI == 1) {
                    if (r0 < M) {
                        v0 += S[(ll)r0 * ldc + col];
                        v1 += S[(ll)r0 * ldc + col + 1];
                    }
                    if (r1 < M) {
                        v2 += S[(ll)r1 * ldc + col];
                        v3 += S[(ll)r1 * ldc + col + 1];
                    }
                }
                if (EPI == 3) {
                    if (r0 < M) {
                        v0 = siluf(S[(ll)r0 * ldc + col]) * v0;
                        v1 = siluf(S[(ll)r0 * ldc + col + 1]) * v1;
                    }
                    if (r1 < M) {
                        v2 = siluf(S[(ll)r1 * ldc + col]) * v2;
                        v3 = siluf(S[(ll)r1 * ldc + col + 1]) * v3;
                    }
                }
            }
            if (r0 < M) {
                C[(ll)r0 * ldc + col] = v0;
                C[(ll)r0 * ldc + col + 1] = v1;
            }
            if (r1 < M) {
                C[(ll)r1 * ldc + col] = v2;
                C[(ll)r1 * ldc + col + 1] = v3;
            }
        }
    }
}

// ---------------- row softmax (in place) ----------------
__global__ void softmax_k(float* __restrict__ a) {
    __shared__ float sh[NTHREADS];
    size_t row = blockIdx.x;
    float* p = a + row * SS;
    float v[4];
    int tid = threadIdx.x;
    float m = -1e30f;
#pragma unroll
    for (int i = 0; i < 4; i++) { v[i] = p[tid + i * NTHREADS]; m = fmaxf(m, v[i]); }
    m = blockReduceMax(m, sh);
    float s = 0.f;
#pragma unroll
    for (int i = 0; i < 4; i++) { v[i] = __expf(v[i] - m); s += v[i]; }
    s = blockReduceSum(s, sh);
    float inv = 1.f / s;
#pragma unroll
    for (int i = 0; i < 4; i++) p[tid + i * NTHREADS] = v[i] * inv;
}

// ---------------- gate + routing ----------------
__global__ void zero_counts_k(int* counts) {
    if (threadIdx.x < EE) counts[threadIdx.x] = 0;
}
__global__ void gate_route_k(const float* __restrict__ x2, const float* __restrict__ gw,
                             const float* __restrict__ gb, int* counts, int* etok,
                             int* texp, int* tslot, float* tw) {
    int t = blockIdx.x;
    __shared__ float xs[DD];
    __shared__ float logits[EE];
    const float* row = x2 + (ll)t * DD;
    for (int i = threadIdx.x; i < DD; i += NTHREADS) xs[i] = row[i];
    __syncthreads();
    int w = threadIdx.x / 32, lane = threadIdx.x % 32;
    float s = 0.f;
    for (int d = lane; d < DD; d += 32) s += xs[d] * gw[d * EE + w];
    for (int o = 16; o; o >>= 1) s += __shfl_xor_sync(0xffffffff, s, o);
    if (lane == 0) logits[w] = s + gb[w];
    __syncthreads();
    if (threadIdx.x == 0) {
        float p[EE];
        float m = -1e30f;
        for (int e = 0; e < EE; e++) m = fmaxf(m, logits[e]);
        float sum = 0.f;
        for (int e = 0; e < EE; e++) { p[e] = __expf(logits[e] - m); sum += p[e]; }
        for (int e = 0; e < EE; e++) p[e] /= sum;
        int i0 = 0;
        for (int e = 1; e < EE; e++) if (p[e] > p[i0]) i0 = e;
        int i1 = -1;
        for (int e = 0; e < EE; e++) {
            if (e == i0) continue;
            if (i1 < 0 || p[e] > p[i1]) i1 = e;
        }
        float denom = p[i0] + p[i1] + 1e-6f;
        int s0 = atomicAdd(&counts[i0], 1);
        int s1 = atomicAdd(&counts[i1], 1);
        etok[i0 * TT + s0] = t;
        etok[i1 * TT + s1] = t;
        texp[t * 2] = i0; texp[t * 2 + 1] = i1;
        tslot[t * 2] = s0; tslot[t * 2 + 1] = s1;
        tw[t * 2] = p[i0] / denom; tw[t * 2 + 1] = p[i1] / denom;
    }
}

// ---------------- final combine ----------------
__global__ void combine_k(const float* __restrict__ xres, const int* __restrict__ texp,
                          const int* __restrict__ tslot, const float* __restrict__ tw,
                          const float* __restrict__ moe, float* __restrict__ out) {
    int t = blockIdx.x;
    int e0 = texp[t * 2], e1 = texp[t * 2 + 1];
    int s0 = tslot[t * 2], s1 = tslot[t * 2 + 1];
    float w0 = tw[t * 2], w1 = tw[t * 2 + 1];
    const float* m0 = moe + ((size_t)e0 * TT + s0) * DD;
    const float* m1 = moe + ((size_t)e1 * TT + s1) * DD;
    const float* xr = xres + (ll)t * DD;
    float* o = out + (ll)t * DD;
    for (int i = threadIdx.x; i < DD; i += NTHREADS)
        o[i] = xr[i] + w0 * m0[i] + w1 * m1[i];
}

// ---------------- host side ----------------
static float* devPtrF(const void* sym) {
    void* p = nullptr;
    cudaGetSymbolAddress(&p, sym);
    return (float*)p;
}
static int* devPtrI(const void* sym) {
    void* p = nullptr;
    cudaGetSymbolAddress(&p, sym);
    return (int*)p;
}
static int smBytes(int BM, int BN, int transb, int gather) {
    int ASZ = BM * 36;
    int BSZ = transb ? BN * 36 : 32 * (BN + 8);
    return 2 * (ASZ + BSZ) * 4 + (gather ? BM * 4 : 0);
}

extern "C" void kernel_launch(void* const* d_in, const int* in_sizes, int n_in,
                              void* d_out, int out_size) {
    const float* x    = (const float*)d_in[0];
    const int*   mask = (const int*)  d_in[1];
    const float* wq1 = (const float*)d_in[2];  const float* bq1 = (const float*)d_in[3];
    const float* wq2 = (const float*)d_in[4];  const float* bq2 = (const float*)d_in[5];
    const float* wk1 = (const float*)d_in[6];  const float* bk1 = (const float*)d_in[7];
    const float* wk2 = (const float*)d_in[8];  const float* bk2 = (const float*)d_in[9];
    const float* wv1 = (const float*)d_in[10]; const float* bv1 = (const float*)d_in[11];
    const float* wv2 = (const float*)d_in[12]; const float* bv2 = (const float*)d_in[13];
    const float* wo  = (const float*)d_in[14]; const float* bo  = (const float*)d_in[15];
    const float* ln1g = (const float*)d_in[16]; const float* ln1b = (const float*)d_in[17];
    const float* ln2g = (const float*)d_in[18]; const float* ln2b = (const float*)d_in[19];
    const float* gw  = (const float*)d_in[20]; const float* gb  = (const float*)d_in[21];
    const float* ew1 = (const float*)d_in[22]; const float* eb1 = (const float*)d_in[23];
    const float* ew2 = (const float*)d_in[24]; const float* eb2 = (const float*)d_in[25];
    const float* ew3 = (const float*)d_in[26]; const float* eb3 = (const float*)d_in[27];
    float* out = (float*)d_out;

    float* x2a  = devPtrF(g_x2a);
    float* tmp1 = devPtrF(g_tmp1);
    float* qb   = devPtrF(g_q);
    float* kb   = devPtrF(g_kk);
    float* vb   = devPtrF(g_v);
    float* attn = devPtrF(g_attn);
    float* ctx  = devPtrF(g_ctx);
    float* xres = devPtrF(g_xres);
    float* x2b  = devPtrF(g_x2b);
    float* mh   = devPtrF(g_mh);
    float* moe  = devPtrF(g_moe);
    int* counts = devPtrI(g_counts);
    int* etok   = devPtrI(g_etok);
    int* texp   = devPtrI(g_texp);
    int* tslot  = devPtrI(g_tslot);
    float* tw   = devPtrF(g_tw);

    int smP  = smBytes(128, 128, 0, 0);   // plain 128x128
    int smG  = smBytes(128, 128, 0, 1);   // gather 128x128
    int smSc = smBytes(128, 128, 1, 0);   // scores (TRANSB)
    int smCx = smBytes(128, 64, 0, 0);    // ctx 128x64

    cudaFuncSetAttribute(tcg<128,128,2,4,0,0,0>, cudaFuncAttributeMaxDynamicSharedMemorySize, smP);
    cudaFuncSetAttribute(tcg<128,128,2,4,3,0,0>, cudaFuncAttributeMaxDynamicSharedMemorySize, smP);
    cudaFuncSetAttribute(tcg<128,128,2,4,1,0,0>, cudaFuncAttributeMaxDynamicSharedMemorySize, smP);
    cudaFuncSetAttribute(tcg<128,128,2,4,2,0,1>, cudaFuncAttributeMaxDynamicSharedMemorySize, smSc);
    cudaFuncSetAttribute(tcg<128,64,4,2,0,0,0>,  cudaFuncAttributeMaxDynamicSharedMemorySize, smCx);
    cudaFuncSetAttribute(tcg<128,128,2,4,0,1,0>, cudaFuncAttributeMaxDynamicSharedMemorySize, smG);
    cudaFuncSetAttribute(tcg<128,128,2,4,3,1,0>, cudaFuncAttributeMaxDynamicSharedMemorySize, smG);

    // 1) LN1
    ln_k<<<TT, NTHREADS>>>(x, ln1g, ln1b, x2a);

    // 2) SwiGLU projections q,k,v  (second GEMM fuses silu(tmp1)*(.)+bias)
    dim3 gProj(TT / 128, DD / 128, 1);
    tcg<128,128,2,4,0,0,0><<<gProj, NTHREADS, smP>>>(x2a, DD,0,0, wq1, DD,0,0, bq1, nullptr, nullptr, tmp1, DD,0,0, 1, TT, nullptr, DD, nullptr);
    tcg<128,128,2,4,3,0,0><<<gProj, NTHREADS, smP>>>(x2a, DD,0,0, wq2, DD,0,0, bq2, tmp1,   nullptr, qb,   DD,0,0, 1, TT, nullptr, DD, nullptr);
    tcg<128,128,2,4,0,0,0><<<gProj, NTHREADS, smP>>>(x2a, DD,0,0, wk1, DD,0,0, bk1, nullptr, nullptr, tmp1, DD,0,0, 1, TT, nullptr, DD, nullptr);
    tcg<128,128,2,4,3,0,0><<<gProj, NTHREADS, smP>>>(x2a, DD,0,0, wk2, DD,0,0, bk2, tmp1,   nullptr, kb,   DD,0,0, 1, TT, nullptr, DD, nullptr);
    tcg<128,128,2,4,0,0,0><<<gProj, NTHREADS, smP>>>(x2a, DD,0,0, wv1, DD,0,0, bv1, nullptr, nullptr, tmp1, DD,0,0, 1, TT, nullptr, DD, nullptr);
    tcg<128,128,2,4,3,0,0><<<gProj, NTHREADS, smP>>>(x2a, DD,0,0, wv2, DD,0,0, bv2, tmp1,   nullptr, vb,   DD,0,0, 1, TT, nullptr, DD, nullptr);

    // 3) attention scores (batched over b,h) + softmax
    tcg<128,128,2,4,2,0,1><<<dim3(SS/128, SS/128, BB*HH), NTHREADS, smSc>>>(
        qb, DD, (ll)SS*DD, 64,
        kb, DD, (ll)SS*DD, 64,
        nullptr, nullptr, mask,
        attn, SS, (ll)HH*SS*SS, (ll)SS*SS,
        HH, SS, nullptr, DK, nullptr);
    softmax_k<<<BB * HH * SS, NTHREADS>>>(attn);

    // 4) ctx = attn @ v  (batched, writes [b,s,h,d] directly)
    tcg<128,64,4,2,0,0,0><<<dim3(SS/128, 1, BB*HH), NTHREADS, smCx>>>(
        attn, SS, (ll)HH*SS*SS, (ll)SS*SS,
        vb, DD, (ll)SS*DD, 64,
        nullptr, nullptr, nullptr,
        ctx, DD, (ll)SS*DD, 64,
        HH, SS, nullptr, SS, nullptr);

    // 5) out proj + residual
    tcg<128,128,2,4,1,0,0><<<gProj, NTHREADS, smP>>>(ctx, DD,0,0, wo, DD,0,0, bo, x, nullptr, xres, DD,0,0, 1, TT, nullptr, DD, nullptr);

    // 6) LN2
    ln_k<<<TT, NTHREADS>>>(xres, ln2g, ln2b, x2b);

    // 7) gate + routing
    zero_counts_k<<<1, 32>>>(counts);
    gate_route_k<<<TT, NTHREADS>>>(x2b, gw, gb, counts, etok, texp, tslot, tw);

    // 8) MoE experts (gathered; worst-case grids with early exit; SwiGLU fused)
    dim3 gE1(TT / 128, FF / 128, 1);
    dim3 gE2(TT / 128, DD / 128, 1);
    for (int e = 0; e < EE; e++) {
        const int* cnt = counts + e;
        const int* tok = etok + e * TT;
        tcg<128,128,2,4,0,1,0><<<gE1, NTHREADS, smG>>>(x2b, DD,0,0,
            ew1 + (ll)e * DD * FF, FF,0,0, eb1 + e * FF, nullptr, nullptr,
            tmp1, FF,0,0, 1, 0, cnt, DD, tok);
        tcg<128,128,2,4,3,1,0><<<gE1, NTHREADS, smG>>>(x2b, DD,0,0,
            ew3 + (ll)e * DD * FF, FF,0,0, eb3 + e * FF, tmp1, nullptr,
            mh, FF,0,0, 1, 0, cnt, DD, tok);
        tcg<128,128,2,4,0,0,0><<<gE2, NTHREADS, smP>>>(mh, FF,0,0,
            ew2 + (ll)e * FF * DD, DD,0,0, eb2 + e * DD, nullptr, nullptr,
            moe + (size_t)e * TT * DD, DD,0,0, 1, 0, cnt, FF, nullptr);
    }

    // 9) combine
    combine_k<<<TT, NTHREADS>>>(xres, texp, tslot, tw, moe, out);
}

// round 5
// speedup vs baseline: 11.6201x; 1.5008x over previous
#include <cuda_runtime.h>
#include <cuda_bf16.h>
#include <math.h>
#include <stdint.h>

// Problem dims
#define BB 4
#define SS 1024
#define DD 1024
#define FF 2048
#define HH 16
#define EE 8
#define DK 64
#define TT (BB*SS)          // 4096 tokens
typedef long long ll;

// ---------------- static device scratch ----------------
__device__ float g_x2a[TT*DD];
__device__ float g_tmp1[3*TT*DD];               // 3 slices for q1/k1/v1
__device__ float g_qkv[3*TT*DD];                // q,k,v slices
__device__ float g_attn[(size_t)BB*HH*SS*SS];   // 268MB
__device__ float g_ctx[TT*DD];
__device__ float g_xres[TT*DD];
__device__ float g_x2b[TT*DD];
__device__ float g_emid[(size_t)EE*TT*FF];      // 268MB MoE mid
__device__ float g_moe[(size_t)EE*TT*DD];       // 134MB
__device__ int   g_counts[EE];
__device__ int   g_etok[EE*TT];
__device__ int   g_texp[TT*2];
__device__ int   g_tslot[TT*2];
__device__ float g_tw[TT*2];

// ---------------- helpers ----------------
__device__ __forceinline__ float blockReduceSum(float v, float* sh) {
    int tid = threadIdx.x;
    sh[tid] = v; __syncthreads();
    for (int s = 128; s > 0; s >>= 1) {
        if (tid < s) sh[tid] += sh[tid + s];
        __syncthreads();
    }
    float r = sh[0]; __syncthreads();
    return r;
}
__device__ __forceinline__ float blockReduceMax(float v, float* sh) {
    int tid = threadIdx.x;
    sh[tid] = v; __syncthreads();
    for (int s = 128; s > 0; s >>= 1) {
        if (tid < s) sh[tid] = fmaxf(sh[tid], sh[tid + s]);
        __syncthreads();
    }
    float r = sh[0]; __syncthreads();
    return r;
}
__device__ __forceinline__ void mma_tf32(float4& d, const uint32_t* a, const uint32_t* b) {
    asm volatile(
        "mma.sync.aligned.m16n8k8.row.col.f32.tf32.tf32.f32 "
        "{%0,%1,%2,%3}, {%4,%5,%6,%7}, {%8,%9}, {%0,%1,%2,%3};"
        : "+f"(d.x), "+f"(d.y), "+f"(d.z), "+f"(d.w)
        : "r"(a[0]), "r"(a[1]), "r"(a[2]), "r"(a[3]), "r"(b[0]), "r"(b[1]));
}
__device__ __forceinline__ void cpa16(float* dst, const float* src, int sz) {
    uint32_t d = (uint32_t)__cvta_generic_to_shared(dst);
    asm volatile("cp.async.cg.shared.global [%0], [%1], 16, %2;\n"
                 :: "r"(d), "l"(src), "r"(sz));
}
__device__ __forceinline__ void ldsm4(uint32_t* d, const float* p) {
    uint32_t a = (uint32_t)__cvta_generic_to_shared(p);
    asm volatile("ldmatrix.sync.aligned.m8n8.x4.shared.b16 {%0,%1,%2,%3}, [%4];"
                 : "=r"(d[0]), "=r"(d[1]), "=r"(d[2]), "=r"(d[3]) : "r"(a));
}
__device__ __forceinline__ float siluf(float x) {
    return x / (1.f + __expf(-x));
}

// ---------------- LayerNorm ----------------
__global__ void ln_k(const float* __restrict__ x, const float* __restrict__ g,
                     const float* __restrict__ b, float* __restrict__ out) {
    __shared__ float sh[256];
    int r = blockIdx.x;
    const float* row = x + (size_t)r * DD;
    float s = 0.f;
    for (int i = threadIdx.x; i < DD; i += 256) s += row[i];
    float mean = blockReduceSum(s, sh) * (1.0f / DD);
    float v = 0.f;
    for (int i = threadIdx.x; i < DD; i += 256) {
        float d = row[i] - mean; v += d * d;
    }
    float var = blockReduceSum(v, sh) * (1.0f / DD);
    float inv = rsqrtf(var + 1e-5f);
    float* o = out + (size_t)r * DD;
    for (int i = threadIdx.x; i < DD; i += 256)
        o[i] = (row[i] - mean) * inv * g[i] + b[i];
}

// ================= pipelined tensor-core tf32 GEMM =================
// C[M,N] = A @ B.  blockIdx.z -> (zb,zh) = (z/ZH, z%ZH).
// EPI: 0 = +bias; 1 = +bias + S residual; 2 = *0.125 + mask(-1e9);
//      3 = silu(S) * (acc + bias)
// GATHER: A rows via tok[]; MPZ: M = Mptr[zb], tok += zb*TT, bias += zb*sBiasZ.
// ZSEL: B/bias selected among 3 pointers by zb.
// TRANSB: B stored [N,K] row-major.
template<int BM, int BN, int WGM, int WGN, int EPI, int GATHER, int TRANSB, int ZSEL, int MPZ>
__global__ void __launch_bounds__(WGM*WGN*32)
tcg(const float* __restrict__ A, int lda, ll sAb, ll sAh,
    const float* __restrict__ B0, const float* __restrict__ B1p, const float* __restrict__ B2p,
    int ldb, ll sBb, ll sBh,
    const float* __restrict__ bias0, const float* __restrict__ bias1, const float* __restrict__ bias2,
    ll sBiasZ,
    const float* __restrict__ S, ll sSz,
    const int* __restrict__ maskp,
    float* __restrict__ C, int ldc, ll sCb, ll sCh,
    int ZH, int M, const int* __restrict__ Mptr, int Kd,
    const int* __restrict__ tok) {
    constexpr int NW = WGM * WGN;
    constexpr int NTH = NW * 32;
    constexpr int BK = 32;
    constexpr int KT = 4;
    constexpr int ASTR = 36;
    constexpr int BSTR = BN + 8;
    constexpr int ASZ = BM * ASTR;
    constexpr int BSZ = TRANSB ? BN * ASTR : BK * BSTR;
    constexpr int STG = ASZ + BSZ;
    constexpr int WM = BM / WGM;
    constexpr int WN = BN / WGN;
    constexpr int MT = WM / 16;
    constexpr int NT = WN / 8;

    int z = blockIdx.z;
    int zb = z / ZH, zh = z - zb * ZH;
    if (MPZ) M = Mptr[zb];
    else if (Mptr) M = *Mptr;
    int bm0 = blockIdx.x * BM;
    if (bm0 >= M) return;
    int bn0 = blockIdx.y * BN;

    const float* Bm = ZSEL ? (zb == 0 ? B0 : (zb == 1 ? B1p : B2p)) : B0;
    const float* bias = ZSEL ? (zb == 0 ? bias0 : (zb == 1 ? bias1 : bias2)) : bias0;
    if (bias && sBiasZ) bias += (ll)zb * sBiasZ;
    A  += (ll)zb * sAb + (ll)zh * sAh;
    Bm += (ll)zb * sBb + (ll)zh * sBh;
    C  += (ll)zb * sCb + (ll)zh * sCh;
    if (S) S += (ll)zb * sSz;
    if (GATHER && MPZ) tok += (ll)zb * TT;

    extern __shared__ float smf[];
    int* toks = (int*)(smf + 2 * STG);
    int tid = threadIdx.x;

    if (GATHER) {
        for (int i = tid; i < BM; i += NTH) {
            int gr = bm0 + i;
            toks[i] = (gr < M) ? tok[gr] : -1;
        }
        __syncthreads();
    }

    int wid = tid >> 5, lane = tid & 31;
    int wm = wid / WGN, wn = wid - wm * WGN;
    int lr = lane >> 2, lc = lane & 3;
    int jmat = lane >> 3, rrow = lane & 7;

    // ldmatrix base offsets (in floats)
    int aoff[MT];
#pragma unroll
    for (int mt = 0; mt < MT; mt++)
        aoff[mt] = (wm * WM + mt * 16 + (jmat & 1) * 8 + rrow) * ASTR + (jmat >> 1) * 4;
    int boff[TRANSB ? (NT / 2 > 0 ? NT / 2 : 1) : 1];
    if (TRANSB) {
#pragma unroll
        for (int p = 0; p < NT / 2; p++)
            boff[p] = (wn * WN + p * 16 + (jmat >> 1) * 8 + rrow) * ASTR + (jmat & 1) * 4;
    }

    auto fill = [&](int st, int k0) {
        float* As = smf + st * STG;
        float* Bs = As + ASZ;
#pragma unroll
        for (int it = 0; it < BM * 8 / NTH; it++) {
            int i = it * NTH + tid;
            int row = i >> 3, c4 = i & 7;
            float* dst = As + row * ASTR + c4 * 4;
            const float* src;
            int sz = 16;
            if (GATHER) {
                int tk = toks[row];
                src = A + (ll)(tk < 0 ? 0 : tk) * lda + k0 + c4 * 4;
                if (tk < 0) sz = 0;
            } else {
                src = A + (ll)(bm0 + row) * lda + k0 + c4 * 4;
            }
            cpa16(dst, src, sz);
        }
        if (TRANSB) {
#pragma unroll
            for (int it = 0; it < BN * 8 / NTH; it++) {
                int i = it * NTH + tid;
                int row = i >> 3, c4 = i & 7;
                cpa16(Bs + row * ASTR + c4 * 4,
                      Bm + (ll)(bn0 + row) * ldb + k0 + c4 * 4, 16);
            }
        } else {
            constexpr int RF4 = BN / 4;
#pragma unroll
            for (int it = 0; it < BK * RF4 / NTH; it++) {
                int i = it * NTH + tid;
                int kk = i / RF4, c4 = i - kk * RF4;
                cpa16(Bs + kk * BSTR + c4 * 4,
                      Bm + (ll)(k0 + kk) * ldb + bn0 + c4 * 4, 16);
            }
        }
    };

    float4 acc[MT][NT];
#pragma unroll
    for (int i = 0; i < MT; i++)
#pragma unroll
        for (int j = 0; j < NT; j++) acc[i][j] = make_float4(0.f, 0.f, 0.f, 0.f);

    int nIt = Kd / BK;
    fill(0, 0);
    asm volatile("cp.async.commit_group;\n");

    for (int itK = 0; itK < nIt; itK++) {
        if (itK + 1 < nIt) {
            fill((itK + 1) & 1, (itK + 1) * BK);
            asm volatile("cp.async.commit_group;\n");
            asm volatile("cp.async.wait_group 1;\n");
        } else {
            asm volatile("cp.async.wait_group 0;\n");
        }
        __syncthreads();
        const float* As = smf + (itK & 1) * STG;
        const float* Bs = As + ASZ;
#pragma unroll
        for (int kt = 0; kt < KT; kt++) {
            uint32_t af[MT][4];
            uint32_t bf[NT][2];
#pragma unroll
            for (int mt = 0; mt < MT; mt++)
                ldsm4(af[mt], As + aoff[mt] + kt * 8);
            if (TRANSB) {
#pragma unroll
                for (int p = 0; p < NT / 2; p++) {
                    uint32_t t4[4];
                    ldsm4(t4, Bs + boff[p] + kt * 8);
                    bf[2 * p][0] = t4[0]; bf[2 * p][1] = t4[1];
                    bf[2 * p + 1][0] = t4[2]; bf[2 * p + 1][1] = t4[3];
                }
            } else {
#pragma unroll
                for (int nt = 0; nt < NT; nt++) {
                    const float* bp = Bs + (kt * 8 + lc) * BSTR + wn * WN + nt * 8 + lr;
                    bf[nt][0] = __float_as_uint(bp[0]);
                    bf[nt][1] = __float_as_uint(bp[4 * BSTR]);
                }
            }
#pragma unroll
            for (int mt = 0; mt < MT; mt++)
#pragma unroll
                for (int nt = 0; nt < NT; nt++)
                    mma_tf32(acc[mt][nt], af[mt], bf[nt]);
        }
        __syncthreads();
    }

    // ---- epilogue ----
#pragma unroll
    for (int mt = 0; mt < MT; mt++) {
        int r0 = bm0 + wm * WM + mt * 16 + lr;
        int r1 = r0 + 8;
#pragma unroll
        for (int nt = 0; nt < NT; nt++) {
            int col = bn0 + wn * WN + nt * 8 + lc * 2;
            float v0 = acc[mt][nt].x, v1 = acc[mt][nt].y;
            float v2 = acc[mt][nt].z, v3 = acc[mt][nt].w;
            if (EPI == 2) {
                v0 *= 0.125f; v1 *= 0.125f; v2 *= 0.125f; v3 *= 0.125f;
                const int* mrow0 = maskp + (ll)zb * SS * SS + (ll)r0 * SS + col;
                const int* mrow1 = maskp + (ll)zb * SS * SS + (ll)r1 * SS + col;
                if (mrow0[0] == 0) v0 = -1e9f;
                if (mrow0[1] == 0) v1 = -1e9f;
                if (mrow1[0] == 0) v2 = -1e9f;
                if (mrow1[1] == 0) v3 = -1e9f;
            } else {
                if (bias) {
                    float b0 = bias[col], b1 = bias[col + 1];
                    v0 += b0; v1 += b1; v2 += b0; v3 += b1;
                }
                if (EPI == 1) {
                    if (r0 < M) {
                        v0 += S[(ll)r0 * ldc + col];
                        v1 += S[(ll)r0 * ldc + col + 1];
                    }
                    if (r1 < M) {
                        v2 += S[(ll)r1 * ldc + col];
                        v3 += S[(ll)r1 * ldc + col + 1];
                    }
                }
                if (EPI == 3) {
                    if (r0 < M) {
                        v0 = siluf(S[(ll)r0 * ldc + col]) * v0;
                        v1 = siluf(S[(ll)r0 * ldc + col + 1]) * v1;
                    }
                    if (r1 < M) {
                        v2 = siluf(S[(ll)r1 * ldc + col]) * v2;
                        v3 = siluf(S[(ll)r1 * ldc + col + 1]) * v3;
                    }
                }
            }
            if (r0 < M) {
                C[(ll)r0 * ldc + col] = v0;
                C[(ll)r0 * ldc + col + 1] = v1;
            }
            if (r1 < M) {
                C[(ll)r1 * ldc + col] = v2;
                C[(ll)r1 * ldc + col + 1] = v3;
            }
        }
    }
}

// ---------------- row softmax (in place, float4) ----------------
__global__ void softmax_k(float* __restrict__ a) {
    __shared__ float sh[256];
    size_t row = blockIdx.x;
    float4* p = (float4*)(a + row * SS);
    int tid = threadIdx.x;
    float4 v = p[tid];
    float m = fmaxf(fmaxf(v.x, v.y), fmaxf(v.z, v.w));
    m = blockReduceMax(m, sh);
    v.x = __expf(v.x - m); v.y = __expf(v.y - m);
    v.z = __expf(v.z - m); v.w = __expf(v.w - m);
    float s = v.x + v.y + v.z + v.w;
    s = blockReduceSum(s, sh);
    float inv = 1.f / s;
    v.x *= inv; v.y *= inv; v.z *= inv; v.w *= inv;
    p[tid] = v;
}

// ---------------- gate + routing ----------------
__global__ void zero_counts_k(int* counts) {
    if (threadIdx.x < EE) counts[threadIdx.x] = 0;
}
__global__ void gate_route_k(const float* __restrict__ x2, const float* __restrict__ gw,
                             const float* __restrict__ gb, int* counts, int* etok,
                             int* texp, int* tslot, float* tw) {
    int t = blockIdx.x;
    __shared__ float xs[DD];
    __shared__ float logits[EE];
    const float* row = x2 + (ll)t * DD;
    for (int i = threadIdx.x; i < DD; i += 256) xs[i] = row[i];
    __syncthreads();
    int w = threadIdx.x / 32, lane = threadIdx.x % 32;
    float s = 0.f;
    for (int d = lane; d < DD; d += 32) s += xs[d] * gw[d * EE + w];
    for (int o = 16; o; o >>= 1) s += __shfl_xor_sync(0xffffffff, s, o);
    if (lane == 0) logits[w] = s + gb[w];
    __syncthreads();
    if (threadIdx.x == 0) {
        float p[EE];
        float m = -1e30f;
        for (int e = 0; e < EE; e++) m = fmaxf(m, logits[e]);
        float sum = 0.f;
        for (int e = 0; e < EE; e++) { p[e] = __expf(logits[e] - m); sum += p[e]; }
        for (int e = 0; e < EE; e++) p[e] /= sum;
        int i0 = 0;
        for (int e = 1; e < EE; e++) if (p[e] > p[i0]) i0 = e;
        int i1 = -1;
        for (int e = 0; e < EE; e++) {
            if (e == i0) continue;
            if (i1 < 0 || p[e] > p[i1]) i1 = e;
        }
        float denom = p[i0] + p[i1] + 1e-6f;
        int s0 = atomicAdd(&counts[i0], 1);
        int s1 = atomicAdd(&counts[i1], 1);
        etok[i0 * TT + s0] = t;
        etok[i1 * TT + s1] = t;
        texp[t * 2] = i0; texp[t * 2 + 1] = i1;
        tslot[t * 2] = s0; tslot[t * 2 + 1] = s1;
        tw[t * 2] = p[i0] / denom; tw[t * 2 + 1] = p[i1] / denom;
    }
}

// ---------------- final combine ----------------
__global__ void combine_k(const float* __restrict__ xres, const int* __restrict__ texp,
                          const int* __restrict__ tslot, const float* __restrict__ tw,
                          const float* __restrict__ moe, float* __restrict__ out) {
    int t = blockIdx.x;
    int e0 = texp[t * 2], e1 = texp[t * 2 + 1];
    int s0 = tslot[t * 2], s1 = tslot[t * 2 + 1];
    float w0 = tw[t * 2], w1 = tw[t * 2 + 1];
    const float* m0 = moe + ((size_t)e0 * TT + s0) * DD;
    const float* m1 = moe + ((size_t)e1 * TT + s1) * DD;
    const float* xr = xres + (ll)t * DD;
    float* o = out + (ll)t * DD;
    for (int i = threadIdx.x; i < DD; i += 256)
        o[i] = xr[i] + w0 * m0[i] + w1 * m1[i];
}

// ---------------- host side ----------------
static float* devPtrF(const void* sym) {
    void* p = nullptr;
    cudaGetSymbolAddress(&p, sym);
    return (float*)p;
}
static int* devPtrI(const void* sym) {
    void* p = nullptr;
    cudaGetSymbolAddress(&p, sym);
    return (int*)p;
}
static int smBytes(int BM, int BN, int transb, int gather) {
    int ASZ = BM * 36;
    int BSZ = transb ? BN * 36 : 32 * (BN + 8);
    return 2 * (ASZ + BSZ) * 4 + (gather ? BM * 4 : 0);
}

extern "C" void kernel_launch(void* const* d_in, const int* in_sizes, int n_in,
                              void* d_out, int out_size) {
    const float* x    = (const float*)d_in[0];
    const int*   mask = (const int*)  d_in[1];
    const float* wq1 = (const float*)d_in[2];  const float* bq1 = (const float*)d_in[3];
    const float* wq2 = (const float*)d_in[4];  const float* bq2 = (const float*)d_in[5];
    const float* wk1 = (const float*)d_in[6];  const float* bk1 = (const float*)d_in[7];
    const float* wk2 = (const float*)d_in[8];  const float* bk2 = (const float*)d_in[9];
    const float* wv1 = (const float*)d_in[10]; const float* bv1 = (const float*)d_in[11];
    const float* wv2 = (const float*)d_in[12]; const float* bv2 = (const float*)d_in[13];
    const float* wo  = (const float*)d_in[14]; const float* bo  = (const float*)d_in[15];
    const float* ln1g = (const float*)d_in[16]; const float* ln1b = (const float*)d_in[17];
    const float* ln2g = (const float*)d_in[18]; const float* ln2b = (const float*)d_in[19];
    const float* gw  = (const float*)d_in[20]; const float* gb  = (const float*)d_in[21];
    const float* ew1 = (const float*)d_in[22]; const float* eb1 = (const float*)d_in[23];
    const float* ew2 = (const float*)d_in[24]; const float* eb2 = (const float*)d_in[25];
    const float* ew3 = (const float*)d_in[26]; const float* eb3 = (const float*)d_in[27];
    float* out = (float*)d_out;

    float* x2a  = devPtrF(g_x2a);
    float* tmp1 = devPtrF(g_tmp1);
    float* qkv  = devPtrF(g_qkv);
    float* attn = devPtrF(g_attn);
    float* ctx  = devPtrF(g_ctx);
    float* xres = devPtrF(g_xres);
    float* x2b  = devPtrF(g_x2b);
    float* emid = devPtrF(g_emid);
    float* moe  = devPtrF(g_moe);
    int* counts = devPtrI(g_counts);
    int* etok   = devPtrI(g_etok);
    int* texp   = devPtrI(g_texp);
    int* tslot  = devPtrI(g_tslot);
    float* tw   = devPtrF(g_tw);

    float* qb = qkv;
    float* kb = qkv + (ll)TT * DD;
    float* vb = qkv + 2ll * TT * DD;

    // kernel configs
    // P: 128x256, 16 warps (proj/oproj/moe2); G: gather variant; SC: scores; CX: ctx
    auto kP0 = tcg<128,256,2,8,0,0,0,1,0>;   // proj1 (ZSEL)
    auto kP3 = tcg<128,256,2,8,3,0,0,1,0>;   // proj2 fused silu (ZSEL)
    auto kO1 = tcg<128,256,2,8,1,0,0,0,0>;   // oproj + residual
    auto kSC = tcg<128,128,4,4,2,0,1,0,0>;   // scores
    auto kCX = tcg<128,64,8,2,0,0,0,0,0>;    // ctx
    auto kM1 = tcg<128,256,2,8,0,1,0,0,1>;   // moe w1 (gather, per-z)
    auto kM3 = tcg<128,256,2,8,3,1,0,0,1>;   // moe w3 fused silu (gather, per-z)
    auto kM2 = tcg<128,256,2,8,0,0,0,0,1>;   // moe w2 (per-z)

    int smP  = smBytes(128, 256, 0, 0);
    int smG  = smBytes(128, 256, 0, 1);
    int smSC = smBytes(128, 128, 1, 0);
    int smCX = smBytes(128, 64, 0, 0);
    cudaFuncSetAttribute(kP0, cudaFuncAttributeMaxDynamicSharedMemorySize, smP);
    cudaFuncSetAttribute(kP3, cudaFuncAttributeMaxDynamicSharedMemorySize, smP);
    cudaFuncSetAttribute(kO1, cudaFuncAttributeMaxDynamicSharedMemorySize, smP);
    cudaFuncSetAttribute(kSC, cudaFuncAttributeMaxDynamicSharedMemorySize, smSC);
    cudaFuncSetAttribute(kCX, cudaFuncAttributeMaxDynamicSharedMemorySize, smCX);
    cudaFuncSetAttribute(kM1, cudaFuncAttributeMaxDynamicSharedMemorySize, smG);
    cudaFuncSetAttribute(kM3, cudaFuncAttributeMaxDynamicSharedMemorySize, smG);
    cudaFuncSetAttribute(kM2, cudaFuncAttributeMaxDynamicSharedMemorySize, smP);

    // 1) LN1
    ln_k<<<TT, 256>>>(x, ln1g, ln1b, x2a);

    // 2) merged SwiGLU projections: z=3 selects (q,k,v)
    dim3 gP(TT / 128, DD / 256, 3);
    kP0<<<gP, 512, smP>>>(x2a, DD, 0, 0,
        wq1, wk1, wv1, DD, 0, 0,
        bq1, bk1, bv1, 0,
        nullptr, 0, nullptr,
        tmp1, DD, (ll)TT * DD, 0,
        1, TT, nullptr, DD, nullptr);
    kP3<<<gP, 512, smP>>>(x2a, DD, 0, 0,
        wq2, wk2, wv2, DD, 0, 0,
        bq2, bk2, bv2, 0,
        tmp1, (ll)TT * DD, nullptr,
        qkv, DD, (ll)TT * DD, 0,
        1, TT, nullptr, DD, nullptr);

    // 3) attention scores (batched over b,h) + softmax
    kSC<<<dim3(SS/128, SS/128, BB*HH), 512, smSC>>>(
        qb, DD, (ll)SS*DD, 64,
        kb, nullptr, nullptr, DD, (ll)SS*DD, 64,
        nullptr, nullptr, nullptr, 0,
        nullptr, 0, mask,
        attn, SS, (ll)HH*SS*SS, (ll)SS*SS,
        HH, SS, nullptr, DK, nullptr);
    softmax_k<<<BB * HH * SS, 256>>>(attn);

    // 4) ctx = attn @ v
    kCX<<<dim3(SS/128, 1, BB*HH), 512, smCX>>>(
        attn, SS, (ll)HH*SS*SS, (ll)SS*SS,
        vb, nullptr, nullptr, DD, (ll)SS*DD, 64,
        nullptr, nullptr, nullptr, 0,
        nullptr, 0, nullptr,
        ctx, DD, (ll)SS*DD, 64,
        HH, SS, nullptr, SS, nullptr);

    // 5) out proj + residual
    kO1<<<dim3(TT/128, DD/256, 1), 512, smP>>>(ctx, DD, 0, 0,
        wo, nullptr, nullptr, DD, 0, 0,
        bo, nullptr, nullptr, 0,
        x, 0, nullptr,
        xres, DD, 0, 0,
        1, TT, nullptr, DD, nullptr);

    // 6) LN2
    ln_k<<<TT, 256>>>(xres, ln2g, ln2b, x2b);

    // 7) gate + routing
    zero_counts_k<<<1, 32>>>(counts);
    gate_route_k<<<TT, 256>>>(x2b, gw, gb, counts, etok, texp, tslot, tw);

    // 8) MoE: 3 launches, z = expert
    kM1<<<dim3(TT/128, FF/256, EE), 512, smG>>>(x2b, DD, 0, 0,
        ew1, nullptr, nullptr, FF, (ll)DD * FF, 0,
        eb1, nullptr, nullptr, FF,
        nullptr, 0, nullptr,
        emid, FF, (ll)TT * FF, 0,
        1, 0, counts, DD, etok);
    kM3<<<dim3(TT/128, FF/256, EE), 512, smG>>>(x2b, DD, 0, 0,
        ew3, nullptr, nullptr, FF, (ll)DD * FF, 0,
        eb3, nullptr, nullptr, FF,
        emid, (ll)TT * FF, nullptr,
        emid, FF, (ll)TT * FF, 0,
        1, 0, counts, DD, etok);
    kM2<<<dim3(TT/128, DD/256, EE), 512, smP>>>(emid, FF, (ll)TT * FF, 0,
        ew2, nullptr, nullptr, DD, (ll)FF * DD, 0,
        eb2, nullptr, nullptr, DD,
        nullptr, 0, nullptr,
        moe, DD, (ll)TT * DD, 0,
        1, 0, counts, FF, etok);

    // 9) combine
    combine_k<<<TT, 256>>>(xres, texp, tslot, tw, moe, out);
}

// round 6
// speedup vs baseline: 12.3302x; 1.0611x over previous
#include <cuda_runtime.h>
#include <cuda_bf16.h>
#include <math.h>
#include <stdint.h>

// Problem dims
#define BB 4
#define SS 1024
#define DD 1024
#define FF 2048
#define HH 16
#define EE 8
#define DK 64
#define TT (BB*SS)          // 4096 tokens
typedef long long ll;

// ---------------- static device scratch ----------------
__device__ float g_x2a[TT*DD];
__device__ float g_tmp1[3*TT*DD];               // 3 slices for q1/k1/v1
__device__ float g_qkv[3*TT*DD];                // q,k,v slices
__device__ float g_ctx[TT*DD];
__device__ float g_xres[TT*DD];
__device__ float g_x2b[TT*DD];
__device__ float g_emid[(size_t)EE*TT*FF];      // MoE mid
__device__ float g_moe[(size_t)EE*TT*DD];
__device__ int   g_counts[EE];
__device__ int   g_etok[EE*TT];
__device__ int   g_texp[TT*2];
__device__ int   g_tslot[TT*2];
__device__ float g_tw[TT*2];

// ---------------- helpers ----------------
__device__ __forceinline__ float blockReduceSum(float v, float* sh) {
    int tid = threadIdx.x;
    sh[tid] = v; __syncthreads();
    for (int s = 128; s > 0; s >>= 1) {
        if (tid < s) sh[tid] += sh[tid + s];
        __syncthreads();
    }
    float r = sh[0]; __syncthreads();
    return r;
}
__device__ __forceinline__ void mma_tf32(float4& d, const uint32_t* a, const uint32_t* b) {
    asm volatile(
        "mma.sync.aligned.m16n8k8.row.col.f32.tf32.tf32.f32 "
        "{%0,%1,%2,%3}, {%4,%5,%6,%7}, {%8,%9}, {%0,%1,%2,%3};"
        : "+f"(d.x), "+f"(d.y), "+f"(d.z), "+f"(d.w)
        : "r"(a[0]), "r"(a[1]), "r"(a[2]), "r"(a[3]), "r"(b[0]), "r"(b[1]));
}
__device__ __forceinline__ void cpa16(float* dst, const float* src, int sz) {
    uint32_t d = (uint32_t)__cvta_generic_to_shared(dst);
    asm volatile("cp.async.cg.shared.global [%0], [%1], 16, %2;\n"
                 :: "r"(d), "l"(src), "r"(sz));
}
__device__ __forceinline__ void ldsm4(uint32_t* d, const float* p) {
    uint32_t a = (uint32_t)__cvta_generic_to_shared(p);
    asm volatile("ldmatrix.sync.aligned.m8n8.x4.shared.b16 {%0,%1,%2,%3}, [%4];"
                 : "=r"(d[0]), "=r"(d[1]), "=r"(d[2]), "=r"(d[3]) : "r"(a));
}
__device__ __forceinline__ float siluf(float x) {
    return x / (1.f + __expf(-x));
}

// ---------------- LayerNorm ----------------
__global__ void ln_k(const float* __restrict__ x, const float* __restrict__ g,
                     const float* __restrict__ b, float* __restrict__ out) {
    __shared__ float sh[256];
    int r = blockIdx.x;
    const float* row = x + (size_t)r * DD;
    float s = 0.f;
    for (int i = threadIdx.x; i < DD; i += 256) s += row[i];
    float mean = blockReduceSum(s, sh) * (1.0f / DD);
    float v = 0.f;
    for (int i = threadIdx.x; i < DD; i += 256) {
        float d = row[i] - mean; v += d * d;
    }
    float var = blockReduceSum(v, sh) * (1.0f / DD);
    float inv = rsqrtf(var + 1e-5f);
    float* o = out + (size_t)r * DD;
    for (int i = threadIdx.x; i < DD; i += 256)
        o[i] = (row[i] - mean) * inv * g[i] + b[i];
}

// ================= pipelined tensor-core tf32 GEMM =================
template<int BM, int BN, int WGM, int WGN, int EPI, int GATHER, int TRANSB, int ZSEL, int MPZ>
__global__ void __launch_bounds__(WGM*WGN*32)
tcg(const float* __restrict__ A, int lda, ll sAb, ll sAh,
    const float* __restrict__ B0, const float* __restrict__ B1p, const float* __restrict__ B2p,
    int ldb, ll sBb, ll sBh,
    const float* __restrict__ bias0, const float* __restrict__ bias1, const float* __restrict__ bias2,
    ll sBiasZ,
    const float* __restrict__ S, ll sSz,
    float* __restrict__ C, int ldc, ll sCb, ll sCh,
    int ZH, int M, const int* __restrict__ Mptr, int Kd,
    const int* __restrict__ tok) {
    constexpr int NW = WGM * WGN;
    constexpr int NTH = NW * 32;
    constexpr int BK = 32;
    constexpr int KT = 4;
    constexpr int ASTR = 36;
    constexpr int BSTR = BN + 8;
    constexpr int ASZ = BM * ASTR;
    constexpr int BSZ = TRANSB ? BN * ASTR : BK * BSTR;
    constexpr int STG = ASZ + BSZ;
    constexpr int WM = BM / WGM;
    constexpr int WN = BN / WGN;
    constexpr int MT = WM / 16;
    constexpr int NT = WN / 8;

    int z = blockIdx.z;
    int zb = z / ZH, zh = z - zb * ZH;
    if (MPZ) M = Mptr[zb];
    else if (Mptr) M = *Mptr;
    int bm0 = blockIdx.x * BM;
    if (bm0 >= M) return;
    int bn0 = blockIdx.y * BN;

    const float* Bm = ZSEL ? (zb == 0 ? B0 : (zb == 1 ? B1p : B2p)) : B0;
    const float* bias = ZSEL ? (zb == 0 ? bias0 : (zb == 1 ? bias1 : bias2)) : bias0;
    if (bias && sBiasZ) bias += (ll)zb * sBiasZ;
    A  += (ll)zb * sAb + (ll)zh * sAh;
    Bm += (ll)zb * sBb + (ll)zh * sBh;
    C  += (ll)zb * sCb + (ll)zh * sCh;
    if (S) S += (ll)zb * sSz;
    if (GATHER && MPZ) tok += (ll)zb * TT;

    extern __shared__ float smf[];
    int* toks = (int*)(smf + 2 * STG);
    int tid = threadIdx.x;

    if (GATHER) {
        for (int i = tid; i < BM; i += NTH) {
            int gr = bm0 + i;
            toks[i] = (gr < M) ? tok[gr] : -1;
        }
        __syncthreads();
    }

    int wid = tid >> 5, lane = tid & 31;
    int wm = wid / WGN, wn = wid - wm * WGN;
    int lr = lane >> 2, lc = lane & 3;
    int jmat = lane >> 3, rrow = lane & 7;

    int aoff[MT];
#pragma unroll
    for (int mt = 0; mt < MT; mt++)
        aoff[mt] = (wm * WM + mt * 16 + (jmat & 1) * 8 + rrow) * ASTR + (jmat >> 1) * 4;
    int boff[TRANSB ? (NT / 2 > 0 ? NT / 2 : 1) : 1];
    if (TRANSB) {
#pragma unroll
        for (int p = 0; p < NT / 2; p++)
            boff[p] = (wn * WN + p * 16 + (jmat >> 1) * 8 + rrow) * ASTR + (jmat & 1) * 4;
    }

    auto fill = [&](int st, int k0) {
        float* As = smf + st * STG;
        float* Bs = As + ASZ;
#pragma unroll
        for (int it = 0; it < BM * 8 / NTH; it++) {
            int i = it * NTH + tid;
            int row = i >> 3, c4 = i & 7;
            float* dst = As + row * ASTR + c4 * 4;
            const float* src;
            int sz = 16;
            if (GATHER) {
                int tk = toks[row];
                src = A + (ll)(tk < 0 ? 0 : tk) * lda + k0 + c4 * 4;
                if (tk < 0) sz = 0;
            } else {
                src = A + (ll)(bm0 + row) * lda + k0 + c4 * 4;
            }
            cpa16(dst, src, sz);
        }
        if (TRANSB) {
#pragma unroll
            for (int it = 0; it < BN * 8 / NTH; it++) {
                int i = it * NTH + tid;
                int row = i >> 3, c4 = i & 7;
                cpa16(Bs + row * ASTR + c4 * 4,
                      Bm + (ll)(bn0 + row) * ldb + k0 + c4 * 4, 16);
            }
        } else {
            constexpr int RF4 = BN / 4;
#pragma unroll
            for (int it = 0; it < BK * RF4 / NTH; it++) {
                int i = it * NTH + tid;
                int kk = i / RF4, c4 = i - kk * RF4;
                cpa16(Bs + kk * BSTR + c4 * 4,
                      Bm + (ll)(k0 + kk) * ldb + bn0 + c4 * 4, 16);
            }
        }
    };

    float4 acc[MT][NT];
#pragma unroll
    for (int i = 0; i < MT; i++)
#pragma unroll
        for (int j = 0; j < NT; j++) acc[i][j] = make_float4(0.f, 0.f, 0.f, 0.f);

    int nIt = Kd / BK;
    fill(0, 0);
    asm volatile("cp.async.commit_group;\n");

    for (int itK = 0; itK < nIt; itK++) {
        if (itK + 1 < nIt) {
            fill((itK + 1) & 1, (itK + 1) * BK);
            asm volatile("cp.async.commit_group;\n");
            asm volatile("cp.async.wait_group 1;\n");
        } else {
            asm volatile("cp.async.wait_group 0;\n");
        }
        __syncthreads();
        const float* As = smf + (itK & 1) * STG;
        const float* Bs = As + ASZ;
#pragma unroll
        for (int kt = 0; kt < KT; kt++) {
            uint32_t af[MT][4];
            uint32_t bf[NT][2];
#pragma unroll
            for (int mt = 0; mt < MT; mt++)
                ldsm4(af[mt], As + aoff[mt] + kt * 8);
            if (TRANSB) {
#pragma unroll
                for (int p = 0; p < NT / 2; p++) {
                    uint32_t t4[4];
                    ldsm4(t4, Bs + boff[p] + kt * 8);
                    bf[2 * p][0] = t4[0]; bf[2 * p][1] = t4[1];
                    bf[2 * p + 1][0] = t4[2]; bf[2 * p + 1][1] = t4[3];
                }
            } else {
#pragma unroll
                for (int nt = 0; nt < NT; nt++) {
                    const float* bp = Bs + (kt * 8 + lc) * BSTR + wn * WN + nt * 8 + lr;
                    bf[nt][0] = __float_as_uint(bp[0]);
                    bf[nt][1] = __float_as_uint(bp[4 * BSTR]);
                }
            }
#pragma unroll
            for (int mt = 0; mt < MT; mt++)
#pragma unroll
                for (int nt = 0; nt < NT; nt++)
                    mma_tf32(acc[mt][nt], af[mt], bf[nt]);
        }
        __syncthreads();
    }

    // ---- epilogue ----
#pragma unroll
    for (int mt = 0; mt < MT; mt++) {
        int r0 = bm0 + wm * WM + mt * 16 + lr;
        int r1 = r0 + 8;
#pragma unroll
        for (int nt = 0; nt < NT; nt++) {
            int col = bn0 + wn * WN + nt * 8 + lc * 2;
            float v0 = acc[mt][nt].x, v1 = acc[mt][nt].y;
            float v2 = acc[mt][nt].z, v3 = acc[mt][nt].w;
            if (bias) {
                float b0 = bias[col], b1 = bias[col + 1];
                v0 += b0; v1 += b1; v2 += b0; v3 += b1;
            }
            if (EPI == 1) {
                if (r0 < M) {
                    v0 += S[(ll)r0 * ldc + col];
                    v1 += S[(ll)r0 * ldc + col + 1];
                }
                if (r1 < M) {
                    v2 += S[(ll)r1 * ldc + col];
                    v3 += S[(ll)r1 * ldc + col + 1];
                }
            }
            if (EPI == 3) {
                if (r0 < M) {
                    v0 = siluf(S[(ll)r0 * ldc + col]) * v0;
                    v1 = siluf(S[(ll)r0 * ldc + col + 1]) * v1;
                }
                if (r1 < M) {
                    v2 = siluf(S[(ll)r1 * ldc + col]) * v2;
                    v3 = siluf(S[(ll)r1 * ldc + col + 1]) * v3;
                }
            }
            if (r0 < M) {
                C[(ll)r0 * ldc + col] = v0;
                C[(ll)r0 * ldc + col + 1] = v1;
            }
            if (r1 < M) {
                C[(ll)r1 * ldc + col] = v2;
                C[(ll)r1 * ldc + col + 1] = v3;
            }
        }
    }
}

// ================= flash attention (tf32) =================
// grid (SS/128, BB*HH), 512 threads (16 warps, 8x2 warp grid).
// Q tile 128x64 register-resident; K/V 64-row tiles double-buffered (cp.async);
// online softmax; P via smem; writes ctx[token][h*64+:64].
#define QSTR 68
__global__ void __launch_bounds__(512)
flash_k(const float* __restrict__ qg, const float* __restrict__ kg,
        const float* __restrict__ vg, const int* __restrict__ maskp,
        float* __restrict__ ctx) {
    extern __shared__ float sm[];
    float* Qs = sm;                         // 128*68
    float* Ks = sm + 128 * QSTR;            // 2 * 64*68
    float* Vs = Ks + 2 * 64 * QSTR;         // 2 * 64*68
    float* Ps = Vs + 2 * 64 * QSTR;         // 128*68
    float* redM = Ps + 128 * QSTR;          // 256
    float* redL = redM + 256;               // 256

    int tid = threadIdx.x;
    int z = blockIdx.y;
    int b = z / HH, h = z % HH;
    int q0 = blockIdx.x * 128;
    int lane = tid & 31, wid = tid >> 5;
    int wm = wid >> 1, wn = wid & 1;
    int lr = lane >> 2, lc = lane & 3;
    int jmat = lane >> 3, rrow = lane & 7;

    const float* Qg = qg + ((ll)(b * SS + q0)) * DD + h * DK;
#pragma unroll
    for (int it = 0; it < 4; it++) {
        int i = it * 512 + tid;
        int row = i >> 4, c4 = i & 15;
        cpa16(Qs + row * QSTR + c4 * 4, Qg + (ll)row * DD + c4 * 4, 16);
    }
    asm volatile("cp.async.commit_group;\n");

    auto pf = [&](int i) {
        int st = i & 1;
        const float* Kg = kg + ((ll)(b * SS + i * 64)) * DD + h * DK;
        const float* Vg = vg + ((ll)(b * SS + i * 64)) * DD + h * DK;
#pragma unroll
        for (int it = 0; it < 2; it++) {
            int j = it * 512 + tid;
            int row = j >> 4, c4 = j & 15;
            cpa16(Ks + st * 64 * QSTR + row * QSTR + c4 * 4, Kg + (ll)row * DD + c4 * 4, 16);
            cpa16(Vs + st * 64 * QSTR + row * QSTR + c4 * 4, Vg + (ll)row * DD + c4 * 4, 16);
        }
    };
    pf(0);
    asm volatile("cp.async.commit_group;\n");

    // Q fragments (register resident)
    asm volatile("cp.async.wait_group 1;\n");
    __syncthreads();
    uint32_t qf[8][4];
    int aoffQ = (wm * 16 + (jmat & 1) * 8 + rrow) * QSTR + (jmat >> 1) * 4;
#pragma unroll
    for (int kt = 0; kt < 8; kt++) ldsm4(qf[kt], Qs + aoffQ + kt * 8);

    float4 oacc[4];
#pragma unroll
    for (int nt = 0; nt < 4; nt++) oacc[nt] = make_float4(0.f, 0.f, 0.f, 0.f);
    float m0 = -1e30f, m1 = -1e30f, l0 = 0.f, l1 = 0.f;
    int r0 = wm * 16 + lr, r1 = r0 + 8;
    int gq0 = q0 + r0, gq1 = q0 + r1;
    const int* mbase = maskp + (ll)b * SS * SS;

    constexpr int NIT = SS / 64;
    for (int i = 0; i < NIT; i++) {
        if (i + 1 < NIT) {
            pf(i + 1);
            asm volatile("cp.async.commit_group;\n");
            asm volatile("cp.async.wait_group 1;\n");
        } else {
            asm volatile("cp.async.wait_group 0;\n");
        }
        __syncthreads();
        const float* Kst = Ks + (i & 1) * 64 * QSTR;
        const float* Vst = Vs + (i & 1) * 64 * QSTR;

        // S = Q @ K^T  (warp: 16 rows x 32 keys)
        float4 s[4];
#pragma unroll
        for (int nt = 0; nt < 4; nt++) s[nt] = make_float4(0.f, 0.f, 0.f, 0.f);
#pragma unroll
        for (int kt = 0; kt < 8; kt++) {
            uint32_t bf[4][2];
#pragma unroll
            for (int p = 0; p < 2; p++) {
                uint32_t t4[4];
                ldsm4(t4, Kst + (wn * 32 + p * 16 + (jmat >> 1) * 8 + rrow) * QSTR
                          + (jmat & 1) * 4 + kt * 8);
                bf[2 * p][0] = t4[0]; bf[2 * p][1] = t4[1];
                bf[2 * p + 1][0] = t4[2]; bf[2 * p + 1][1] = t4[3];
            }
#pragma unroll
            for (int nt = 0; nt < 4; nt++) mma_tf32(s[nt], qf[kt], bf[nt]);
        }
        // scale + mask
#pragma unroll
        for (int nt = 0; nt < 4; nt++) {
            int gk = i * 64 + wn * 32 + nt * 8 + lc * 2;
            const int* mr0 = mbase + (ll)gq0 * SS + gk;
            const int* mr1 = mbase + (ll)gq1 * SS + gk;
            s[nt].x = mr0[0] ? s[nt].x * 0.125f : -1e9f;
            s[nt].y = mr0[1] ? s[nt].y * 0.125f : -1e9f;
            s[nt].z = mr1[0] ? s[nt].z * 0.125f : -1e9f;
            s[nt].w = mr1[1] ? s[nt].w * 0.125f : -1e9f;
        }
        // warp-partial row max
        float mx0 = -1e30f, mx1 = -1e30f;
#pragma unroll
        for (int nt = 0; nt < 4; nt++) {
            mx0 = fmaxf(mx0, fmaxf(s[nt].x, s[nt].y));
            mx1 = fmaxf(mx1, fmaxf(s[nt].z, s[nt].w));
        }
#pragma unroll
        for (int o = 1; o <= 2; o <<= 1) {
            mx0 = fmaxf(mx0, __shfl_xor_sync(0xffffffff, mx0, o));
            mx1 = fmaxf(mx1, __shfl_xor_sync(0xffffffff, mx1, o));
        }
        if (lc == 0) { redM[r0 * 2 + wn] = mx0; redM[r1 * 2 + wn] = mx1; }
        __syncthreads();
        float nm0 = fmaxf(m0, fmaxf(redM[r0 * 2], redM[r0 * 2 + 1]));
        float nm1 = fmaxf(m1, fmaxf(redM[r1 * 2], redM[r1 * 2 + 1]));
        float sc0 = __expf(m0 - nm0), sc1 = __expf(m1 - nm1);
        m0 = nm0; m1 = nm1;
        // exp + store P + partial sums
        float su0 = 0.f, su1 = 0.f;
#pragma unroll
        for (int nt = 0; nt < 4; nt++) {
            int col = wn * 32 + nt * 8 + lc * 2;
            float e0 = __expf(s[nt].x - m0), e1 = __expf(s[nt].y - m0);
            float e2 = __expf(s[nt].z - m1), e3 = __expf(s[nt].w - m1);
            su0 += e0 + e1; su1 += e2 + e3;
            Ps[r0 * QSTR + col] = e0; Ps[r0 * QSTR + col + 1] = e1;
            Ps[r1 * QSTR + col] = e2; Ps[r1 * QSTR + col + 1] = e3;
        }
#pragma unroll
        for (int o = 1; o <= 2; o <<= 1) {
            su0 += __shfl_xor_sync(0xffffffff, su0, o);
            su1 += __shfl_xor_sync(0xffffffff, su1, o);
        }
        if (lc == 0) { redL[r0 * 2 + wn] = su0; redL[r1 * 2 + wn] = su1; }
        __syncthreads();
        l0 = l0 * sc0 + redL[r0 * 2] + redL[r0 * 2 + 1];
        l1 = l1 * sc1 + redL[r1 * 2] + redL[r1 * 2 + 1];
#pragma unroll
        for (int nt = 0; nt < 4; nt++) {
            oacc[nt].x *= sc0; oacc[nt].y *= sc0;
            oacc[nt].z *= sc1; oacc[nt].w *= sc1;
        }
        // O += P @ V   (warp: 16 rows x 32 dk, k over 64 keys)
        int aoffP = (wm * 16 + (jmat & 1) * 8 + rrow) * QSTR + (jmat >> 1) * 4;
#pragma unroll
        for (int kt = 0; kt < 8; kt++) {
            uint32_t af[4];
            ldsm4(af, Ps + aoffP + kt * 8);
#pragma unroll
            for (int nt = 0; nt < 4; nt++) {
                const float* bp = Vst + (kt * 8 + lc) * QSTR + wn * 32 + nt * 8 + lr;
                uint32_t bfr[2] = { __float_as_uint(bp[0]), __float_as_uint(bp[4 * QSTR]) };
                mma_tf32(oacc[nt], af, bfr);
            }
        }
        __syncthreads();
    }

    float inv0 = 1.f / l0, inv1 = 1.f / l1;
    float* cg = ctx + ((ll)(b * SS + q0)) * DD + h * DK;
#pragma unroll
    for (int nt = 0; nt < 4; nt++) {
        int col = wn * 32 + nt * 8 + lc * 2;
        cg[(ll)r0 * DD + col]     = oacc[nt].x * inv0;
        cg[(ll)r0 * DD + col + 1] = oacc[nt].y * inv0;
        cg[(ll)r1 * DD + col]     = oacc[nt].z * inv1;
        cg[(ll)r1 * DD + col + 1] = oacc[nt].w * inv1;
    }
}

// ---------------- gate + routing ----------------
__global__ void zero_counts_k(int* counts) {
    if (threadIdx.x < EE) counts[threadIdx.x] = 0;
}
__global__ void gate_route_k(const float* __restrict__ x2, const float* __restrict__ gw,
                             const float* __restrict__ gb, int* counts, int* etok,
                             int* texp, int* tslot, float* tw) {
    int t = blockIdx.x;
    __shared__ float xs[DD];
    __shared__ float logits[EE];
    const float* row = x2 + (ll)t * DD;
    for (int i = threadIdx.x; i < DD; i += 256) xs[i] = row[i];
    __syncthreads();
    int w = threadIdx.x / 32, lane = threadIdx.x % 32;
    float s = 0.f;
    for (int d = lane; d < DD; d += 32) s += xs[d] * gw[d * EE + w];
    for (int o = 16; o; o >>= 1) s += __shfl_xor_sync(0xffffffff, s, o);
    if (lane == 0) logits[w] = s + gb[w];
    __syncthreads();
    if (threadIdx.x == 0) {
        float p[EE];
        float m = -1e30f;
        for (int e = 0; e < EE; e++) m = fmaxf(m, logits[e]);
        float sum = 0.f;
        for (int e = 0; e < EE; e++) { p[e] = __expf(logits[e] - m); sum += p[e]; }
        for (int e = 0; e < EE; e++) p[e] /= sum;
        int i0 = 0;
        for (int e = 1; e < EE; e++) if (p[e] > p[i0]) i0 = e;
        int i1 = -1;
        for (int e = 0; e < EE; e++) {
            if (e == i0) continue;
            if (i1 < 0 || p[e] > p[i1]) i1 = e;
        }
        float denom = p[i0] + p[i1] + 1e-6f;
        int s0 = atomicAdd(&counts[i0], 1);
        int s1 = atomicAdd(&counts[i1], 1);
        etok[i0 * TT + s0] = t;
        etok[i1 * TT + s1] = t;
        texp[t * 2] = i0; texp[t * 2 + 1] = i1;
        tslot[t * 2] = s0; tslot[t * 2 + 1] = s1;
        tw[t * 2] = p[i0] / denom; tw[t * 2 + 1] = p[i1] / denom;
    }
}

// ---------------- final combine ----------------
__global__ void combine_k(const float* __restrict__ xres, const int* __restrict__ texp,
                          const int* __restrict__ tslot, const float* __restrict__ tw,
                          const float* __restrict__ moe, float* __restrict__ out) {
    int t = blockIdx.x;
    int e0 = texp[t * 2], e1 = texp[t * 2 + 1];
    int s0 = tslot[t * 2], s1 = tslot[t * 2 + 1];
    float w0 = tw[t * 2], w1 = tw[t * 2 + 1];
    const float* m0 = moe + ((size_t)e0 * TT + s0) * DD;
    const float* m1 = moe + ((size_t)e1 * TT + s1) * DD;
    const float* xr = xres + (ll)t * DD;
    float* o = out + (ll)t * DD;
    for (int i = threadIdx.x; i < DD; i += 256)
        o[i] = xr[i] + w0 * m0[i] + w1 * m1[i];
}

// ---------------- host side ----------------
static float* devPtrF(const void* sym) {
    void* p = nullptr;
    cudaGetSymbolAddress(&p, sym);
    return (float*)p;
}
static int* devPtrI(const void* sym) {
    void* p = nullptr;
    cudaGetSymbolAddress(&p, sym);
    return (int*)p;
}
static int smBytes(int BM, int BN, int transb, int gather) {
    int ASZ = BM * 36;
    int BSZ = transb ? BN * 36 : 32 * (BN + 8);
    return 2 * (ASZ + BSZ) * 4 + (gather ? BM * 4 : 0);
}

extern "C" void kernel_launch(void* const* d_in, const int* in_sizes, int n_in,
                              void* d_out, int out_size) {
    const float* x    = (const float*)d_in[0];
    const int*   mask = (const int*)  d_in[1];
    const float* wq1 = (const float*)d_in[2];  const float* bq1 = (const float*)d_in[3];
    const float* wq2 = (const float*)d_in[4];  const float* bq2 = (const float*)d_in[5];
    const float* wk1 = (const float*)d_in[6];  const float* bk1 = (const float*)d_in[7];
    const float* wk2 = (const float*)d_in[8];  const float* bk2 = (const float*)d_in[9];
    const float* wv1 = (const float*)d_in[10]; const float* bv1 = (const float*)d_in[11];
    const float* wv2 = (const float*)d_in[12]; const float* bv2 = (const float*)d_in[13];
    const float* wo  = (const float*)d_in[14]; const float* bo  = (const float*)d_in[15];
    const float* ln1g = (const float*)d_in[16]; const float* ln1b = (const float*)d_in[17];
    const float* ln2g = (const float*)d_in[18]; const float* ln2b = (const float*)d_in[19];
    const float* gw  = (const float*)d_in[20]; const float* gb  = (const float*)d_in[21];
    const float* ew1 = (const float*)d_in[22]; const float* eb1 = (const float*)d_in[23];
    const float* ew2 = (const float*)d_in[24]; const float* eb2 = (const float*)d_in[25];
    const float* ew3 = (const float*)d_in[26]; const float* eb3 = (const float*)d_in[27];
    float* out = (float*)d_out;

    float* x2a  = devPtrF(g_x2a);
    float* tmp1 = devPtrF(g_tmp1);
    float* qkv  = devPtrF(g_qkv);
    float* ctx  = devPtrF(g_ctx);
    float* xres = devPtrF(g_xres);
    float* x2b  = devPtrF(g_x2b);
    float* emid = devPtrF(g_emid);
    float* moe  = devPtrF(g_moe);
    int* counts = devPtrI(g_counts);
    int* etok   = devPtrI(g_etok);
    int* texp   = devPtrI(g_texp);
    int* tslot  = devPtrI(g_tslot);
    float* tw   = devPtrF(g_tw);

    float* qb = qkv;
    float* kb = qkv + (ll)TT * DD;
    float* vb = qkv + 2ll * TT * DD;

    auto kP0 = tcg<128,256,2,8,0,0,0,1,0>;   // proj1 (ZSEL)
    auto kP3 = tcg<128,256,2,8,3,0,0,1,0>;   // proj2 fused silu (ZSEL)
    auto kO1 = tcg<128,256,2,8,1,0,0,0,0>;   // oproj + residual
    auto kM1 = tcg<128,256,2,8,0,1,0,0,1>;   // moe w1 (gather, per-z)
    auto kM3 = tcg<128,256,2,8,3,1,0,0,1>;   // moe w3 fused silu (gather, per-z)
    auto kM2 = tcg<128,256,2,8,0,0,0,0,1>;   // moe w2 (per-z)

    int smP  = smBytes(128, 256, 0, 0);
    int smG  = smBytes(128, 256, 0, 1);
    int smFL = (128 * QSTR + 4 * 64 * QSTR + 128 * QSTR + 512) * 4;
    cudaFuncSetAttribute(kP0, cudaFuncAttributeMaxDynamicSharedMemorySize, smP);
    cudaFuncSetAttribute(kP3, cudaFuncAttributeMaxDynamicSharedMemorySize, smP);
    cudaFuncSetAttribute(kO1, cudaFuncAttributeMaxDynamicSharedMemorySize, smP);
    cudaFuncSetAttribute(kM1, cudaFuncAttributeMaxDynamicSharedMemorySize, smG);
    cudaFuncSetAttribute(kM3, cudaFuncAttributeMaxDynamicSharedMemorySize, smG);
    cudaFuncSetAttribute(kM2, cudaFuncAttributeMaxDynamicSharedMemorySize, smP);
    cudaFuncSetAttribute(flash_k, cudaFuncAttributeMaxDynamicSharedMemorySize, smFL);

    // 1) LN1
    ln_k<<<TT, 256>>>(x, ln1g, ln1b, x2a);

    // 2) merged SwiGLU projections: z=3 selects (q,k,v)
    dim3 gP(TT / 128, DD / 256, 3);
    kP0<<<gP, 512, smP>>>(x2a, DD, 0, 0,
        wq1, wk1, wv1, DD, 0, 0,
        bq1, bk1, bv1, 0,
        nullptr, 0,
        tmp1, DD, (ll)TT * DD, 0,
        1, TT, nullptr, DD, nullptr);
    kP3<<<gP, 512, smP>>>(x2a, DD, 0, 0,
        wq2, wk2, wv2, DD, 0, 0,
        bq2, bk2, bv2, 0,
        tmp1, (ll)TT * DD,
        qkv, DD, (ll)TT * DD, 0,
        1, TT, nullptr, DD, nullptr);

    // 3+4) flash attention (scores+softmax+ctx fused)
    flash_k<<<dim3(SS / 128, BB * HH), 512, smFL>>>(qb, kb, vb, mask, ctx);

    // 5) out proj + residual
    kO1<<<dim3(TT/128, DD/256, 1), 512, smP>>>(ctx, DD, 0, 0,
        wo, nullptr, nullptr, DD, 0, 0,
        bo, nullptr, nullptr, 0,
        x, 0,
        xres, DD, 0, 0,
        1, TT, nullptr, DD, nullptr);

    // 6) LN2
    ln_k<<<TT, 256>>>(xres, ln2g, ln2b, x2b);

    // 7) gate + routing
    zero_counts_k<<<1, 32>>>(counts);
    gate_route_k<<<TT, 256>>>(x2b, gw, gb, counts, etok, texp, tslot, tw);

    // 8) MoE: 3 launches, z = expert
    kM1<<<dim3(TT/128, FF/256, EE), 512, smG>>>(x2b, DD, 0, 0,
        ew1, nullptr, nullptr, FF, (ll)DD * FF, 0,
        eb1, nullptr, nullptr, FF,
        nullptr, 0,
        emid, FF, (ll)TT * FF, 0,
        1, 0, counts, DD, etok);
    kM3<<<dim3(TT/128, FF/256, EE), 512, smG>>>(x2b, DD, 0, 0,
        ew3, nullptr, nullptr, FF, (ll)DD * FF, 0,
        eb3, nullptr, nullptr, FF,
        emid, (ll)TT * FF,
        emid, FF, (ll)TT * FF, 0,
        1, 0, counts, DD, etok);
    kM2<<<dim3(TT/128, DD/256, EE), 512, smP>>>(emid, FF, (ll)TT * FF, 0,
        ew2, nullptr, nullptr, DD, (ll)FF * DD, 0,
        eb2, nullptr, nullptr, DD,
        nullptr, 0,
        moe, DD, (ll)TT * DD, 0,
        1, 0, counts, FF, etok);

    // 9) combine
    combine_k<<<TT, 256>>>(xres, texp, tslot, tw, moe, out);
}

// round 7
// speedup vs baseline: 13.6978x; 1.1109x over previous
#include <cuda_runtime.h>
#include <cuda_bf16.h>
#include <math.h>
#include <stdint.h>

// Problem dims
#define BB 4
#define SS 1024
#define DD 1024
#define FF 2048
#define HH 16
#define EE 8
#define DK 64
#define TT (BB*SS)          // 4096 tokens
typedef long long ll;

// ---------------- static device scratch ----------------
__device__ float g_x2a[TT*DD];
__device__ float g_qkv[3*TT*DD];                // q,k,v slices
__device__ float g_vt[TT*DD];                   // V transposed per (b,h): [b*DD+hd][s]
__device__ float g_ctx[TT*DD];
__device__ float g_xres[TT*DD];
__device__ float g_x2b[TT*DD];
__device__ float g_emid[(size_t)EE*TT*FF];      // MoE mid
__device__ float g_moe[(size_t)EE*TT*DD];
__device__ int   g_counts[EE];
__device__ int   g_etok[EE*TT];
__device__ int   g_texp[TT*2];
__device__ int   g_tslot[TT*2];
__device__ float g_tw[TT*2];

// ---------------- helpers ----------------
__device__ __forceinline__ float blockReduceSum(float v, float* sh) {
    int tid = threadIdx.x;
    sh[tid] = v; __syncthreads();
    for (int s = 128; s > 0; s >>= 1) {
        if (tid < s) sh[tid] += sh[tid + s];
        __syncthreads();
    }
    float r = sh[0]; __syncthreads();
    return r;
}
__device__ __forceinline__ void mma_tf32(float4& d, const uint32_t* a, const uint32_t* b) {
    asm volatile(
        "mma.sync.aligned.m16n8k8.row.col.f32.tf32.tf32.f32 "
        "{%0,%1,%2,%3}, {%4,%5,%6,%7}, {%8,%9}, {%0,%1,%2,%3};"
        : "+f"(d.x), "+f"(d.y), "+f"(d.z), "+f"(d.w)
        : "r"(a[0]), "r"(a[1]), "r"(a[2]), "r"(a[3]), "r"(b[0]), "r"(b[1]));
}
__device__ __forceinline__ void cpa16(float* dst, const float* src, int sz) {
    uint32_t d = (uint32_t)__cvta_generic_to_shared(dst);
    asm volatile("cp.async.cg.shared.global [%0], [%1], 16, %2;\n"
                 :: "r"(d), "l"(src), "r"(sz));
}
__device__ __forceinline__ void ldsm4(uint32_t* d, const float* p) {
    uint32_t a = (uint32_t)__cvta_generic_to_shared(p);
    asm volatile("ldmatrix.sync.aligned.m8n8.x4.shared.b16 {%0,%1,%2,%3}, [%4];"
                 : "=r"(d[0]), "=r"(d[1]), "=r"(d[2]), "=r"(d[3]) : "r"(a));
}
__device__ __forceinline__ float siluf(float x) {
    return x / (1.f + __expf(-x));
}

// ---------------- LayerNorm ----------------
__global__ void ln_k(const float* __restrict__ x, const float* __restrict__ g,
                     const float* __restrict__ b, float* __restrict__ out) {
    __shared__ float sh[256];
    int r = blockIdx.x;
    const float* row = x + (size_t)r * DD;
    float s = 0.f;
    for (int i = threadIdx.x; i < DD; i += 256) s += row[i];
    float mean = blockReduceSum(s, sh) * (1.0f / DD);
    float v = 0.f;
    for (int i = threadIdx.x; i < DD; i += 256) {
        float d = row[i] - mean; v += d * d;
    }
    float var = blockReduceSum(v, sh) * (1.0f / DD);
    float inv = rsqrtf(var + 1e-5f);
    float* o = out + (size_t)r * DD;
    for (int i = threadIdx.x; i < DD; i += 256)
        o[i] = (row[i] - mean) * inv * g[i] + b[i];
}

// ---------------- V transpose: vb[(b*S+s)*DD+hd] -> vt[(b*DD+hd)*SS+s] ----------------
__global__ void vtrans_k(const float* __restrict__ v, float* __restrict__ vt) {
    __shared__ float t[32][33];
    int b = blockIdx.z;
    int s0 = blockIdx.x * 32, d0 = blockIdx.y * 32;
    int tx = threadIdx.x, ty = threadIdx.y;       // 32 x 8
    for (int j = ty; j < 32; j += 8)
        t[j][tx] = v[((ll)(b * SS + s0 + j)) * DD + d0 + tx];
    __syncthreads();
    for (int j = ty; j < 32; j += 8)
        vt[((ll)(b * DD + d0 + j)) * SS + s0 + tx] = t[tx][j];
}

// ================= pipelined tensor-core tf32 GEMM (single) =================
template<int BM, int BN, int WGM, int WGN, int EPI, int GATHER, int MPZ>
__global__ void __launch_bounds__(WGM*WGN*32)
tcg(const float* __restrict__ A, int lda, ll sAz,
    const float* __restrict__ B0, int ldb, ll sBz,
    const float* __restrict__ bias0, ll sBiasZ,
    const float* __restrict__ S,
    float* __restrict__ C, int ldc, ll sCz,
    int M, const int* __restrict__ Mptr, int Kd,
    const int* __restrict__ tok) {
    constexpr int NTH = WGM * WGN * 32;
    constexpr int BK = 32;
    constexpr int KT = 4;
    constexpr int ASTR = 36;
    constexpr int BSTR = BN + 8;
    constexpr int ASZ = BM * ASTR;
    constexpr int BSZ = BK * BSTR;
    constexpr int STG = ASZ + BSZ;
    constexpr int WM = BM / WGM;
    constexpr int WN = BN / WGN;
    constexpr int MT = WM / 16;
    constexpr int NT = WN / 8;

    int zb = blockIdx.z;
    if (MPZ) M = Mptr[zb];
    else if (Mptr) M = *Mptr;
    int bm0 = blockIdx.x * BM;
    if (bm0 >= M) return;
    int bn0 = blockIdx.y * BN;

    const float* Bm = B0 + (ll)zb * sBz;
    const float* bias = bias0 ? bias0 + (ll)zb * sBiasZ : nullptr;
    A += (ll)zb * sAz;
    C += (ll)zb * sCz;
    if (GATHER && MPZ) tok += (ll)zb * TT;

    extern __shared__ float smf[];
    int* toks = (int*)(smf + 2 * STG);
    int tid = threadIdx.x;

    if (GATHER) {
        for (int i = tid; i < BM; i += NTH) {
            int gr = bm0 + i;
            toks[i] = (gr < M) ? tok[gr] : -1;
        }
        __syncthreads();
    }

    int wid = tid >> 5, lane = tid & 31;
    int wm = wid / WGN, wn = wid - wm * WGN;
    int lr = lane >> 2, lc = lane & 3;
    int jmat = lane >> 3, rrow = lane & 7;

    int aoff[MT];
#pragma unroll
    for (int mt = 0; mt < MT; mt++)
        aoff[mt] = (wm * WM + mt * 16 + (jmat & 1) * 8 + rrow) * ASTR + (jmat >> 1) * 4;

    auto fill = [&](int st, int k0) {
        float* As = smf + st * STG;
        float* Bs = As + ASZ;
#pragma unroll
        for (int it = 0; it < BM * 8 / NTH; it++) {
            int i = it * NTH + tid;
            int row = i >> 3, c4 = i & 7;
            float* dst = As + row * ASTR + c4 * 4;
            const float* src;
            int sz = 16;
            if (GATHER) {
                int tk = toks[row];
                src = A + (ll)(tk < 0 ? 0 : tk) * lda + k0 + c4 * 4;
                if (tk < 0) sz = 0;
            } else {
                src = A + (ll)(bm0 + row) * lda + k0 + c4 * 4;
            }
            cpa16(dst, src, sz);
        }
        constexpr int RF4 = BN / 4;
#pragma unroll
        for (int it = 0; it < BK * RF4 / NTH; it++) {
            int i = it * NTH + tid;
            int kk = i / RF4, c4 = i - kk * RF4;
            cpa16(Bs + kk * BSTR + c4 * 4,
                  Bm + (ll)(k0 + kk) * ldb + bn0 + c4 * 4, 16);
        }
    };

    float4 acc[MT][NT];
#pragma unroll
    for (int i = 0; i < MT; i++)
#pragma unroll
        for (int j = 0; j < NT; j++) acc[i][j] = make_float4(0.f, 0.f, 0.f, 0.f);

    int nIt = Kd / BK;
    fill(0, 0);
    asm volatile("cp.async.commit_group;\n");

    for (int itK = 0; itK < nIt; itK++) {
        if (itK + 1 < nIt) {
            fill((itK + 1) & 1, (itK + 1) * BK);
            asm volatile("cp.async.commit_group;\n");
            asm volatile("cp.async.wait_group 1;\n");
        } else {
            asm volatile("cp.async.wait_group 0;\n");
        }
        __syncthreads();
        const float* As = smf + (itK & 1) * STG;
        const float* Bs = As + ASZ;
#pragma unroll
        for (int kt = 0; kt < KT; kt++) {
            uint32_t af[MT][4];
            uint32_t bf[NT][2];
#pragma unroll
            for (int mt = 0; mt < MT; mt++)
                ldsm4(af[mt], As + aoff[mt] + kt * 8);
#pragma unroll
            for (int nt = 0; nt < NT; nt++) {
                const float* bp = Bs + (kt * 8 + lc) * BSTR + wn * WN + nt * 8 + lr;
                bf[nt][0] = __float_as_uint(bp[0]);
                bf[nt][1] = __float_as_uint(bp[4 * BSTR]);
            }
#pragma unroll
            for (int mt = 0; mt < MT; mt++)
#pragma unroll
                for (int nt = 0; nt < NT; nt++)
                    mma_tf32(acc[mt][nt], af[mt], bf[nt]);
        }
        __syncthreads();
    }

#pragma unroll
    for (int mt = 0; mt < MT; mt++) {
        int r0 = bm0 + wm * WM + mt * 16 + lr;
        int r1 = r0 + 8;
#pragma unroll
        for (int nt = 0; nt < NT; nt++) {
            int col = bn0 + wn * WN + nt * 8 + lc * 2;
            float v0 = acc[mt][nt].x, v1 = acc[mt][nt].y;
            float v2 = acc[mt][nt].z, v3 = acc[mt][nt].w;
            if (bias) {
                float b0 = bias[col], b1 = bias[col + 1];
                v0 += b0; v1 += b1; v2 += b0; v3 += b1;
            }
            if (EPI == 1) {
                if (r0 < M) {
                    v0 += S[(ll)r0 * ldc + col];
                    v1 += S[(ll)r0 * ldc + col + 1];
                }
                if (r1 < M) {
                    v2 += S[(ll)r1 * ldc + col];
                    v3 += S[(ll)r1 * ldc + col + 1];
                }
            }
            if (r0 < M) {
                C[(ll)r0 * ldc + col] = v0;
                C[(ll)r0 * ldc + col + 1] = v1;
            }
            if (r1 < M) {
                C[(ll)r1 * ldc + col] = v2;
                C[(ll)r1 * ldc + col + 1] = v3;
            }
        }
    }
}

// ================= dual tf32 GEMM: out = silu(A@Wa+ba) * (A@Wb+bb) =================
// BM=128, BN=128, 16 warps (4x4). ZSEL: pick among 3 weight/bias ptrs by z.
template<int GATHER, int ZSEL, int MPZ>
__global__ void __launch_bounds__(512)
tcgd(const float* __restrict__ A, int lda,
     const float* __restrict__ Ba0, const float* __restrict__ Ba1, const float* __restrict__ Ba2,
     const float* __restrict__ Bb0, const float* __restrict__ Bb1, const float* __restrict__ Bb2,
     int ldb, ll sBz,
     const float* __restrict__ ba0, const float* __restrict__ ba1, const float* __restrict__ ba2,
     const float* __restrict__ bb0, const float* __restrict__ bb1, const float* __restrict__ bb2,
     ll sBiasZ,
     float* __restrict__ C, int ldc, ll sCz,
     int M, const int* __restrict__ Mptr, int Kd,
     const int* __restrict__ tok) {
    constexpr int NTH = 512;
    constexpr int BM = 128, BN = 128, BK = 32, KT = 4;
    constexpr int ASTR = 36, BSTR = BN + 8;
    constexpr int ASZ = BM * ASTR, BSZ = BK * BSTR;
    constexpr int STG = ASZ + 2 * BSZ;
    constexpr int MT = 2, NT = 4;     // WM=32, WN=32

    int zb = blockIdx.z;
    if (MPZ) M = Mptr[zb];
    int bm0 = blockIdx.x * BM;
    if (bm0 >= M) return;
    int bn0 = blockIdx.y * BN;

    const float* BA = ZSEL ? (zb == 0 ? Ba0 : (zb == 1 ? Ba1 : Ba2)) : Ba0 + (ll)zb * sBz;
    const float* BBp = ZSEL ? (zb == 0 ? Bb0 : (zb == 1 ? Bb1 : Bb2)) : Bb0 + (ll)zb * sBz;
    const float* biasA = ZSEL ? (zb == 0 ? ba0 : (zb == 1 ? ba1 : ba2)) : ba0 + (ll)zb * sBiasZ;
    const float* biasB = ZSEL ? (zb == 0 ? bb0 : (zb == 1 ? bb1 : bb2)) : bb0 + (ll)zb * sBiasZ;
    C += (ll)zb * sCz;
    if (GATHER && MPZ) tok += (ll)zb * TT;

    extern __shared__ float smf[];
    int* toks = (int*)(smf + 2 * STG);
    int tid = threadIdx.x;

    if (GATHER) {
        for (int i = tid; i < BM; i += NTH) {
            int gr = bm0 + i;
            toks[i] = (gr < M) ? tok[gr] : -1;
        }
        __syncthreads();
    }

    int wid = tid >> 5, lane = tid & 31;
    int wm = wid >> 2, wn = wid & 3;
    int lr = lane >> 2, lc = lane & 3;
    int jmat = lane >> 3, rrow = lane & 7;

    int aoff[MT];
#pragma unroll
    for (int mt = 0; mt < MT; mt++)
        aoff[mt] = (wm * 32 + mt * 16 + (jmat & 1) * 8 + rrow) * ASTR + (jmat >> 1) * 4;

    auto fill = [&](int st, int k0) {
        float* As = smf + st * STG;
        float* Bsa = As + ASZ;
        float* Bsb = Bsa + BSZ;
#pragma unroll
        for (int it = 0; it < 2; it++) {
            int i = it * NTH + tid;
            int row = i >> 3, c4 = i & 7;
            float* dst = As + row * ASTR + c4 * 4;
            const float* src;
            int sz = 16;
            if (GATHER) {
                int tk = toks[row];
                src = A + (ll)(tk < 0 ? 0 : tk) * lda + k0 + c4 * 4;
                if (tk < 0) sz = 0;
            } else {
                src = A + (ll)(bm0 + row) * lda + k0 + c4 * 4;
            }
            cpa16(dst, src, sz);
        }
        constexpr int RF4 = BN / 4;   // 32
#pragma unroll
        for (int it = 0; it < 2; it++) {
            int i = it * NTH + tid;
            int kk = i / RF4, c4 = i - kk * RF4;
            cpa16(Bsa + kk * BSTR + c4 * 4, BA  + (ll)(k0 + kk) * ldb + bn0 + c4 * 4, 16);
            cpa16(Bsb + kk * BSTR + c4 * 4, BBp + (ll)(k0 + kk) * ldb + bn0 + c4 * 4, 16);
        }
    };

    float4 accA[MT][NT], accB[MT][NT];
#pragma unroll
    for (int i = 0; i < MT; i++)
#pragma unroll
        for (int j = 0; j < NT; j++) {
            accA[i][j] = make_float4(0.f, 0.f, 0.f, 0.f);
            accB[i][j] = make_float4(0.f, 0.f, 0.f, 0.f);
        }

    int nIt = Kd / BK;
    fill(0, 0);
    asm volatile("cp.async.commit_group;\n");

    for (int itK = 0; itK < nIt; itK++) {
        if (itK + 1 < nIt) {
            fill((itK + 1) & 1, (itK + 1) * BK);
            asm volatile("cp.async.commit_group;\n");
            asm volatile("cp.async.wait_group 1;\n");
        } else {
            asm volatile("cp.async.wait_group 0;\n");
        }
        __syncthreads();
        const float* As = smf + (itK & 1) * STG;
        const float* Bsa = As + ASZ;
        const float* Bsb = Bsa + BSZ;
#pragma unroll
        for (int kt = 0; kt < KT; kt++) {
            uint32_t af[MT][4];
#pragma unroll
            for (int mt = 0; mt < MT; mt++)
                ldsm4(af[mt], As + aoff[mt] + kt * 8);
            uint32_t bfa[NT][2], bfb[NT][2];
#pragma unroll
            for (int nt = 0; nt < NT; nt++) {
                int off = (kt * 8 + lc) * BSTR + wn * 32 + nt * 8 + lr;
                bfa[nt][0] = __float_as_uint(Bsa[off]);
                bfa[nt][1] = __float_as_uint(Bsa[off + 4 * BSTR]);
                bfb[nt][0] = __float_as_uint(Bsb[off]);
                bfb[nt][1] = __float_as_uint(Bsb[off + 4 * BSTR]);
            }
#pragma unroll
            for (int mt = 0; mt < MT; mt++)
#pragma unroll
                for (int nt = 0; nt < NT; nt++) {
                    mma_tf32(accA[mt][nt], af[mt], bfa[nt]);
                    mma_tf32(accB[mt][nt], af[mt], bfb[nt]);
                }
        }
        __syncthreads();
    }

#pragma unroll
    for (int mt = 0; mt < MT; mt++) {
        int r0 = bm0 + wm * 32 + mt * 16 + lr;
        int r1 = r0 + 8;
#pragma unroll
        for (int nt = 0; nt < NT; nt++) {
            int col = bn0 + wn * 32 + nt * 8 + lc * 2;
            float ba_ = biasA[col], ba1_ = biasA[col + 1];
            float bb_ = biasB[col], bb1_ = biasB[col + 1];
            if (r0 < M) {
                C[(ll)r0 * ldc + col]     = siluf(accA[mt][nt].x + ba_)  * (accB[mt][nt].x + bb_);
                C[(ll)r0 * ldc + col + 1] = siluf(accA[mt][nt].y + ba1_) * (accB[mt][nt].y + bb1_);
            }
            if (r1 < M) {
                C[(ll)r1 * ldc + col]     = siluf(accA[mt][nt].z + ba_)  * (accB[mt][nt].z + bb_);
                C[(ll)r1 * ldc + col + 1] = siluf(accA[mt][nt].w + ba1_) * (accB[mt][nt].w + bb1_);
            }
        }
    }
}

// ================= flash attention (tf32, V pre-transposed) =================
// grid (SS/128, BB*HH), 512 threads (16 warps, 8x2). Ps aliases Qs.
#define QSTR 68
__global__ void __launch_bounds__(512)
flash_k(const float* __restrict__ qg, const float* __restrict__ kg,
        const float* __restrict__ vtg, const int* __restrict__ maskp,
        float* __restrict__ ctx) {
    extern __shared__ float sm[];
    float* Qs = sm;                         // 128*68 (becomes Ps)
    float* Ks = sm + 128 * QSTR;            // 2 * 64*68
    float* Vs = Ks + 2 * 64 * QSTR;         // 2 * 64*68 (transposed: [dk][key])
    float* redM = Vs + 2 * 64 * QSTR;       // 256
    float* redL = redM + 256;               // 256
    float* Ps = Qs;

    int tid = threadIdx.x;
    int z = blockIdx.y;
    int b = z / HH, h = z % HH;
    int q0 = blockIdx.x * 128;
    int lane = tid & 31, wid = tid >> 5;
    int wm = wid >> 1, wn = wid & 1;
    int lr = lane >> 2, lc = lane & 3;
    int jmat = lane >> 3, rrow = lane & 7;

    const float* Qg = qg + ((ll)(b * SS + q0)) * DD + h * DK;
#pragma unroll
    for (int it = 0; it < 4; it++) {
        int i = it * 512 + tid;
        int row = i >> 4, c4 = i & 15;
        cpa16(Qs + row * QSTR + c4 * 4, Qg + (ll)row * DD + c4 * 4, 16);
    }
    asm volatile("cp.async.commit_group;\n");

    auto pf = [&](int i) {
        int st = i & 1;
        const float* Kg = kg + ((ll)(b * SS + i * 64)) * DD + h * DK;
        const float* Vg = vtg + ((ll)(b * DD + h * DK)) * SS + i * 64;
#pragma unroll
        for (int it = 0; it < 2; it++) {
            int j = it * 512 + tid;
            int row = j >> 4, c4 = j & 15;
            cpa16(Ks + st * 64 * QSTR + row * QSTR + c4 * 4, Kg + (ll)row * DD + c4 * 4, 16);
        }
#pragma unroll
        for (int it = 0; it < 2; it++) {
            int j = it * 512 + tid;
            int row = j >> 4, c4 = j & 15;    // row = dk, 64 keys = 16 chunks
            cpa16(Vs + st * 64 * QSTR + row * QSTR + c4 * 4, Vg + (ll)row * SS + c4 * 4, 16);
        }
    };
    pf(0);
    asm volatile("cp.async.commit_group;\n");

    // Q fragments (register resident)
    asm volatile("cp.async.wait_group 1;\n");
    __syncthreads();
    uint32_t qf[8][4];
    int aoffQ = (wm * 16 + (jmat & 1) * 8 + rrow) * QSTR + (jmat >> 1) * 4;
#pragma unroll
    for (int kt = 0; kt < 8; kt++) ldsm4(qf[kt], Qs + aoffQ + kt * 8);

    float4 oacc[4];
#pragma unroll
    for (int nt = 0; nt < 4; nt++) oacc[nt] = make_float4(0.f, 0.f, 0.f, 0.f);
    float m0 = -1e30f, m1 = -1e30f, l0 = 0.f, l1 = 0.f;
    int r0 = wm * 16 + lr, r1 = r0 + 8;
    int gq0 = q0 + r0, gq1 = q0 + r1;
    const int* mbase = maskp + (ll)b * SS * SS;

    constexpr int NIT = SS / 64;
    for (int i = 0; i < NIT; i++) {
        if (i + 1 < NIT) {
            pf(i + 1);
            asm volatile("cp.async.commit_group;\n");
            asm volatile("cp.async.wait_group 1;\n");
        } else {
            asm volatile("cp.async.wait_group 0;\n");
        }
        __syncthreads();
        const float* Kst = Ks + (i & 1) * 64 * QSTR;
        const float* Vst = Vs + (i & 1) * 64 * QSTR;

        // S = Q @ K^T
        float4 s[4];
#pragma unroll
        for (int nt = 0; nt < 4; nt++) s[nt] = make_float4(0.f, 0.f, 0.f, 0.f);
#pragma unroll
        for (int kt = 0; kt < 8; kt++) {
            uint32_t bf[4][2];
#pragma unroll
            for (int p = 0; p < 2; p++) {
                uint32_t t4[4];
                ldsm4(t4, Kst + (wn * 32 + p * 16 + (jmat >> 1) * 8 + rrow) * QSTR
                          + (jmat & 1) * 4 + kt * 8);
                bf[2 * p][0] = t4[0]; bf[2 * p][1] = t4[1];
                bf[2 * p + 1][0] = t4[2]; bf[2 * p + 1][1] = t4[3];
            }
#pragma unroll
            for (int nt = 0; nt < 4; nt++) mma_tf32(s[nt], qf[kt], bf[nt]);
        }
        // scale + mask (int2 vector loads)
#pragma unroll
        for (int nt = 0; nt < 4; nt++) {
            int gk = i * 64 + wn * 32 + nt * 8 + lc * 2;
            int2 mr0 = *(const int2*)(mbase + (ll)gq0 * SS + gk);
            int2 mr1 = *(const int2*)(mbase + (ll)gq1 * SS + gk);
            s[nt].x = mr0.x ? s[nt].x * 0.125f : -1e9f;
            s[nt].y = mr0.y ? s[nt].y * 0.125f : -1e9f;
            s[nt].z = mr1.x ? s[nt].z * 0.125f : -1e9f;
            s[nt].w = mr1.y ? s[nt].w * 0.125f : -1e9f;
        }
        // row max (warp partial + cross-warp via smem)
        float mx0 = -1e30f, mx1 = -1e30f;
#pragma unroll
        for (int nt = 0; nt < 4; nt++) {
            mx0 = fmaxf(mx0, fmaxf(s[nt].x, s[nt].y));
            mx1 = fmaxf(mx1, fmaxf(s[nt].z, s[nt].w));
        }
#pragma unroll
        for (int o = 1; o <= 2; o <<= 1) {
            mx0 = fmaxf(mx0, __shfl_xor_sync(0xffffffff, mx0, o));
            mx1 = fmaxf(mx1, __shfl_xor_sync(0xffffffff, mx1, o));
        }
        if (lc == 0) { redM[r0 * 2 + wn] = mx0; redM[r1 * 2 + wn] = mx1; }
        __syncthreads();
        float nm0 = fmaxf(m0, fmaxf(redM[r0 * 2], redM[r0 * 2 + 1]));
        float nm1 = fmaxf(m1, fmaxf(redM[r1 * 2], redM[r1 * 2 + 1]));
        float sc0 = __expf(m0 - nm0), sc1 = __expf(m1 - nm1);
        m0 = nm0; m1 = nm1;
        // exp + store P + partial sums
        float su0 = 0.f, su1 = 0.f;
#pragma unroll
        for (int nt = 0; nt < 4; nt++) {
            int col = wn * 32 + nt * 8 + lc * 2;
            float e0 = __expf(s[nt].x - m0), e1 = __expf(s[nt].y - m0);
            float e2 = __expf(s[nt].z - m1), e3 = __expf(s[nt].w - m1);
            su0 += e0 + e1; su1 += e2 + e3;
            Ps[r0 * QSTR + col] = e0; Ps[r0 * QSTR + col + 1] = e1;
            Ps[r1 * QSTR + col] = e2; Ps[r1 * QSTR + col + 1] = e3;
        }
#pragma unroll
        for (int o = 1; o <= 2; o <<= 1) {
            su0 += __shfl_xor_sync(0xffffffff, su0, o);
            su1 += __shfl_xor_sync(0xffffffff, su1, o);
        }
        if (lc == 0) { redL[r0 * 2 + wn] = su0; redL[r1 * 2 + wn] = su1; }
        __syncthreads();
        l0 = l0 * sc0 + redL[r0 * 2] + redL[r0 * 2 + 1];
        l1 = l1 * sc1 + redL[r1 * 2] + redL[r1 * 2 + 1];
#pragma unroll
        for (int nt = 0; nt < 4; nt++) {
            oacc[nt].x *= sc0; oacc[nt].y *= sc0;
            oacc[nt].z *= sc1; oacc[nt].w *= sc1;
        }
        // O += P @ V   (V transposed in smem -> ldmatrix B fragments)
        int aoffP = (wm * 16 + (jmat & 1) * 8 + rrow) * QSTR + (jmat >> 1) * 4;
#pragma unroll
        for (int kt = 0; kt < 8; kt++) {
            uint32_t af[4];
            ldsm4(af, Ps + aoffP + kt * 8);
            uint32_t bf[4][2];
#pragma unroll
            for (int p = 0; p < 2; p++) {
                uint32_t t4[4];
                ldsm4(t4, Vst + (wn * 32 + p * 16 + (jmat >> 1) * 8 + rrow) * QSTR
                          + (jmat & 1) * 4 + kt * 8);
                bf[2 * p][0] = t4[0]; bf[2 * p][1] = t4[1];
                bf[2 * p + 1][0] = t4[2]; bf[2 * p + 1][1] = t4[3];
            }
#pragma unroll
            for (int nt = 0; nt < 4; nt++) mma_tf32(oacc[nt], af, bf[nt]);
        }
        __syncthreads();
    }

    float inv0 = 1.f / l0, inv1 = 1.f / l1;
    float* cg = ctx + ((ll)(b * SS + q0)) * DD + h * DK;
#pragma unroll
    for (int nt = 0; nt < 4; nt++) {
        int col = wn * 32 + nt * 8 + lc * 2;
        cg[(ll)r0 * DD + col]     = oacc[nt].x * inv0;
        cg[(ll)r0 * DD + col + 1] = oacc[nt].y * inv0;
        cg[(ll)r1 * DD + col]     = oacc[nt].z * inv1;
        cg[(ll)r1 * DD + col + 1] = oacc[nt].w * inv1;
    }
}

// ---------------- gate + routing ----------------
__global__ void zero_counts_k(int* counts) {
    if (threadIdx.x < EE) counts[threadIdx.x] = 0;
}
__global__ void gate_route_k(const float* __restrict__ x2, const float* __restrict__ gw,
                             const float* __restrict__ gb, int* counts, int* etok,
                             int* texp, int* tslot, float* tw) {
    int t = blockIdx.x;
    __shared__ float xs[DD];
    __shared__ float logits[EE];
    const float* row = x2 + (ll)t * DD;
    for (int i = threadIdx.x; i < DD; i += 256) xs[i] = row[i];
    __syncthreads();
    int w = threadIdx.x / 32, lane = threadIdx.x % 32;
    float s = 0.f;
    for (int d = lane; d < DD; d += 32) s += xs[d] * gw[d * EE + w];
    for (int o = 16; o; o >>= 1) s += __shfl_xor_sync(0xffffffff, s, o);
    if (lane == 0) logits[w] = s + gb[w];
    __syncthreads();
    if (threadIdx.x == 0) {
        float p[EE];
        float m = -1e30f;
        for (int e = 0; e < EE; e++) m = fmaxf(m, logits[e]);
        float sum = 0.f;
        for (int e = 0; e < EE; e++) { p[e] = __expf(logits[e] - m); sum += p[e]; }
        for (int e = 0; e < EE; e++) p[e] /= sum;
        int i0 = 0;
        for (int e = 1; e < EE; e++) if (p[e] > p[i0]) i0 = e;
        int i1 = -1;
        for (int e = 0; e < EE; e++) {
            if (e == i0) continue;
            if (i1 < 0 || p[e] > p[i1]) i1 = e;
        }
        float denom = p[i0] + p[i1] + 1e-6f;
        int s0 = atomicAdd(&counts[i0], 1);
        int s1 = atomicAdd(&counts[i1], 1);
        etok[i0 * TT + s0] = t;
        etok[i1 * TT + s1] = t;
        texp[t * 2] = i0; texp[t * 2 + 1] = i1;
        tslot[t * 2] = s0; tslot[t * 2 + 1] = s1;
        tw[t * 2] = p[i0] / denom; tw[t * 2 + 1] = p[i1] / denom;
    }
}

// ---------------- final combine ----------------
__global__ void combine_k(const float* __restrict__ xres, const int* __restrict__ texp,
                          const int* __restrict__ tslot, const float* __restrict__ tw,
                          const float* __restrict__ moe, float* __restrict__ out) {
    int t = blockIdx.x;
    int e0 = texp[t * 2], e1 = texp[t * 2 + 1];
    int s0 = tslot[t * 2], s1 = tslot[t * 2 + 1];
    float w0 = tw[t * 2], w1 = tw[t * 2 + 1];
    const float* m0 = moe + ((size_t)e0 * TT + s0) * DD;
    const float* m1 = moe + ((size_t)e1 * TT + s1) * DD;
    const float* xr = xres + (ll)t * DD;
    float* o = out + (ll)t * DD;
    for (int i = threadIdx.x; i < DD; i += 256)
        o[i] = xr[i] + w0 * m0[i] + w1 * m1[i];
}

// ---------------- host side ----------------
static float* devPtrF(const void* sym) {
    void* p = nullptr;
    cudaGetSymbolAddress(&p, sym);
    return (float*)p;
}
static int* devPtrI(const void* sym) {
    void* p = nullptr;
    cudaGetSymbolAddress(&p, sym);
    return (int*)p;
}

extern "C" void kernel_launch(void* const* d_in, const int* in_sizes, int n_in,
                              void* d_out, int out_size) {
    const float* x    = (const float*)d_in[0];
    const int*   mask = (const int*)  d_in[1];
    const float* wq1 = (const float*)d_in[2];  const float* bq1 = (const float*)d_in[3];
    const float* wq2 = (const float*)d_in[4];  const float* bq2 = (const float*)d_in[5];
    const float* wk1 = (const float*)d_in[6];  const float* bk1 = (const float*)d_in[7];
    const float* wk2 = (const float*)d_in[8];  const float* bk2 = (const float*)d_in[9];
    const float* wv1 = (const float*)d_in[10]; const float* bv1 = (const float*)d_in[11];
    const float* wv2 = (const float*)d_in[12]; const float* bv2 = (const float*)d_in[13];
    const float* wo  = (const float*)d_in[14]; const float* bo  = (const float*)d_in[15];
    const float* ln1g = (const float*)d_in[16]; const float* ln1b = (const float*)d_in[17];
    const float* ln2g = (const float*)d_in[18]; const float* ln2b = (const float*)d_in[19];
    const float* gw  = (const float*)d_in[20]; const float* gb  = (const float*)d_in[21];
    const float* ew1 = (const float*)d_in[22]; const float* eb1 = (const float*)d_in[23];
    const float* ew2 = (const float*)d_in[24]; const float* eb2 = (const float*)d_in[25];
    const float* ew3 = (const float*)d_in[26]; const float* eb3 = (const float*)d_in[27];
    float* out = (float*)d_out;

    float* x2a  = devPtrF(g_x2a);
    float* qkv  = devPtrF(g_qkv);
    float* vt   = devPtrF(g_vt);
    float* ctx  = devPtrF(g_ctx);
    float* xres = devPtrF(g_xres);
    float* x2b  = devPtrF(g_x2b);
    float* emid = devPtrF(g_emid);
    float* moe  = devPtrF(g_moe);
    int* counts = devPtrI(g_counts);
    int* etok   = devPtrI(g_etok);
    int* texp   = devPtrI(g_texp);
    int* tslot  = devPtrI(g_tslot);
    float* tw   = devPtrF(g_tw);

    float* qb = qkv;
    float* kb = qkv + (ll)TT * DD;
    float* vb = qkv + 2ll * TT * DD;

    auto kDP = tcgd<0,1,0>;                   // dual proj (ZSEL)
    auto kDM = tcgd<1,0,1>;                   // dual MoE up (gather, per-z)
    auto kO1 = tcg<128,256,2,8,1,0,0>;        // oproj + residual
    auto kM2 = tcg<128,256,2,8,0,0,1>;        // moe down (per-z)

    int smD  = (2 * (128 * 36 + 2 * 32 * 136) + 128) * 4;   // dual gemm
    int smP  = (2 * (128 * 36 + 32 * (256 + 8))) * 4;       // 128x256 single
    int smFL = (128 * QSTR + 4 * 64 * QSTR + 512) * 4;      // flash (Ps aliases Qs)
    cudaFuncSetAttribute(kDP, cudaFuncAttributeMaxDynamicSharedMemorySize, smD);
    cudaFuncSetAttribute(kDM, cudaFuncAttributeMaxDynamicSharedMemorySize, smD);
    cudaFuncSetAttribute(kO1, cudaFuncAttributeMaxDynamicSharedMemorySize, smP);
    cudaFuncSetAttribute(kM2, cudaFuncAttributeMaxDynamicSharedMemorySize, smP);
    cudaFuncSetAttribute(flash_k, cudaFuncAttributeMaxDynamicSharedMemorySize, smFL);

    // 1) LN1
    ln_k<<<TT, 256>>>(x, ln1g, ln1b, x2a);

    // 2) fused SwiGLU projections: one dual-GEMM launch, z selects (q,k,v)
    kDP<<<dim3(TT/128, DD/128, 3), 512, smD>>>(x2a, DD,
        wq1, wk1, wv1, wq2, wk2, wv2, DD, 0,
        bq1, bk1, bv1, bq2, bk2, bv2, 0,
        qkv, DD, (ll)TT * DD,
        TT, nullptr, DD, nullptr);

    // 2b) transpose V for flash
    vtrans_k<<<dim3(SS/32, DD/32, BB), dim3(32, 8)>>>(vb, vt);

    // 3+4) flash attention
    flash_k<<<dim3(SS / 128, BB * HH), 512, smFL>>>(qb, kb, vt, mask, ctx);

    // 5) out proj + residual
    kO1<<<dim3(TT/128, DD/256, 1), 512, smP>>>(ctx, DD, 0,
        wo, DD, 0, bo, 0, x,
        xres, DD, 0,
        TT, nullptr, DD, nullptr);

    // 6) LN2
    ln_k<<<TT, 256>>>(xres, ln2g, ln2b, x2b);

    // 7) gate + routing
    zero_counts_k<<<1, 32>>>(counts);
    gate_route_k<<<TT, 256>>>(x2b, gw, gb, counts, etok, texp, tslot, tw);

    // 8) MoE: dual up-proj (1 launch) + down-proj (1 launch), z = expert
    kDM<<<dim3(TT/128, FF/128, EE), 512, smD>>>(x2b, DD,
        ew1, nullptr, nullptr, ew3, nullptr, nullptr, FF, (ll)DD * FF,
        eb1, nullptr, nullptr, eb3, nullptr, nullptr, FF,
        emid, FF, (ll)TT * FF,
        0, counts, DD, etok);
    kM2<<<dim3(TT/128, DD/256, EE), 512, smP>>>(emid, FF, (ll)TT * FF,
        ew2, DD, (ll)FF * DD, eb2, DD, nullptr,
        moe, DD, (ll)TT * DD,
        0, counts, FF, nullptr);

    // 9) combine
    combine_k<<<TT, 256>>>(xres, texp, tslot, tw, moe, out);
}

// round 8
// speedup vs baseline: 15.3675x; 1.1219x over previous
#include <cuda_runtime.h>
#include <cuda_bf16.h>
#include <math.h>
#include <stdint.h>

// Problem dims
#define BB 4
#define SS 1024
#define DD 1024
#define FF 2048
#define HH 16
#define EE 8
#define DK 64
#define TT (BB*SS)          // 4096 tokens
typedef long long ll;

// ---------------- static device scratch ----------------
__device__ float g_x2a[TT*DD];
__device__ float g_qkv[3*TT*DD];                // q,k,v slices
__device__ float g_vt[TT*DD];                   // V transposed per (b,h): [b*DD+hd][s]
__device__ float g_ctx[TT*DD];
__device__ float g_xres[TT*DD];
__device__ float g_x2b[TT*DD];
__device__ float g_emid[(size_t)EE*TT*FF];      // MoE mid
__device__ float g_moe[(size_t)EE*TT*DD];
__device__ int   g_counts[EE];
__device__ int   g_etok[EE*TT];
__device__ int   g_texp[TT*2];
__device__ int   g_tslot[TT*2];
__device__ float g_tw[TT*2];

// ---------------- helpers ----------------
__device__ __forceinline__ float blockReduceSum(float v, float* sh) {
    int tid = threadIdx.x;
    sh[tid] = v; __syncthreads();
    for (int s = 128; s > 0; s >>= 1) {
        if (tid < s) sh[tid] += sh[tid + s];
        __syncthreads();
    }
    float r = sh[0]; __syncthreads();
    return r;
}
__device__ __forceinline__ void mma_tf32(float4& d, const uint32_t* a, const uint32_t* b) {
    asm volatile(
        "mma.sync.aligned.m16n8k8.row.col.f32.tf32.tf32.f32 "
        "{%0,%1,%2,%3}, {%4,%5,%6,%7}, {%8,%9}, {%0,%1,%2,%3};"
        : "+f"(d.x), "+f"(d.y), "+f"(d.z), "+f"(d.w)
        : "r"(a[0]), "r"(a[1]), "r"(a[2]), "r"(a[3]), "r"(b[0]), "r"(b[1]));
}
__device__ __forceinline__ void cpa16(float* dst, const float* src, int sz) {
    uint32_t d = (uint32_t)__cvta_generic_to_shared(dst);
    asm volatile("cp.async.cg.shared.global [%0], [%1], 16, %2;\n"
                 :: "r"(d), "l"(src), "r"(sz));
}
__device__ __forceinline__ void ldsm4(uint32_t* d, const float* p) {
    uint32_t a = (uint32_t)__cvta_generic_to_shared(p);
    asm volatile("ldmatrix.sync.aligned.m8n8.x4.shared.b16 {%0,%1,%2,%3}, [%4];"
                 : "=r"(d[0]), "=r"(d[1]), "=r"(d[2]), "=r"(d[3]) : "r"(a));
}
__device__ __forceinline__ float siluf(float x) {
    return x / (1.f + __expf(-x));
}

// ---------------- LayerNorm ----------------
__global__ void ln_k(const float* __restrict__ x, const float* __restrict__ g,
                     const float* __restrict__ b, float* __restrict__ out) {
    __shared__ float sh[256];
    int r = blockIdx.x;
    const float* row = x + (size_t)r * DD;
    float s = 0.f;
    for (int i = threadIdx.x; i < DD; i += 256) s += row[i];
    float mean = blockReduceSum(s, sh) * (1.0f / DD);
    float v = 0.f;
    for (int i = threadIdx.x; i < DD; i += 256) {
        float d = row[i] - mean; v += d * d;
    }
    float var = blockReduceSum(v, sh) * (1.0f / DD);
    float inv = rsqrtf(var + 1e-5f);
    float* o = out + (size_t)r * DD;
    for (int i = threadIdx.x; i < DD; i += 256)
        o[i] = (row[i] - mean) * inv * g[i] + b[i];
}

// ---------------- V transpose: vb[(b*S+s)*DD+hd] -> vt[(b*DD+hd)*SS+s] ----------------
__global__ void vtrans_k(const float* __restrict__ v, float* __restrict__ vt) {
    __shared__ float t[32][33];
    int b = blockIdx.z;
    int s0 = blockIdx.x * 32, d0 = blockIdx.y * 32;
    int tx = threadIdx.x, ty = threadIdx.y;       // 32 x 8
    for (int j = ty; j < 32; j += 8)
        t[j][tx] = v[((ll)(b * SS + s0 + j)) * DD + d0 + tx];
    __syncthreads();
    for (int j = ty; j < 32; j += 8)
        vt[((ll)(b * DD + d0 + j)) * SS + s0 + tx] = t[tx][j];
}

// ================= 3-stage pipelined tensor-core tf32 GEMM (single) =================
template<int BM, int BN, int WGM, int WGN, int EPI, int GATHER, int MPZ>
__global__ void __launch_bounds__(WGM*WGN*32)
tcg(const float* __restrict__ A, int lda, ll sAz,
    const float* __restrict__ B0, int ldb, ll sBz,
    const float* __restrict__ bias0, ll sBiasZ,
    const float* __restrict__ S,
    float* __restrict__ C, int ldc, ll sCz,
    int M, const int* __restrict__ Mptr, int Kd,
    const int* __restrict__ tok) {
    constexpr int NTH = WGM * WGN * 32;
    constexpr int BK = 32;
    constexpr int KT = 4;
    constexpr int ASTR = 36;
    constexpr int BSTR = BN + 8;
    constexpr int ASZ = BM * ASTR;
    constexpr int BSZ = BK * BSTR;
    constexpr int STG = ASZ + BSZ;
    constexpr int WM = BM / WGM;
    constexpr int WN = BN / WGN;
    constexpr int MT = WM / 16;
    constexpr int NT = WN / 8;

    int zb = blockIdx.z;
    if (MPZ) M = Mptr[zb];
    else if (Mptr) M = *Mptr;
    int bm0 = blockIdx.x * BM;
    if (bm0 >= M) return;
    int bn0 = blockIdx.y * BN;

    const float* Bm = B0 + (ll)zb * sBz;
    const float* bias = bias0 ? bias0 + (ll)zb * sBiasZ : nullptr;
    A += (ll)zb * sAz;
    C += (ll)zb * sCz;
    if (GATHER && MPZ) tok += (ll)zb * TT;

    extern __shared__ float smf[];
    int* toks = (int*)(smf + 3 * STG);
    int tid = threadIdx.x;

    if (GATHER) {
        for (int i = tid; i < BM; i += NTH) {
            int gr = bm0 + i;
            toks[i] = (gr < M) ? tok[gr] : -1;
        }
        __syncthreads();
    }

    int wid = tid >> 5, lane = tid & 31;
    int wm = wid / WGN, wn = wid - wm * WGN;
    int lr = lane >> 2, lc = lane & 3;
    int jmat = lane >> 3, rrow = lane & 7;

    int aoff[MT];
#pragma unroll
    for (int mt = 0; mt < MT; mt++)
        aoff[mt] = (wm * WM + mt * 16 + (jmat & 1) * 8 + rrow) * ASTR + (jmat >> 1) * 4;

    auto fill = [&](int st, int k0) {
        float* As = smf + st * STG;
        float* Bs = As + ASZ;
#pragma unroll
        for (int it = 0; it < BM * 8 / NTH; it++) {
            int i = it * NTH + tid;
            int row = i >> 3, c4 = i & 7;
            float* dst = As + row * ASTR + c4 * 4;
            const float* src;
            int sz = 16;
            if (GATHER) {
                int tk = toks[row];
                src = A + (ll)(tk < 0 ? 0 : tk) * lda + k0 + c4 * 4;
                if (tk < 0) sz = 0;
            } else {
                src = A + (ll)(bm0 + row) * lda + k0 + c4 * 4;
            }
            cpa16(dst, src, sz);
        }
        constexpr int RF4 = BN / 4;
#pragma unroll
        for (int it = 0; it < BK * RF4 / NTH; it++) {
            int i = it * NTH + tid;
            int kk = i / RF4, c4 = i - kk * RF4;
            cpa16(Bs + kk * BSTR + c4 * 4,
                  Bm + (ll)(k0 + kk) * ldb + bn0 + c4 * 4, 16);
        }
    };

    float4 acc[MT][NT];
#pragma unroll
    for (int i = 0; i < MT; i++)
#pragma unroll
        for (int j = 0; j < NT; j++) acc[i][j] = make_float4(0.f, 0.f, 0.f, 0.f);

    int nIt = Kd / BK;
    fill(0, 0);
    asm volatile("cp.async.commit_group;\n");
    if (nIt > 1) {
        fill(1, BK);
        asm volatile("cp.async.commit_group;\n");
    }

    for (int itK = 0; itK < nIt; itK++) {
        if (itK + 1 < nIt) asm volatile("cp.async.wait_group 1;\n");
        else               asm volatile("cp.async.wait_group 0;\n");
        __syncthreads();
        const float* As = smf + (itK % 3) * STG;
        const float* Bs = As + ASZ;
#pragma unroll
        for (int kt = 0; kt < KT; kt++) {
            uint32_t af[MT][4];
            uint32_t bf[NT][2];
#pragma unroll
            for (int mt = 0; mt < MT; mt++)
                ldsm4(af[mt], As + aoff[mt] + kt * 8);
#pragma unroll
            for (int nt = 0; nt < NT; nt++) {
                const float* bp = Bs + (kt * 8 + lc) * BSTR + wn * WN + nt * 8 + lr;
                bf[nt][0] = __float_as_uint(bp[0]);
                bf[nt][1] = __float_as_uint(bp[4 * BSTR]);
            }
#pragma unroll
            for (int mt = 0; mt < MT; mt++)
#pragma unroll
                for (int nt = 0; nt < NT; nt++)
                    mma_tf32(acc[mt][nt], af[mt], bf[nt]);
        }
        if (itK + 2 < nIt) {
            fill((itK + 2) % 3, (itK + 2) * BK);
            asm volatile("cp.async.commit_group;\n");
        }
    }

#pragma unroll
    for (int mt = 0; mt < MT; mt++) {
        int r0 = bm0 + wm * WM + mt * 16 + lr;
        int r1 = r0 + 8;
#pragma unroll
        for (int nt = 0; nt < NT; nt++) {
            int col = bn0 + wn * WN + nt * 8 + lc * 2;
            float v0 = acc[mt][nt].x, v1 = acc[mt][nt].y;
            float v2 = acc[mt][nt].z, v3 = acc[mt][nt].w;
            if (bias) {
                float b0 = bias[col], b1 = bias[col + 1];
                v0 += b0; v1 += b1; v2 += b0; v3 += b1;
            }
            if (EPI == 1) {
                if (r0 < M) {
                    v0 += S[(ll)r0 * ldc + col];
                    v1 += S[(ll)r0 * ldc + col + 1];
                }
                if (r1 < M) {
                    v2 += S[(ll)r1 * ldc + col];
                    v3 += S[(ll)r1 * ldc + col + 1];
                }
            }
            if (r0 < M) {
                C[(ll)r0 * ldc + col] = v0;
                C[(ll)r0 * ldc + col + 1] = v1;
            }
            if (r1 < M) {
                C[(ll)r1 * ldc + col] = v2;
                C[(ll)r1 * ldc + col + 1] = v3;
            }
        }
    }
}

// ================= dual tf32 GEMM: out = silu(A@Wa+ba) * (A@Wb+bb) =================
// BM=128, BN=128, 16 warps (4x4), 3-stage pipeline.
template<int GATHER, int ZSEL, int MPZ>
__global__ void __launch_bounds__(512)
tcgd(const float* __restrict__ A, int lda,
     const float* __restrict__ Ba0, const float* __restrict__ Ba1, const float* __restrict__ Ba2,
     const float* __restrict__ Bb0, const float* __restrict__ Bb1, const float* __restrict__ Bb2,
     int ldb, ll sBz,
     const float* __restrict__ ba0, const float* __restrict__ ba1, const float* __restrict__ ba2,
     const float* __restrict__ bb0, const float* __restrict__ bb1, const float* __restrict__ bb2,
     ll sBiasZ,
     float* __restrict__ C, int ldc, ll sCz,
     int M, const int* __restrict__ Mptr, int Kd,
     const int* __restrict__ tok) {
    constexpr int NTH = 512;
    constexpr int BM = 128, BN = 128, BK = 32, KT = 4;
    constexpr int ASTR = 36, BSTR = BN + 8;
    constexpr int ASZ = BM * ASTR, BSZ = BK * BSTR;
    constexpr int STG = ASZ + 2 * BSZ;
    constexpr int MT = 2, NT = 4;     // WM=32, WN=32

    int zb = blockIdx.z;
    if (MPZ) M = Mptr[zb];
    int bm0 = blockIdx.x * BM;
    if (bm0 >= M) return;
    int bn0 = blockIdx.y * BN;

    const float* BA = ZSEL ? (zb == 0 ? Ba0 : (zb == 1 ? Ba1 : Ba2)) : Ba0 + (ll)zb * sBz;
    const float* BBp = ZSEL ? (zb == 0 ? Bb0 : (zb == 1 ? Bb1 : Bb2)) : Bb0 + (ll)zb * sBz;
    const float* biasA = ZSEL ? (zb == 0 ? ba0 : (zb == 1 ? ba1 : ba2)) : ba0 + (ll)zb * sBiasZ;
    const float* biasB = ZSEL ? (zb == 0 ? bb0 : (zb == 1 ? bb1 : bb2)) : bb0 + (ll)zb * sBiasZ;
    C += (ll)zb * sCz;
    if (GATHER && MPZ) tok += (ll)zb * TT;

    extern __shared__ float smf[];
    int* toks = (int*)(smf + 3 * STG);
    int tid = threadIdx.x;

    if (GATHER) {
        for (int i = tid; i < BM; i += NTH) {
            int gr = bm0 + i;
            toks[i] = (gr < M) ? tok[gr] : -1;
        }
        __syncthreads();
    }

    int wid = tid >> 5, lane = tid & 31;
    int wm = wid >> 2, wn = wid & 3;
    int lr = lane >> 2, lc = lane & 3;
    int jmat = lane >> 3, rrow = lane & 7;

    int aoff[MT];
#pragma unroll
    for (int mt = 0; mt < MT; mt++)
        aoff[mt] = (wm * 32 + mt * 16 + (jmat & 1) * 8 + rrow) * ASTR + (jmat >> 1) * 4;

    auto fill = [&](int st, int k0) {
        float* As = smf + st * STG;
        float* Bsa = As + ASZ;
        float* Bsb = Bsa + BSZ;
#pragma unroll
        for (int it = 0; it < 2; it++) {
            int i = it * NTH + tid;
            int row = i >> 3, c4 = i & 7;
            float* dst = As + row * ASTR + c4 * 4;
            const float* src;
            int sz = 16;
            if (GATHER) {
                int tk = toks[row];
                src = A + (ll)(tk < 0 ? 0 : tk) * lda + k0 + c4 * 4;
                if (tk < 0) sz = 0;
            } else {
                src = A + (ll)(bm0 + row) * lda + k0 + c4 * 4;
            }
            cpa16(dst, src, sz);
        }
        constexpr int RF4 = BN / 4;   // 32
#pragma unroll
        for (int it = 0; it < 2; it++) {
            int i = it * NTH + tid;
            int kk = i / RF4, c4 = i - kk * RF4;
            cpa16(Bsa + kk * BSTR + c4 * 4, BA  + (ll)(k0 + kk) * ldb + bn0 + c4 * 4, 16);
            cpa16(Bsb + kk * BSTR + c4 * 4, BBp + (ll)(k0 + kk) * ldb + bn0 + c4 * 4, 16);
        }
    };

    float4 accA[MT][NT], accB[MT][NT];
#pragma unroll
    for (int i = 0; i < MT; i++)
#pragma unroll
        for (int j = 0; j < NT; j++) {
            accA[i][j] = make_float4(0.f, 0.f, 0.f, 0.f);
            accB[i][j] = make_float4(0.f, 0.f, 0.f, 0.f);
        }

    int nIt = Kd / BK;
    fill(0, 0);
    asm volatile("cp.async.commit_group;\n");
    if (nIt > 1) {
        fill(1, BK);
        asm volatile("cp.async.commit_group;\n");
    }

    for (int itK = 0; itK < nIt; itK++) {
        if (itK + 1 < nIt) asm volatile("cp.async.wait_group 1;\n");
        else               asm volatile("cp.async.wait_group 0;\n");
        __syncthreads();
        const float* As = smf + (itK % 3) * STG;
        const float* Bsa = As + ASZ;
        const float* Bsb = Bsa + BSZ;
#pragma unroll
        for (int kt = 0; kt < KT; kt++) {
            uint32_t af[MT][4];
#pragma unroll
            for (int mt = 0; mt < MT; mt++)
                ldsm4(af[mt], As + aoff[mt] + kt * 8);
            uint32_t bfa[NT][2], bfb[NT][2];
#pragma unroll
            for (int nt = 0; nt < NT; nt++) {
                int off = (kt * 8 + lc) * BSTR + wn * 32 + nt * 8 + lr;
                bfa[nt][0] = __float_as_uint(Bsa[off]);
                bfa[nt][1] = __float_as_uint(Bsa[off + 4 * BSTR]);
                bfb[nt][0] = __float_as_uint(Bsb[off]);
                bfb[nt][1] = __float_as_uint(Bsb[off + 4 * BSTR]);
            }
#pragma unroll
            for (int mt = 0; mt < MT; mt++)
#pragma unroll
                for (int nt = 0; nt < NT; nt++) {
                    mma_tf32(accA[mt][nt], af[mt], bfa[nt]);
                    mma_tf32(accB[mt][nt], af[mt], bfb[nt]);
                }
        }
        if (itK + 2 < nIt) {
            fill((itK + 2) % 3, (itK + 2) * BK);
            asm volatile("cp.async.commit_group;\n");
        }
    }

#pragma unroll
    for (int mt = 0; mt < MT; mt++) {
        int r0 = bm0 + wm * 32 + mt * 16 + lr;
        int r1 = r0 + 8;
#pragma unroll
        for (int nt = 0; nt < NT; nt++) {
            int col = bn0 + wn * 32 + nt * 8 + lc * 2;
            float ba_ = biasA[col], ba1_ = biasA[col + 1];
            float bb_ = biasB[col], bb1_ = biasB[col + 1];
            if (r0 < M) {
                C[(ll)r0 * ldc + col]     = siluf(accA[mt][nt].x + ba_)  * (accB[mt][nt].x + bb_);
                C[(ll)r0 * ldc + col + 1] = siluf(accA[mt][nt].y + ba1_) * (accB[mt][nt].y + bb1_);
            }
            if (r1 < M) {
                C[(ll)r1 * ldc + col]     = siluf(accA[mt][nt].z + ba_)  * (accB[mt][nt].z + bb_);
                C[(ll)r1 * ldc + col + 1] = siluf(accA[mt][nt].w + ba1_) * (accB[mt][nt].w + bb1_);
            }
        }
    }
}

// ================= flash attention (tf32, V pre-transposed) =================
// 64-row Q tiles, 256 threads (8 warps, 4x2), 2 CTAs/SM. Ps aliases Qs.
#define QSTR 68
__global__ void __launch_bounds__(256, 2)
flash_k(const float* __restrict__ qg, const float* __restrict__ kg,
        const float* __restrict__ vtg, const int* __restrict__ maskp,
        float* __restrict__ ctx) {
    extern __shared__ float sm[];
    float* Qs = sm;                         // 64*68 (becomes Ps)
    float* Ks = sm + 64 * QSTR;             // 2 * 64*68
    float* Vs = Ks + 2 * 64 * QSTR;         // 2 * 64*68 (transposed: [dk][key])
    float* redM = Vs + 2 * 64 * QSTR;       // 128
    float* redL = redM + 128;               // 128
    float* Ps = Qs;

    int tid = threadIdx.x;
    int z = blockIdx.y;
    int b = z / HH, h = z % HH;
    int q0 = blockIdx.x * 64;
    int lane = tid & 31, wid = tid >> 5;
    int wm = wid >> 1, wn = wid & 1;
    int lr = lane >> 2, lc = lane & 3;
    int jmat = lane >> 3, rrow = lane & 7;

    const float* Qg = qg + ((ll)(b * SS + q0)) * DD + h * DK;
#pragma unroll
    for (int it = 0; it < 4; it++) {
        int i = it * 256 + tid;
        int row = i >> 4, c4 = i & 15;
        cpa16(Qs + row * QSTR + c4 * 4, Qg + (ll)row * DD + c4 * 4, 16);
    }
    asm volatile("cp.async.commit_group;\n");

    auto pf = [&](int i) {
        int st = i & 1;
        const float* Kg = kg + ((ll)(b * SS + i * 64)) * DD + h * DK;
        const float* Vg = vtg + ((ll)(b * DD + h * DK)) * SS + i * 64;
#pragma unroll
        for (int it = 0; it < 4; it++) {
            int j = it * 256 + tid;
            int row = j >> 4, c4 = j & 15;
            cpa16(Ks + st * 64 * QSTR + row * QSTR + c4 * 4, Kg + (ll)row * DD + c4 * 4, 16);
        }
#pragma unroll
        for (int it = 0; it < 4; it++) {
            int j = it * 256 + tid;
            int row = j >> 4, c4 = j & 15;    // row = dk, 64 keys = 16 chunks
            cpa16(Vs + st * 64 * QSTR + row * QSTR + c4 * 4, Vg + (ll)row * SS + c4 * 4, 16);
        }
    };
    pf(0);
    asm volatile("cp.async.commit_group;\n");

    // Q fragments (register resident)
    asm volatile("cp.async.wait_group 1;\n");
    __syncthreads();
    uint32_t qf[8][4];
    int aoffQ = (wm * 16 + (jmat & 1) * 8 + rrow) * QSTR + (jmat >> 1) * 4;
#pragma unroll
    for (int kt = 0; kt < 8; kt++) ldsm4(qf[kt], Qs + aoffQ + kt * 8);

    float4 oacc[4];
#pragma unroll
    for (int nt = 0; nt < 4; nt++) oacc[nt] = make_float4(0.f, 0.f, 0.f, 0.f);
    float m0 = -1e30f, m1 = -1e30f, l0 = 0.f, l1 = 0.f;
    int r0 = wm * 16 + lr, r1 = r0 + 8;
    int gq0 = q0 + r0, gq1 = q0 + r1;
    const int* mbase = maskp + (ll)b * SS * SS;

    constexpr int NIT = SS / 64;
    for (int i = 0; i < NIT; i++) {
        if (i + 1 < NIT) {
            pf(i + 1);
            asm volatile("cp.async.commit_group;\n");
            asm volatile("cp.async.wait_group 1;\n");
        } else {
            asm volatile("cp.async.wait_group 0;\n");
        }
        __syncthreads();
        const float* Kst = Ks + (i & 1) * 64 * QSTR;
        const float* Vst = Vs + (i & 1) * 64 * QSTR;

        // S = Q @ K^T
        float4 s[4];
#pragma unroll
        for (int nt = 0; nt < 4; nt++) s[nt] = make_float4(0.f, 0.f, 0.f, 0.f);
#pragma unroll
        for (int kt = 0; kt < 8; kt++) {
            uint32_t bf[4][2];
#pragma unroll
            for (int p = 0; p < 2; p++) {
                uint32_t t4[4];
                ldsm4(t4, Kst + (wn * 32 + p * 16 + (jmat >> 1) * 8 + rrow) * QSTR
                          + (jmat & 1) * 4 + kt * 8);
                bf[2 * p][0] = t4[0]; bf[2 * p][1] = t4[1];
                bf[2 * p + 1][0] = t4[2]; bf[2 * p + 1][1] = t4[3];
            }
#pragma unroll
            for (int nt = 0; nt < 4; nt++) mma_tf32(s[nt], qf[kt], bf[nt]);
        }
        // scale + mask (int2 vector loads)
#pragma unroll
        for (int nt = 0; nt < 4; nt++) {
            int gk = i * 64 + wn * 32 + nt * 8 + lc * 2;
            int2 mr0 = *(const int2*)(mbase + (ll)gq0 * SS + gk);
            int2 mr1 = *(const int2*)(mbase + (ll)gq1 * SS + gk);
            s[nt].x = mr0.x ? s[nt].x * 0.125f : -1e9f;
            s[nt].y = mr0.y ? s[nt].y * 0.125f : -1e9f;
            s[nt].z = mr1.x ? s[nt].z * 0.125f : -1e9f;
            s[nt].w = mr1.y ? s[nt].w * 0.125f : -1e9f;
        }
        // row max (warp partial + cross-warp via smem)
        float mx0 = -1e30f, mx1 = -1e30f;
#pragma unroll
        for (int nt = 0; nt < 4; nt++) {
            mx0 = fmaxf(mx0, fmaxf(s[nt].x, s[nt].y));
            mx1 = fmaxf(mx1, fmaxf(s[nt].z, s[nt].w));
        }
#pragma unroll
        for (int o = 1; o <= 2; o <<= 1) {
            mx0 = fmaxf(mx0, __shfl_xor_sync(0xffffffff, mx0, o));
            mx1 = fmaxf(mx1, __shfl_xor_sync(0xffffffff, mx1, o));
        }
        if (lc == 0) { redM[r0 * 2 + wn] = mx0; redM[r1 * 2 + wn] = mx1; }
        __syncthreads();
        float nm0 = fmaxf(m0, fmaxf(redM[r0 * 2], redM[r0 * 2 + 1]));
        float nm1 = fmaxf(m1, fmaxf(redM[r1 * 2], redM[r1 * 2 + 1]));
        float sc0 = __expf(m0 - nm0), sc1 = __expf(m1 - nm1);
        m0 = nm0; m1 = nm1;
        // exp + store P + partial sums
        float su0 = 0.f, su1 = 0.f;
#pragma unroll
        for (int nt = 0; nt < 4; nt++) {
            int col = wn * 32 + nt * 8 + lc * 2;
            float e0 = __expf(s[nt].x - m0), e1 = __expf(s[nt].y - m0);
            float e2 = __expf(s[nt].z - m1), e3 = __expf(s[nt].w - m1);
            su0 += e0 + e1; su1 += e2 + e3;
            Ps[r0 * QSTR + col] = e0; Ps[r0 * QSTR + col + 1] = e1;
            Ps[r1 * QSTR + col] = e2; Ps[r1 * QSTR + col + 1] = e3;
        }
#pragma unroll
        for (int o = 1; o <= 2; o <<= 1) {
            su0 += __shfl_xor_sync(0xffffffff, su0, o);
            su1 += __shfl_xor_sync(0xffffffff, su1, o);
        }
        if (lc == 0) { redL[r0 * 2 + wn] = su0; redL[r1 * 2 + wn] = su1; }
        __syncthreads();
        l0 = l0 * sc0 + redL[r0 * 2] + redL[r0 * 2 + 1];
        l1 = l1 * sc1 + redL[r1 * 2] + redL[r1 * 2 + 1];
#pragma unroll
        for (int nt = 0; nt < 4; nt++) {
            oacc[nt].x *= sc0; oacc[nt].y *= sc0;
            oacc[nt].z *= sc1; oacc[nt].w *= sc1;
        }
        // O += P @ V   (V transposed in smem -> ldmatrix B fragments)
        int aoffP = (wm * 16 + (jmat & 1) * 8 + rrow) * QSTR + (jmat >> 1) * 4;
#pragma unroll
        for (int kt = 0; kt < 8; kt++) {
            uint32_t af[4];
            ldsm4(af, Ps + aoffP + kt * 8);
            uint32_t bf[4][2];
#pragma unroll
            for (int p = 0; p < 2; p++) {
                uint32_t t4[4];
                ldsm4(t4, Vst + (wn * 32 + p * 16 + (jmat >> 1) * 8 + rrow) * QSTR
                          + (jmat & 1) * 4 + kt * 8);
                bf[2 * p][0] = t4[0]; bf[2 * p][1] = t4[1];
                bf[2 * p + 1][0] = t4[2]; bf[2 * p + 1][1] = t4[3];
            }
#pragma unroll
            for (int nt = 0; nt < 4; nt++) mma_tf32(oacc[nt], af, bf[nt]);
        }
        __syncthreads();
    }

    float inv0 = 1.f / l0, inv1 = 1.f / l1;
    float* cg = ctx + ((ll)(b * SS + q0)) * DD + h * DK;
#pragma unroll
    for (int nt = 0; nt < 4; nt++) {
        int col = wn * 32 + nt * 8 + lc * 2;
        cg[(ll)r0 * DD + col]     = oacc[nt].x * inv0;
        cg[(ll)r0 * DD + col + 1] = oacc[nt].y * inv0;
        cg[(ll)r1 * DD + col]     = oacc[nt].z * inv1;
        cg[(ll)r1 * DD + col + 1] = oacc[nt].w * inv1;
    }
}

// ---------------- gate + routing ----------------
__global__ void zero_counts_k(int* counts) {
    if (threadIdx.x < EE) counts[threadIdx.x] = 0;
}
__global__ void gate_route_k(const float* __restrict__ x2, const float* __restrict__ gw,
                             const float* __restrict__ gb, int* counts, int* etok,
                             int* texp, int* tslot, float* tw) {
    int t = blockIdx.x;
    __shared__ float xs[DD];
    __shared__ float logits[EE];
    const float* row = x2 + (ll)t * DD;
    for (int i = threadIdx.x; i < DD; i += 256) xs[i] = row[i];
    __syncthreads();
    int w = threadIdx.x / 32, lane = threadIdx.x % 32;
    float s = 0.f;
    for (int d = lane; d < DD; d += 32) s += xs[d] * gw[d * EE + w];
    for (int o = 16; o; o >>= 1) s += __shfl_xor_sync(0xffffffff, s, o);
    if (lane == 0) logits[w] = s + gb[w];
    __syncthreads();
    if (threadIdx.x == 0) {
        float p[EE];
        float m = -1e30f;
        for (int e = 0; e < EE; e++) m = fmaxf(m, logits[e]);
        float sum = 0.f;
        for (int e = 0; e < EE; e++) { p[e] = __expf(logits[e] - m); sum += p[e]; }
        for (int e = 0; e < EE; e++) p[e] /= sum;
        int i0 = 0;
        for (int e = 1; e < EE; e++) if (p[e] > p[i0]) i0 = e;
        int i1 = -1;
        for (int e = 0; e < EE; e++) {
            if (e == i0) continue;
            if (i1 < 0 || p[e] > p[i1]) i1 = e;
        }
        float denom = p[i0] + p[i1] + 1e-6f;
        int s0 = atomicAdd(&counts[i0], 1);
        int s1 = atomicAdd(&counts[i1], 1);
        etok[i0 * TT + s0] = t;
        etok[i1 * TT + s1] = t;
        texp[t * 2] = i0; texp[t * 2 + 1] = i1;
        tslot[t * 2] = s0; tslot[t * 2 + 1] = s1;
        tw[t * 2] = p[i0] / denom; tw[t * 2 + 1] = p[i1] / denom;
    }
}

// ---------------- final combine ----------------
__global__ void combine_k(const float* __restrict__ xres, const int* __restrict__ texp,
                          const int* __restrict__ tslot, const float* __restrict__ tw,
                          const float* __restrict__ moe, float* __restrict__ out) {
    int t = blockIdx.x;
    int e0 = texp[t * 2], e1 = texp[t * 2 + 1];
    int s0 = tslot[t * 2], s1 = tslot[t * 2 + 1];
    float w0 = tw[t * 2], w1 = tw[t * 2 + 1];
    const float* m0 = moe + ((size_t)e0 * TT + s0) * DD;
    const float* m1 = moe + ((size_t)e1 * TT + s1) * DD;
    const float* xr = xres + (ll)t * DD;
    float* o = out + (ll)t * DD;
    for (int i = threadIdx.x; i < DD; i += 256)
        o[i] = xr[i] + w0 * m0[i] + w1 * m1[i];
}

// ---------------- host side ----------------
static float* devPtrF(const void* sym) {
    void* p = nullptr;
    cudaGetSymbolAddress(&p, sym);
    return (float*)p;
}
static int* devPtrI(const void* sym) {
    void* p = nullptr;
    cudaGetSymbolAddress(&p, sym);
    return (int*)p;
}

extern "C" void kernel_launch(void* const* d_in, const int* in_sizes, int n_in,
                              void* d_out, int out_size) {
    const float* x    = (const float*)d_in[0];
    const int*   mask = (const int*)  d_in[1];
    const float* wq1 = (const float*)d_in[2];  const float* bq1 = (const float*)d_in[3];
    const float* wq2 = (const float*)d_in[4];  const float* bq2 = (const float*)d_in[5];
    const float* wk1 = (const float*)d_in[6];  const float* bk1 = (const float*)d_in[7];
    const float* wk2 = (const float*)d_in[8];  const float* bk2 = (const float*)d_in[9];
    const float* wv1 = (const float*)d_in[10]; const float* bv1 = (const float*)d_in[11];
    const float* wv2 = (const float*)d_in[12]; const float* bv2 = (const float*)d_in[13];
    const float* wo  = (const float*)d_in[14]; const float* bo  = (const float*)d_in[15];
    const float* ln1g = (const float*)d_in[16]; const float* ln1b = (const float*)d_in[17];
    const float* ln2g = (const float*)d_in[18]; const float* ln2b = (const float*)d_in[19];
    const float* gw  = (const float*)d_in[20]; const float* gb  = (const float*)d_in[21];
    const float* ew1 = (const float*)d_in[22]; const float* eb1 = (const float*)d_in[23];
    const float* ew2 = (const float*)d_in[24]; const float* eb2 = (const float*)d_in[25];
    const float* ew3 = (const float*)d_in[26]; const float* eb3 = (const float*)d_in[27];
    float* out = (float*)d_out;

    float* x2a  = devPtrF(g_x2a);
    float* qkv  = devPtrF(g_qkv);
    float* vt   = devPtrF(g_vt);
    float* ctx  = devPtrF(g_ctx);
    float* xres = devPtrF(g_xres);
    float* x2b  = devPtrF(g_x2b);
    float* emid = devPtrF(g_emid);
    float* moe  = devPtrF(g_moe);
    int* counts = devPtrI(g_counts);
    int* etok   = devPtrI(g_etok);
    int* texp   = devPtrI(g_texp);
    int* tslot  = devPtrI(g_tslot);
    float* tw   = devPtrF(g_tw);

    float* qb = qkv;
    float* kb = qkv + (ll)TT * DD;
    float* vb = qkv + 2ll * TT * DD;

    auto kDP = tcgd<0,1,0>;                   // dual proj (ZSEL)
    auto kDM = tcgd<1,0,1>;                   // dual MoE up (gather, per-z)
    auto kO1 = tcg<128,256,2,8,1,0,0>;        // oproj + residual
    auto kM2 = tcg<128,256,2,8,0,0,1>;        // moe down (per-z)

    int smD  = (3 * (128 * 36 + 2 * 32 * 136) + 128) * 4;   // dual gemm, 3-stage
    int smP  = (3 * (128 * 36 + 32 * (256 + 8))) * 4;       // 128x256 single, 3-stage
    int smFL = (64 * QSTR + 4 * 64 * QSTR + 256) * 4;       // flash 64-row
    cudaFuncSetAttribute(kDP, cudaFuncAttributeMaxDynamicSharedMemorySize, smD);
    cudaFuncSetAttribute(kDM, cudaFuncAttributeMaxDynamicSharedMemorySize, smD);
    cudaFuncSetAttribute(kO1, cudaFuncAttributeMaxDynamicSharedMemorySize, smP);
    cudaFuncSetAttribute(kM2, cudaFuncAttributeMaxDynamicSharedMemorySize, smP);
    cudaFuncSetAttribute(flash_k, cudaFuncAttributeMaxDynamicSharedMemorySize, smFL);

    // 1) LN1
    ln_k<<<TT, 256>>>(x, ln1g, ln1b, x2a);

    // 2) fused SwiGLU projections: one dual-GEMM launch, z selects (q,k,v)
    kDP<<<dim3(TT/128, DD/128, 3), 512, smD>>>(x2a, DD,
        wq1, wk1, wv1, wq2, wk2, wv2, DD, 0,
        bq1, bk1, bv1, bq2, bk2, bv2, 0,
        qkv, DD, (ll)TT * DD,
        TT, nullptr, DD, nullptr);

    // 2b) transpose V for flash
    vtrans_k<<<dim3(SS/32, DD/32, BB), dim3(32, 8)>>>(vb, vt);

    // 3+4) flash attention
    flash_k<<<dim3(SS / 64, BB * HH), 256, smFL>>>(qb, kb, vt, mask, ctx);

    // 5) out proj + residual
    kO1<<<dim3(TT/128, DD/256, 1), 512, smP>>>(ctx, DD, 0,
        wo, DD, 0, bo, 0, x,
        xres, DD, 0,
        TT, nullptr, DD, nullptr);

    // 6) LN2
    ln_k<<<TT, 256>>>(xres, ln2g, ln2b, x2b);

    // 7) gate + routing
    zero_counts_k<<<1, 32>>>(counts);
    gate_route_k<<<TT, 256>>>(x2b, gw, gb, counts, etok, texp, tslot, tw);

    // 8) MoE: dual up-proj (1 launch) + down-proj (1 launch), z = expert
    kDM<<<dim3(TT/128, FF/128, EE), 512, smD>>>(x2b, DD,
        ew1, nullptr, nullptr, ew3, nullptr, nullptr, FF, (ll)DD * FF,
        eb1, nullptr, nullptr, eb3, nullptr, nullptr, FF,
        emid, FF, (ll)TT * FF,
        0, counts, DD, etok);
    kM2<<<dim3(TT/128, DD/256, EE), 512, smP>>>(emid, FF, (ll)TT * FF,
        ew2, DD, (ll)FF * DD, eb2, DD, nullptr,
        moe, DD, (ll)TT * DD,
        0, counts, FF, nullptr);

    // 9) combine
    combine_k<<<TT, 256>>>(xres, texp, tslot, tw, moe, out);
}

// round 9
// speedup vs baseline: 16.3280x; 1.0625x over previous
#include <cuda_runtime.h>
#include <cuda_bf16.h>
#include <math.h>
#include <stdint.h>

// Problem dims
#define BB 4
#define SS 1024
#define DD 1024
#define FF 2048
#define HH 16
#define EE 8
#define DK 64
#define TT (BB*SS)          // 4096 tokens
typedef long long ll;

// ---------------- static device scratch ----------------
__device__ float g_x2a[TT*DD];
__device__ float g_qkv[3*TT*DD];                // q,k slices (v slice unused)
__device__ float g_vt[TT*DD];                   // V transposed per (b): [b*DD+hd][s]
__device__ float g_ctx[TT*DD];
__device__ float g_xres[TT*DD];
__device__ float g_x2b[TT*DD];
__device__ float g_emid[(size_t)EE*TT*FF];      // MoE mid
__device__ float g_moe[(size_t)EE*TT*DD];
__device__ unsigned g_mb[(size_t)TT*32];        // bitpacked mask: row*32 words
__device__ int   g_counts[EE];
__device__ int   g_etok[EE*TT];
__device__ int   g_texp[TT*2];
__device__ int   g_tslot[TT*2];
__device__ float g_tw[TT*2];

// ---------------- helpers ----------------
__device__ __forceinline__ float blockReduceSum(float v, float* sh) {
    int tid = threadIdx.x;
    sh[tid] = v; __syncthreads();
    for (int s = 128; s > 0; s >>= 1) {
        if (tid < s) sh[tid] += sh[tid + s];
        __syncthreads();
    }
    float r = sh[0]; __syncthreads();
    return r;
}
__device__ __forceinline__ void mma_tf32(float4& d, const uint32_t* a, const uint32_t* b) {
    asm volatile(
        "mma.sync.aligned.m16n8k8.row.col.f32.tf32.tf32.f32 "
        "{%0,%1,%2,%3}, {%4,%5,%6,%7}, {%8,%9}, {%0,%1,%2,%3};"
        : "+f"(d.x), "+f"(d.y), "+f"(d.z), "+f"(d.w)
        : "r"(a[0]), "r"(a[1]), "r"(a[2]), "r"(a[3]), "r"(b[0]), "r"(b[1]));
}
__device__ __forceinline__ void cpa16(float* dst, const float* src, int sz) {
    uint32_t d = (uint32_t)__cvta_generic_to_shared(dst);
    asm volatile("cp.async.cg.shared.global [%0], [%1], 16, %2;\n"
                 :: "r"(d), "l"(src), "r"(sz));
}
__device__ __forceinline__ void ldsm4(uint32_t* d, const float* p) {
    uint32_t a = (uint32_t)__cvta_generic_to_shared(p);
    asm volatile("ldmatrix.sync.aligned.m8n8.x4.shared.b16 {%0,%1,%2,%3}, [%4];"
                 : "=r"(d[0]), "=r"(d[1]), "=r"(d[2]), "=r"(d[3]) : "r"(a));
}
__device__ __forceinline__ float siluf(float x) {
    return x / (1.f + __expf(-x));
}

// ---------------- LayerNorm ----------------
__global__ void ln_k(const float* __restrict__ x, const float* __restrict__ g,
                     const float* __restrict__ b, float* __restrict__ out) {
    __shared__ float sh[256];
    int r = blockIdx.x;
    const float* row = x + (size_t)r * DD;
    float s = 0.f;
    for (int i = threadIdx.x; i < DD; i += 256) s += row[i];
    float mean = blockReduceSum(s, sh) * (1.0f / DD);
    float v = 0.f;
    for (int i = threadIdx.x; i < DD; i += 256) {
        float d = row[i] - mean; v += d * d;
    }
    float var = blockReduceSum(v, sh) * (1.0f / DD);
    float inv = rsqrtf(var + 1e-5f);
    float* o = out + (size_t)r * DD;
    for (int i = threadIdx.x; i < DD; i += 256)
        o[i] = (row[i] - mean) * inv * g[i] + b[i];
}

// ---------------- mask bitpack: 8 rows/block, ballot per 32 keys ----------------
__global__ void packmask_k(const int* __restrict__ mask, unsigned* __restrict__ mb) {
    int wid = threadIdx.x >> 5, lane = threadIdx.x & 31;
    ll row = (ll)blockIdx.x * 8 + wid;           // row = b*SS + q
    const int* mrow = mask + row * SS;
#pragma unroll
    for (int w = 0; w < 32; w++) {
        unsigned word = __ballot_sync(0xffffffff, mrow[w * 32 + lane] != 0);
        if (lane == 0) mb[row * 32 + w] = word;
    }
}

// ================= 3-stage pipelined tensor-core tf32 GEMM (single) =================
template<int BM, int BN, int WGM, int WGN, int EPI, int GATHER, int MPZ>
__global__ void __launch_bounds__(WGM*WGN*32)
tcg(const float* __restrict__ A, int lda, ll sAz,
    const float* __restrict__ B0, int ldb, ll sBz,
    const float* __restrict__ bias0, ll sBiasZ,
    const float* __restrict__ S,
    float* __restrict__ C, int ldc, ll sCz,
    int M, const int* __restrict__ Mptr, int Kd,
    const int* __restrict__ tok) {
    constexpr int NTH = WGM * WGN * 32;
    constexpr int BK = 32;
    constexpr int KT = 4;
    constexpr int ASTR = 36;
    constexpr int BSTR = BN + 8;
    constexpr int ASZ = BM * ASTR;
    constexpr int BSZ = BK * BSTR;
    constexpr int STG = ASZ + BSZ;
    constexpr int WM = BM / WGM;
    constexpr int WN = BN / WGN;
    constexpr int MT = WM / 16;
    constexpr int NT = WN / 8;

    int zb = blockIdx.z;
    if (MPZ) M = Mptr[zb];
    else if (Mptr) M = *Mptr;
    int bm0 = blockIdx.x * BM;
    if (bm0 >= M) return;
    int bn0 = blockIdx.y * BN;

    const float* Bm = B0 + (ll)zb * sBz;
    const float* bias = bias0 ? bias0 + (ll)zb * sBiasZ : nullptr;
    A += (ll)zb * sAz;
    C += (ll)zb * sCz;
    if (GATHER && MPZ) tok += (ll)zb * TT;

    extern __shared__ float smf[];
    int* toks = (int*)(smf + 3 * STG);
    int tid = threadIdx.x;

    if (GATHER) {
        for (int i = tid; i < BM; i += NTH) {
            int gr = bm0 + i;
            toks[i] = (gr < M) ? tok[gr] : -1;
        }
        __syncthreads();
    }

    int wid = tid >> 5, lane = tid & 31;
    int wm = wid / WGN, wn = wid - wm * WGN;
    int lr = lane >> 2, lc = lane & 3;
    int jmat = lane >> 3, rrow = lane & 7;

    int aoff[MT];
#pragma unroll
    for (int mt = 0; mt < MT; mt++)
        aoff[mt] = (wm * WM + mt * 16 + (jmat & 1) * 8 + rrow) * ASTR + (jmat >> 1) * 4;

    auto fill = [&](int st, int k0) {
        float* As = smf + st * STG;
        float* Bs = As + ASZ;
#pragma unroll
        for (int it = 0; it < BM * 8 / NTH; it++) {
            int i = it * NTH + tid;
            int row = i >> 3, c4 = i & 7;
            float* dst = As + row * ASTR + c4 * 4;
            const float* src;
            int sz = 16;
            if (GATHER) {
                int tk = toks[row];
                src = A + (ll)(tk < 0 ? 0 : tk) * lda + k0 + c4 * 4;
                if (tk < 0) sz = 0;
            } else {
                src = A + (ll)(bm0 + row) * lda + k0 + c4 * 4;
            }
            cpa16(dst, src, sz);
        }
        constexpr int RF4 = BN / 4;
#pragma unroll
        for (int it = 0; it < BK * RF4 / NTH; it++) {
            int i = it * NTH + tid;
            int kk = i / RF4, c4 = i - kk * RF4;
            cpa16(Bs + kk * BSTR + c4 * 4,
                  Bm + (ll)(k0 + kk) * ldb + bn0 + c4 * 4, 16);
        }
    };

    float4 acc[MT][NT];
#pragma unroll
    for (int i = 0; i < MT; i++)
#pragma unroll
        for (int j = 0; j < NT; j++) acc[i][j] = make_float4(0.f, 0.f, 0.f, 0.f);

    int nIt = Kd / BK;
    fill(0, 0);
    asm volatile("cp.async.commit_group;\n");
    if (nIt > 1) {
        fill(1, BK);
        asm volatile("cp.async.commit_group;\n");
    }

    for (int itK = 0; itK < nIt; itK++) {
        if (itK + 1 < nIt) asm volatile("cp.async.wait_group 1;\n");
        else               asm volatile("cp.async.wait_group 0;\n");
        __syncthreads();
        const float* As = smf + (itK % 3) * STG;
        const float* Bs = As + ASZ;
#pragma unroll
        for (int kt = 0; kt < KT; kt++) {
            uint32_t af[MT][4];
            uint32_t bf[NT][2];
#pragma unroll
            for (int mt = 0; mt < MT; mt++)
                ldsm4(af[mt], As + aoff[mt] + kt * 8);
#pragma unroll
            for (int nt = 0; nt < NT; nt++) {
                const float* bp = Bs + (kt * 8 + lc) * BSTR + wn * WN + nt * 8 + lr;
                bf[nt][0] = __float_as_uint(bp[0]);
                bf[nt][1] = __float_as_uint(bp[4 * BSTR]);
            }
#pragma unroll
            for (int mt = 0; mt < MT; mt++)
#pragma unroll
                for (int nt = 0; nt < NT; nt++)
                    mma_tf32(acc[mt][nt], af[mt], bf[nt]);
        }
        if (itK + 2 < nIt) {
            fill((itK + 2) % 3, (itK + 2) * BK);
            asm volatile("cp.async.commit_group;\n");
        }
    }

#pragma unroll
    for (int mt = 0; mt < MT; mt++) {
        int r0 = bm0 + wm * WM + mt * 16 + lr;
        int r1 = r0 + 8;
#pragma unroll
        for (int nt = 0; nt < NT; nt++) {
            int col = bn0 + wn * WN + nt * 8 + lc * 2;
            float v0 = acc[mt][nt].x, v1 = acc[mt][nt].y;
            float v2 = acc[mt][nt].z, v3 = acc[mt][nt].w;
            if (bias) {
                float b0 = bias[col], b1 = bias[col + 1];
                v0 += b0; v1 += b1; v2 += b0; v3 += b1;
            }
            if (EPI == 1) {
                if (r0 < M) {
                    v0 += S[(ll)r0 * ldc + col];
                    v1 += S[(ll)r0 * ldc + col + 1];
                }
                if (r1 < M) {
                    v2 += S[(ll)r1 * ldc + col];
                    v3 += S[(ll)r1 * ldc + col + 1];
                }
            }
            if (r0 < M) {
                C[(ll)r0 * ldc + col] = v0;
                C[(ll)r0 * ldc + col + 1] = v1;
            }
            if (r1 < M) {
                C[(ll)r1 * ldc + col] = v2;
                C[(ll)r1 * ldc + col + 1] = v3;
            }
        }
    }
}

// ================= dual tf32 GEMM: out = silu(A@Wa+ba) * (A@Wb+bb) =================
// BM=64, BN=128, 8 warps (2x4), 256 threads, 2-stage, 2 CTAs/SM.
// VT: for zb==2 write result transposed into vtout[(b*DD+col)*SS+s].
template<int GATHER, int ZSEL, int MPZ, int VT>
__global__ void __launch_bounds__(256, 2)
tcgd(const float* __restrict__ A, int lda,
     const float* __restrict__ Ba0, const float* __restrict__ Ba1, const float* __restrict__ Ba2,
     const float* __restrict__ Bb0, const float* __restrict__ Bb1, const float* __restrict__ Bb2,
     int ldb, ll sBz,
     const float* __restrict__ ba0, const float* __restrict__ ba1, const float* __restrict__ ba2,
     const float* __restrict__ bb0, const float* __restrict__ bb1, const float* __restrict__ bb2,
     ll sBiasZ,
     float* __restrict__ C, int ldc, ll sCz,
     float* __restrict__ vtout,
     int M, const int* __restrict__ Mptr, int Kd,
     const int* __restrict__ tok) {
    constexpr int NTH = 256;
    constexpr int BM = 64, BN = 128, BK = 32, KT = 4;
    constexpr int ASTR = 36, BSTR = BN + 8;
    constexpr int ASZ = BM * ASTR, BSZ = BK * BSTR;
    constexpr int STG = ASZ + 2 * BSZ;
    constexpr int MT = 2, NT = 4;     // WM=32, WN=32

    int zb = blockIdx.z;
    if (MPZ) M = Mptr[zb];
    int bm0 = blockIdx.x * BM;
    if (bm0 >= M) return;
    int bn0 = blockIdx.y * BN;

    const float* BA = ZSEL ? (zb == 0 ? Ba0 : (zb == 1 ? Ba1 : Ba2)) : Ba0 + (ll)zb * sBz;
    const float* BBp = ZSEL ? (zb == 0 ? Bb0 : (zb == 1 ? Bb1 : Bb2)) : Bb0 + (ll)zb * sBz;
    const float* biasA = ZSEL ? (zb == 0 ? ba0 : (zb == 1 ? ba1 : ba2)) : ba0 + (ll)zb * sBiasZ;
    const float* biasB = ZSEL ? (zb == 0 ? bb0 : (zb == 1 ? bb1 : bb2)) : bb0 + (ll)zb * sBiasZ;
    C += (ll)zb * sCz;
    if (GATHER && MPZ) tok += (ll)zb * TT;

    extern __shared__ float smf[];
    int* toks = (int*)(smf + 2 * STG);
    int tid = threadIdx.x;

    if (GATHER) {
        for (int i = tid; i < BM; i += NTH) {
            int gr = bm0 + i;
            toks[i] = (gr < M) ? tok[gr] : -1;
        }
        __syncthreads();
    }

    int wid = tid >> 5, lane = tid & 31;
    int wm = wid >> 2, wn = wid & 3;
    int lr = lane >> 2, lc = lane & 3;
    int jmat = lane >> 3, rrow = lane & 7;

    int aoff[MT];
#pragma unroll
    for (int mt = 0; mt < MT; mt++)
        aoff[mt] = (wm * 32 + mt * 16 + (jmat & 1) * 8 + rrow) * ASTR + (jmat >> 1) * 4;

    auto fill = [&](int st, int k0) {
        float* As = smf + st * STG;
        float* Bsa = As + ASZ;
        float* Bsb = Bsa + BSZ;
#pragma unroll
        for (int it = 0; it < BM * 8 / NTH; it++) {
            int i = it * NTH + tid;
            int row = i >> 3, c4 = i & 7;
            float* dst = As + row * ASTR + c4 * 4;
            const float* src;
            int sz = 16;
            if (GATHER) {
                int tk = toks[row];
                src = A + (ll)(tk < 0 ? 0 : tk) * lda + k0 + c4 * 4;
                if (tk < 0) sz = 0;
            } else {
                src = A + (ll)(bm0 + row) * lda + k0 + c4 * 4;
            }
            cpa16(dst, src, sz);
        }
        constexpr int RF4 = BN / 4;   // 32
#pragma unroll
        for (int it = 0; it < BK * RF4 / NTH; it++) {
            int i = it * NTH + tid;
            int kk = i / RF4, c4 = i - kk * RF4;
            cpa16(Bsa + kk * BSTR + c4 * 4, BA  + (ll)(k0 + kk) * ldb + bn0 + c4 * 4, 16);
            cpa16(Bsb + kk * BSTR + c4 * 4, BBp + (ll)(k0 + kk) * ldb + bn0 + c4 * 4, 16);
        }
    };

    float4 accA[MT][NT], accB[MT][NT];
#pragma unroll
    for (int i = 0; i < MT; i++)
#pragma unroll
        for (int j = 0; j < NT; j++) {
            accA[i][j] = make_float4(0.f, 0.f, 0.f, 0.f);
            accB[i][j] = make_float4(0.f, 0.f, 0.f, 0.f);
        }

    int nIt = Kd / BK;
    fill(0, 0);
    asm volatile("cp.async.commit_group;\n");

    for (int itK = 0; itK < nIt; itK++) {
        if (itK + 1 < nIt) {
            fill((itK + 1) & 1, (itK + 1) * BK);
            asm volatile("cp.async.commit_group;\n");
            asm volatile("cp.async.wait_group 1;\n");
        } else {
            asm volatile("cp.async.wait_group 0;\n");
        }
        __syncthreads();
        const float* As = smf + (itK & 1) * STG;
        const float* Bsa = As + ASZ;
        const float* Bsb = Bsa + BSZ;
#pragma unroll
        for (int kt = 0; kt < KT; kt++) {
            uint32_t af[MT][4];
#pragma unroll
            for (int mt = 0; mt < MT; mt++)
                ldsm4(af[mt], As + aoff[mt] + kt * 8);
            uint32_t bfa[NT][2], bfb[NT][2];
#pragma unroll
            for (int nt = 0; nt < NT; nt++) {
                int off = (kt * 8 + lc) * BSTR + wn * 32 + nt * 8 + lr;
                bfa[nt][0] = __float_as_uint(Bsa[off]);
                bfa[nt][1] = __float_as_uint(Bsa[off + 4 * BSTR]);
                bfb[nt][0] = __float_as_uint(Bsb[off]);
                bfb[nt][1] = __float_as_uint(Bsb[off + 4 * BSTR]);
            }
#pragma unroll
            for (int mt = 0; mt < MT; mt++)
#pragma unroll
                for (int nt = 0; nt < NT; nt++) {
                    mma_tf32(accA[mt][nt], af[mt], bfa[nt]);
                    mma_tf32(accB[mt][nt], af[mt], bfb[nt]);
                }
        }
        __syncthreads();
    }

#pragma unroll
    for (int mt = 0; mt < MT; mt++) {
        int r0 = bm0 + wm * 32 + mt * 16 + lr;
        int r1 = r0 + 8;
#pragma unroll
        for (int nt = 0; nt < NT; nt++) {
            int col = bn0 + wn * 32 + nt * 8 + lc * 2;
            float ba_ = biasA[col], ba1_ = biasA[col + 1];
            float bb_ = biasB[col], bb1_ = biasB[col + 1];
            float o0 = siluf(accA[mt][nt].x + ba_)  * (accB[mt][nt].x + bb_);
            float o1 = siluf(accA[mt][nt].y + ba1_) * (accB[mt][nt].y + bb1_);
            float o2 = siluf(accA[mt][nt].z + ba_)  * (accB[mt][nt].z + bb_);
            float o3 = siluf(accA[mt][nt].w + ba1_) * (accB[mt][nt].w + bb1_);
            if (VT && zb == 2) {
                int b0 = r0 >> 10, s0 = r0 & 1023;
                int b1 = r1 >> 10, s1 = r1 & 1023;
                vtout[((ll)(b0 * DD + col))     * SS + s0] = o0;
                vtout[((ll)(b0 * DD + col + 1)) * SS + s0] = o1;
                vtout[((ll)(b1 * DD + col))     * SS + s1] = o2;
                vtout[((ll)(b1 * DD + col + 1)) * SS + s1] = o3;
            } else {
                if (r0 < M) {
                    C[(ll)r0 * ldc + col]     = o0;
                    C[(ll)r0 * ldc + col + 1] = o1;
                }
                if (r1 < M) {
                    C[(ll)r1 * ldc + col]     = o2;
                    C[(ll)r1 * ldc + col + 1] = o3;
                }
            }
        }
    }
}

// ================= flash attention (tf32, V pre-transposed, bitmask) =================
// 64-row Q tiles, 256 threads (8 warps, 4x2), 2 CTAs/SM. Ps aliases Qs.
#define QSTR 68
__global__ void __launch_bounds__(256, 2)
flash_k(const float* __restrict__ qg, const float* __restrict__ kg,
        const float* __restrict__ vtg, const unsigned* __restrict__ mb,
        float* __restrict__ ctx) {
    extern __shared__ float sm[];
    float* Qs = sm;                         // 64*68 (becomes Ps)
    float* Ks = sm + 64 * QSTR;             // 2 * 64*68
    float* Vs = Ks + 2 * 64 * QSTR;         // 2 * 64*68 (transposed: [dk][key])
    float* redM = Vs + 2 * 64 * QSTR;       // 128
    float* redL = redM + 128;               // 128
    float* Ps = Qs;

    int tid = threadIdx.x;
    int z = blockIdx.y;
    int b = z / HH, h = z % HH;
    int q0 = blockIdx.x * 64;
    int lane = tid & 31, wid = tid >> 5;
    int wm = wid >> 1, wn = wid & 1;
    int lr = lane >> 2, lc = lane & 3;
    int jmat = lane >> 3, rrow = lane & 7;

    const float* Qg = qg + ((ll)(b * SS + q0)) * DD + h * DK;
#pragma unroll
    for (int it = 0; it < 4; it++) {
        int i = it * 256 + tid;
        int row = i >> 4, c4 = i & 15;
        cpa16(Qs + row * QSTR + c4 * 4, Qg + (ll)row * DD + c4 * 4, 16);
    }
    asm volatile("cp.async.commit_group;\n");

    auto pf = [&](int i) {
        int st = i & 1;
        const float* Kg = kg + ((ll)(b * SS + i * 64)) * DD + h * DK;
        const float* Vg = vtg + ((ll)(b * DD + h * DK)) * SS + i * 64;
#pragma unroll
        for (int it = 0; it < 4; it++) {
            int j = it * 256 + tid;
            int row = j >> 4, c4 = j & 15;
            cpa16(Ks + st * 64 * QSTR + row * QSTR + c4 * 4, Kg + (ll)row * DD + c4 * 4, 16);
        }
#pragma unroll
        for (int it = 0; it < 4; it++) {
            int j = it * 256 + tid;
            int row = j >> 4, c4 = j & 15;    // row = dk, 64 keys = 16 chunks
            cpa16(Vs + st * 64 * QSTR + row * QSTR + c4 * 4, Vg + (ll)row * SS + c4 * 4, 16);
        }
    };
    pf(0);
    asm volatile("cp.async.commit_group;\n");

    // Q fragments (register resident)
    asm volatile("cp.async.wait_group 1;\n");
    __syncthreads();
    uint32_t qf[8][4];
    int aoffQ = (wm * 16 + (jmat & 1) * 8 + rrow) * QSTR + (jmat >> 1) * 4;
#pragma unroll
    for (int kt = 0; kt < 8; kt++) ldsm4(qf[kt], Qs + aoffQ + kt * 8);

    float4 oacc[4];
#pragma unroll
    for (int nt = 0; nt < 4; nt++) oacc[nt] = make_float4(0.f, 0.f, 0.f, 0.f);
    float m0 = -1e30f, m1 = -1e30f, l0 = 0.f, l1 = 0.f;
    int r0 = wm * 16 + lr, r1 = r0 + 8;
    int gq0 = q0 + r0, gq1 = q0 + r1;
    const unsigned* mb0 = mb + ((ll)(b * SS + gq0)) * 32 + wn;
    const unsigned* mb1 = mb + ((ll)(b * SS + gq1)) * 32 + wn;

    constexpr int NIT = SS / 64;
    for (int i = 0; i < NIT; i++) {
        if (i + 1 < NIT) {
            pf(i + 1);
            asm volatile("cp.async.commit_group;\n");
            asm volatile("cp.async.wait_group 1;\n");
        } else {
            asm volatile("cp.async.wait_group 0;\n");
        }
        __syncthreads();
        const float* Kst = Ks + (i & 1) * 64 * QSTR;
        const float* Vst = Vs + (i & 1) * 64 * QSTR;

        // S = Q @ K^T
        float4 s[4];
#pragma unroll
        for (int nt = 0; nt < 4; nt++) s[nt] = make_float4(0.f, 0.f, 0.f, 0.f);
#pragma unroll
        for (int kt = 0; kt < 8; kt++) {
            uint32_t bf[4][2];
#pragma unroll
            for (int p = 0; p < 2; p++) {
                uint32_t t4[4];
                ldsm4(t4, Kst + (wn * 32 + p * 16 + (jmat >> 1) * 8 + rrow) * QSTR
                          + (jmat & 1) * 4 + kt * 8);
                bf[2 * p][0] = t4[0]; bf[2 * p][1] = t4[1];
                bf[2 * p + 1][0] = t4[2]; bf[2 * p + 1][1] = t4[3];
            }
#pragma unroll
            for (int nt = 0; nt < 4; nt++) mma_tf32(s[nt], qf[kt], bf[nt]);
        }
        // scale + bitmask
        unsigned w0 = mb0[i * 2];
        unsigned w1 = mb1[i * 2];
#pragma unroll
        for (int nt = 0; nt < 4; nt++) {
            int bitb = nt * 8 + lc * 2;
            s[nt].x = ((w0 >> bitb) & 1u)       ? s[nt].x * 0.125f : -1e9f;
            s[nt].y = ((w0 >> (bitb + 1)) & 1u) ? s[nt].y * 0.125f : -1e9f;
            s[nt].z = ((w1 >> bitb) & 1u)       ? s[nt].z * 0.125f : -1e9f;
            s[nt].w = ((w1 >> (bitb + 1)) & 1u) ? s[nt].w * 0.125f : -1e9f;
        }
        // row max (warp partial + cross-warp via smem)
        float mx0 = -1e30f, mx1 = -1e30f;
#pragma unroll
        for (int nt = 0; nt < 4; nt++) {
            mx0 = fmaxf(mx0, fmaxf(s[nt].x, s[nt].y));
            mx1 = fmaxf(mx1, fmaxf(s[nt].z, s[nt].w));
        }
#pragma unroll
        for (int o = 1; o <= 2; o <<= 1) {
            mx0 = fmaxf(mx0, __shfl_xor_sync(0xffffffff, mx0, o));
            mx1 = fmaxf(mx1, __shfl_xor_sync(0xffffffff, mx1, o));
        }
        if (lc == 0) { redM[r0 * 2 + wn] = mx0; redM[r1 * 2 + wn] = mx1; }
        __syncthreads();
        float nm0 = fmaxf(m0, fmaxf(redM[r0 * 2], redM[r0 * 2 + 1]));
        float nm1 = fmaxf(m1, fmaxf(redM[r1 * 2], redM[r1 * 2 + 1]));
        float sc0 = __expf(m0 - nm0), sc1 = __expf(m1 - nm1);
        m0 = nm0; m1 = nm1;
        // exp + store P + partial sums
        float su0 = 0.f, su1 = 0.f;
#pragma unroll
        for (int nt = 0; nt < 4; nt++) {
            int col = wn * 32 + nt * 8 + lc * 2;
            float e0 = __expf(s[nt].x - m0), e1 = __expf(s[nt].y - m0);
            float e2 = __expf(s[nt].z - m1), e3 = __expf(s[nt].w - m1);
            su0 += e0 + e1; su1 += e2 + e3;
            Ps[r0 * QSTR + col] = e0; Ps[r0 * QSTR + col + 1] = e1;
            Ps[r1 * QSTR + col] = e2; Ps[r1 * QSTR + col + 1] = e3;
        }
#pragma unroll
        for (int o = 1; o <= 2; o <<= 1) {
            su0 += __shfl_xor_sync(0xffffffff, su0, o);
            su1 += __shfl_xor_sync(0xffffffff, su1, o);
        }
        if (lc == 0) { redL[r0 * 2 + wn] = su0; redL[r1 * 2 + wn] = su1; }
        __syncthreads();
        l0 = l0 * sc0 + redL[r0 * 2] + redL[r0 * 2 + 1];
        l1 = l1 * sc1 + redL[r1 * 2] + redL[r1 * 2 + 1];
#pragma unroll
        for (int nt = 0; nt < 4; nt++) {
            oacc[nt].x *= sc0; oacc[nt].y *= sc0;
            oacc[nt].z *= sc1; oacc[nt].w *= sc1;
        }
        // O += P @ V   (V transposed in smem -> ldmatrix B fragments)
        int aoffP = (wm * 16 + (jmat & 1) * 8 + rrow) * QSTR + (jmat >> 1) * 4;
#pragma unroll
        for (int kt = 0; kt < 8; kt++) {
            uint32_t af[4];
            ldsm4(af, Ps + aoffP + kt * 8);
            uint32_t bf[4][2];
#pragma unroll
            for (int p = 0; p < 2; p++) {
                uint32_t t4[4];
                ldsm4(t4, Vst + (wn * 32 + p * 16 + (jmat >> 1) * 8 + rrow) * QSTR
                          + (jmat & 1) * 4 + kt * 8);
                bf[2 * p][0] = t4[0]; bf[2 * p][1] = t4[1];
                bf[2 * p + 1][0] = t4[2]; bf[2 * p + 1][1] = t4[3];
            }
#pragma unroll
            for (int nt = 0; nt < 4; nt++) mma_tf32(oacc[nt], af, bf[nt]);
        }
        __syncthreads();
    }

    float inv0 = 1.f / l0, inv1 = 1.f / l1;
    float* cg = ctx + ((ll)(b * SS + q0)) * DD + h * DK;
#pragma unroll
    for (int nt = 0; nt < 4; nt++) {
        int col = wn * 32 + nt * 8 + lc * 2;
        cg[(ll)r0 * DD + col]     = oacc[nt].x * inv0;
        cg[(ll)r0 * DD + col + 1] = oacc[nt].y * inv0;
        cg[(ll)r1 * DD + col]     = oacc[nt].z * inv1;
        cg[(ll)r1 * DD + col + 1] = oacc[nt].w * inv1;
    }
}

// ---------------- gate + routing ----------------
__global__ void zero_counts_k(int* counts) {
    if (threadIdx.x < EE) counts[threadIdx.x] = 0;
}
__global__ void gate_route_k(const float* __restrict__ x2, const float* __restrict__ gw,
                             const float* __restrict__ gb, int* counts, int* etok,
                             int* texp, int* tslot, float* tw) {
    int t = blockIdx.x;
    __shared__ float xs[DD];
    __shared__ float logits[EE];
    const float* row = x2 + (ll)t * DD;
    for (int i = threadIdx.x; i < DD; i += 256) xs[i] = row[i];
    __syncthreads();
    int w = threadIdx.x / 32, lane = threadIdx.x % 32;
    float s = 0.f;
    for (int d = lane; d < DD; d += 32) s += xs[d] * gw[d * EE + w];
    for (int o = 16; o; o >>= 1) s += __shfl_xor_sync(0xffffffff, s, o);
    if (lane == 0) logits[w] = s + gb[w];
    __syncthreads();
    if (threadIdx.x == 0) {
        float p[EE];
        float m = -1e30f;
        for (int e = 0; e < EE; e++) m = fmaxf(m, logits[e]);
        float sum = 0.f;
        for (int e = 0; e < EE; e++) { p[e] = __expf(logits[e] - m); sum += p[e]; }
        for (int e = 0; e < EE; e++) p[e] /= sum;
        int i0 = 0;
        for (int e = 1; e < EE; e++) if (p[e] > p[i0]) i0 = e;
        int i1 = -1;
        for (int e = 0; e < EE; e++) {
            if (e == i0) continue;
            if (i1 < 0 || p[e] > p[i1]) i1 = e;
        }
        float denom = p[i0] + p[i1] + 1e-6f;
        int s0 = atomicAdd(&counts[i0], 1);
        int s1 = atomicAdd(&counts[i1], 1);
        etok[i0 * TT + s0] = t;
        etok[i1 * TT + s1] = t;
        texp[t * 2] = i0; texp[t * 2 + 1] = i1;
        tslot[t * 2] = s0; tslot[t * 2 + 1] = s1;
        tw[t * 2] = p[i0] / denom; tw[t * 2 + 1] = p[i1] / denom;
    }
}

// ---------------- final combine ----------------
__global__ void combine_k(const float* __restrict__ xres, const int* __restrict__ texp,
                          const int* __restrict__ tslot, const float* __restrict__ tw,
                          const float* __restrict__ moe, float* __restrict__ out) {
    int t = blockIdx.x;
    int e0 = texp[t * 2], e1 = texp[t * 2 + 1];
    int s0 = tslot[t * 2], s1 = tslot[t * 2 + 1];
    float w0 = tw[t * 2], w1 = tw[t * 2 + 1];
    const float* m0 = moe + ((size_t)e0 * TT + s0) * DD;
    const float* m1 = moe + ((size_t)e1 * TT + s1) * DD;
    const float* xr = xres + (ll)t * DD;
    float* o = out + (ll)t * DD;
    for (int i = threadIdx.x; i < DD; i += 256)
        o[i] = xr[i] + w0 * m0[i] + w1 * m1[i];
}

// ---------------- host side ----------------
static float* devPtrF(const void* sym) {
    void* p = nullptr;
    cudaGetSymbolAddress(&p, sym);
    return (float*)p;
}
static int* devPtrI(const void* sym) {
    void* p = nullptr;
    cudaGetSymbolAddress(&p, sym);
    return (int*)p;
}

extern "C" void kernel_launch(void* const* d_in, const int* in_sizes, int n_in,
                              void* d_out, int out_size) {
    const float* x    = (const float*)d_in[0];
    const int*   mask = (const int*)  d_in[1];
    const float* wq1 = (const float*)d_in[2];  const float* bq1 = (const float*)d_in[3];
    const float* wq2 = (const float*)d_in[4];  const float* bq2 = (const float*)d_in[5];
    const float* wk1 = (const float*)d_in[6];  const float* bk1 = (const float*)d_in[7];
    const float* wk2 = (const float*)d_in[8];  const float* bk2 = (const float*)d_in[9];
    const float* wv1 = (const float*)d_in[10]; const float* bv1 = (const float*)d_in[11];
    const float* wv2 = (const float*)d_in[12]; const float* bv2 = (const float*)d_in[13];
    const float* wo  = (const float*)d_in[14]; const float* bo  = (const float*)d_in[15];
    const float* ln1g = (const float*)d_in[16]; const float* ln1b = (const float*)d_in[17];
    const float* ln2g = (const float*)d_in[18]; const float* ln2b = (const float*)d_in[19];
    const float* gw  = (const float*)d_in[20]; const float* gb  = (const float*)d_in[21];
    const float* ew1 = (const float*)d_in[22]; const float* eb1 = (const float*)d_in[23];
    const float* ew2 = (const float*)d_in[24]; const float* eb2 = (const float*)d_in[25];
    const float* ew3 = (const float*)d_in[26]; const float* eb3 = (const float*)d_in[27];
    float* out = (float*)d_out;

    float* x2a  = devPtrF(g_x2a);
    float* qkv  = devPtrF(g_qkv);
    float* vt   = devPtrF(g_vt);
    float* ctx  = devPtrF(g_ctx);
    float* xres = devPtrF(g_xres);
    float* x2b  = devPtrF(g_x2b);
    float* emid = devPtrF(g_emid);
    float* moe  = devPtrF(g_moe);
    unsigned* mb = (unsigned*)devPtrI(g_mb);
    int* counts = devPtrI(g_counts);
    int* etok   = devPtrI(g_etok);
    int* texp   = devPtrI(g_texp);
    int* tslot  = devPtrI(g_tslot);
    float* tw   = devPtrF(g_tw);

    float* qb = qkv;
    float* kb = qkv + (ll)TT * DD;

    auto kDP = tcgd<0,1,0,1>;                 // dual proj (ZSEL, VT for z==2)
    auto kDM = tcgd<1,0,1,0>;                 // dual MoE up (gather, per-z)
    auto kO1 = tcg<128,256,2,8,1,0,0>;        // oproj + residual
    auto kM2 = tcg<128,256,2,8,0,0,1>;        // moe down (per-z)

    int smD  = (2 * (64 * 36 + 2 * 32 * 136) + 64) * 4;     // dual gemm, 2-stage, BM=64
    int smP  = (3 * (128 * 36 + 32 * (256 + 8))) * 4;       // 128x256 single, 3-stage
    int smFL = (64 * QSTR + 4 * 64 * QSTR + 256) * 4;       // flash 64-row
    cudaFuncSetAttribute(kDP, cudaFuncAttributeMaxDynamicSharedMemorySize, smD);
    cudaFuncSetAttribute(kDM, cudaFuncAttributeMaxDynamicSharedMemorySize, smD);
    cudaFuncSetAttribute(kO1, cudaFuncAttributeMaxDynamicSharedMemorySize, smP);
    cudaFuncSetAttribute(kM2, cudaFuncAttributeMaxDynamicSharedMemorySize, smP);
    cudaFuncSetAttribute(flash_k, cudaFuncAttributeMaxDynamicSharedMemorySize, smFL);

    // 1) LN1 + mask bitpack
    ln_k<<<TT, 256>>>(x, ln1g, ln1b, x2a);
    packmask_k<<<TT / 8, 256>>>(mask, mb);

    // 2) fused SwiGLU projections: one dual-GEMM launch; z=2 writes V transposed
    kDP<<<dim3(TT/64, DD/128, 3), 256, smD>>>(x2a, DD,
        wq1, wk1, wv1, wq2, wk2, wv2, DD, 0,
        bq1, bk1, bv1, bq2, bk2, bv2, 0,
        qkv, DD, (ll)TT * DD, vt,
        TT, nullptr, DD, nullptr);

    // 3+4) flash attention
    flash_k<<<dim3(SS / 64, BB * HH), 256, smFL>>>(qb, kb, vt, mb, ctx);

    // 5) out proj + residual
    kO1<<<dim3(TT/128, DD/256, 1), 512, smP>>>(ctx, DD, 0,
        wo, DD, 0, bo, 0, x,
        xres, DD, 0,
        TT, nullptr, DD, nullptr);

    // 6) LN2
    ln_k<<<TT, 256>>>(xres, ln2g, ln2b, x2b);

    // 7) gate + routing
    zero_counts_k<<<1, 32>>>(counts);
    gate_route_k<<<TT, 256>>>(x2b, gw, gb, counts, etok, texp, tslot, tw);

    // 8) MoE: dual up-proj (1 launch) + down-proj (1 launch), z = expert
    kDM<<<dim3(TT/64, FF/128, EE), 256, smD>>>(x2b, DD,
        ew1, nullptr, nullptr, ew3, nullptr, nullptr, FF, (ll)DD * FF,
        eb1, nullptr, nullptr, eb3, nullptr, nullptr, FF,
        emid, FF, (ll)TT * FF, nullptr,
        0, counts, DD, etok);
    kM2<<<dim3(TT/128, DD/256, EE), 512, smP>>>(emid, FF, (ll)TT * FF,
        ew2, DD, (ll)FF * DD, eb2, DD, nullptr,
        moe, DD, (ll)TT * DD,
        0, counts, FF, nullptr);

    // 9) combine
    combine_k<<<TT, 256>>>(xres, texp, tslot, tw, moe, out);
}